// round 1
// baseline (speedup 1.0000x reference)
#include <cuda_runtime.h>

#define T_SEQ  2048
#define NHEAD  16
#define HDIM   128
#define BATCH  2
#define CDIM   2048
#define MROWS  (BATCH * T_SEQ)   // 4096

// Scratch (device globals: allocation-free, graph-safe)
__device__ float g_Q[(size_t)BATCH * NHEAD * T_SEQ * HDIM];
__device__ float g_K[(size_t)BATCH * NHEAD * T_SEQ * HDIM];
__device__ float g_V[(size_t)BATCH * NHEAD * T_SEQ * HDIM];
__device__ float g_Y[(size_t)BATCH * T_SEQ * CDIM];

// ---------------------------------------------------------------------------
// C(M,N) = A(M,K) @ W(N,K)^T + bias(N)
// MODE 0: plain row-major store C[m*N + n]
// MODE 1: QKV scatter: m=(b,t), n=(h,d) -> out[((b*H+h)*T+t)*HD + d]
// BM=BN=128, BK=16, 256 threads, 8x8 per thread (strided 16), prefetched.
// ---------------------------------------------------------------------------
template <int MODE>
__global__ void __launch_bounds__(256)
gemm_nt(const float* __restrict__ A, const float* __restrict__ W,
        const float* __restrict__ bias, float* __restrict__ C,
        int M, int N, int K)
{
    __shared__ float As[16][129];
    __shared__ float Bs[16][129];

    const int tid  = threadIdx.x;
    const int tRow = tid >> 4;     // 0..15
    const int tCol = tid & 15;     // 0..15
    const int mBase = blockIdx.y * 128;
    const int nBase = blockIdx.x * 128;

    const float* Ab = A + (size_t)mBase * K;
    const float* Wb = W + (size_t)nBase * K;

    const int lr = tid >> 2;        // 0..63
    const int lc = (tid & 3) * 4;   // 0,4,8,12

    float acc[8][8];
#pragma unroll
    for (int i = 0; i < 8; i++)
#pragma unroll
        for (int j = 0; j < 8; j++) acc[i][j] = 0.f;

    // prefetch tile 0
    float4 pa0 = *(const float4*)&Ab[(size_t)lr * K + lc];
    float4 pa1 = *(const float4*)&Ab[(size_t)(lr + 64) * K + lc];
    float4 pb0 = *(const float4*)&Wb[(size_t)lr * K + lc];
    float4 pb1 = *(const float4*)&Wb[(size_t)(lr + 64) * K + lc];

    const int nTiles = K >> 4;
    for (int kt = 0; kt < nTiles; kt++) {
        // commit prefetched tile to smem (transposed)
        As[lc + 0][lr] = pa0.x; As[lc + 1][lr] = pa0.y;
        As[lc + 2][lr] = pa0.z; As[lc + 3][lr] = pa0.w;
        As[lc + 0][lr + 64] = pa1.x; As[lc + 1][lr + 64] = pa1.y;
        As[lc + 2][lr + 64] = pa1.z; As[lc + 3][lr + 64] = pa1.w;
        Bs[lc + 0][lr] = pb0.x; Bs[lc + 1][lr] = pb0.y;
        Bs[lc + 2][lr] = pb0.z; Bs[lc + 3][lr] = pb0.w;
        Bs[lc + 0][lr + 64] = pb1.x; Bs[lc + 1][lr + 64] = pb1.y;
        Bs[lc + 2][lr + 64] = pb1.z; Bs[lc + 3][lr + 64] = pb1.w;
        __syncthreads();

        if (kt + 1 < nTiles) {
            const float* A2 = Ab + (size_t)(kt + 1) * 16;
            const float* W2 = Wb + (size_t)(kt + 1) * 16;
            pa0 = *(const float4*)&A2[(size_t)lr * K + lc];
            pa1 = *(const float4*)&A2[(size_t)(lr + 64) * K + lc];
            pb0 = *(const float4*)&W2[(size_t)lr * K + lc];
            pb1 = *(const float4*)&W2[(size_t)(lr + 64) * K + lc];
        }

#pragma unroll
        for (int kk = 0; kk < 16; kk++) {
            float a[8], b[8];
#pragma unroll
            for (int i = 0; i < 8; i++) a[i] = As[kk][tRow + 16 * i];
#pragma unroll
            for (int j = 0; j < 8; j++) b[j] = Bs[kk][tCol + 16 * j];
#pragma unroll
            for (int i = 0; i < 8; i++)
#pragma unroll
                for (int j = 0; j < 8; j++) acc[i][j] += a[i] * b[j];
        }
        __syncthreads();
    }

#pragma unroll
    for (int i = 0; i < 8; i++) {
        const int m = mBase + tRow + 16 * i;
#pragma unroll
        for (int j = 0; j < 8; j++) {
            const int n = nBase + tCol + 16 * j;
            const float v = acc[i][j] + bias[n];
            if (MODE == 0) {
                C[(size_t)m * N + n] = v;
            } else {
                const int b = m >> 11;            // m / T_SEQ
                const int t = m & (T_SEQ - 1);
                const int h = n >> 7;             // n / HDIM
                const int d = n & (HDIM - 1);
                C[(((size_t)(b * NHEAD + h)) * T_SEQ + t) * HDIM + d] = v;
            }
        }
    }
}

// ---------------------------------------------------------------------------
// Flash attention, causal. One CTA = (bh, 64 q-rows). 256 threads (16x16).
// Thread (ty,tx): rows r0..r0+3 (r0=ty*4), S cols / O cols c = tx + 16*j.
// Output stored TRANSPOSED: Y[b, h*128+d, t]  (matches reference's
// transpose(0,1,3,2).reshape view).
// smem: Qs[64][128], Ks[64][132], Vs[64][128], Ss[64][65] (also transpose stage)
// ---------------------------------------------------------------------------
#define KS_STRIDE 132
#define SS_STRIDE 65
#define ATTN_SMEM_FLOATS (64*128 + 64*KS_STRIDE + 64*128 + 64*SS_STRIDE)
#define ATTN_SMEM_BYTES  (ATTN_SMEM_FLOATS * 4)

__global__ void __launch_bounds__(256)
attn_kernel(const float* __restrict__ Q, const float* __restrict__ K,
            const float* __restrict__ V, float* __restrict__ Y)
{
    extern __shared__ float sm[];
    float* Qs = sm;                       // 64*128
    float* Ks = Qs + 64 * 128;            // 64*132
    float* Vs = Ks + 64 * KS_STRIDE;      // 64*128
    float* Ss = Vs + 64 * 128;            // 64*65

    const int tid = threadIdx.x;
    const int tx  = tid & 15;
    const int ty  = tid >> 4;
    const int r0  = ty * 4;
    const int qb  = blockIdx.x;           // 0..31
    const int bh  = blockIdx.y;           // 0..31

    const float* Qg = Q + ((size_t)bh * T_SEQ + qb * 64) * HDIM;

    // load Q tile (contiguous copy, stride 128 preserved)
    for (int l = tid; l < 64 * 32; l += 256)
        ((float4*)Qs)[l] = ((const float4*)Qg)[l];

    float m_i[4], l_i[4], o[4][8];
#pragma unroll
    for (int i = 0; i < 4; i++) {
        m_i[i] = -1e30f; l_i[i] = 0.f;
#pragma unroll
        for (int j = 0; j < 8; j++) o[i][j] = 0.f;
    }

    const float scale = 0.08838834764831845f;   // 1/sqrt(128)

    for (int jb = 0; jb <= qb; jb++) {
        __syncthreads();   // protect Ks/Vs/Ss reuse (and Qs vis on first iter)
        const float* Kg = K + ((size_t)bh * T_SEQ + jb * 64) * HDIM;
        const float* Vg = V + ((size_t)bh * T_SEQ + jb * 64) * HDIM;
        for (int l = tid; l < 64 * 32; l += 256) {
            const int r = l >> 5, d4 = (l & 31) * 4;
            *(float4*)&Ks[r * KS_STRIDE + d4] = ((const float4*)Kg)[l];
            ((float4*)Vs)[l] = ((const float4*)Vg)[l];
        }
        __syncthreads();

        // S = Q K^T  (64x64 tile, fp32, float4 over d)
        float s[4][4];
#pragma unroll
        for (int i = 0; i < 4; i++)
#pragma unroll
            for (int j = 0; j < 4; j++) s[i][j] = 0.f;

#pragma unroll 4
        for (int d4 = 0; d4 < 32; d4++) {
            float4 q4[4], k4[4];
#pragma unroll
            for (int i = 0; i < 4; i++)
                q4[i] = *(const float4*)&Qs[(r0 + i) * 128 + d4 * 4];
#pragma unroll
            for (int j = 0; j < 4; j++)
                k4[j] = *(const float4*)&Ks[(tx + 16 * j) * KS_STRIDE + d4 * 4];
#pragma unroll
            for (int i = 0; i < 4; i++)
#pragma unroll
                for (int j = 0; j < 4; j++)
                    s[i][j] += q4[i].x * k4[j].x + q4[i].y * k4[j].y +
                               q4[i].z * k4[j].z + q4[i].w * k4[j].w;
        }

        const bool diag = (jb == qb);
#pragma unroll
        for (int i = 0; i < 4; i++)
#pragma unroll
            for (int j = 0; j < 4; j++) {
                float v = s[i][j] * scale;
                if (diag && (tx + 16 * j > r0 + i)) v = -1e30f;
                s[i][j] = v;
            }

        // online softmax per row (16-lane shfl reductions; tx = lane bits 0-3)
#pragma unroll
        for (int i = 0; i < 4; i++) {
            float mx = fmaxf(fmaxf(s[i][0], s[i][1]), fmaxf(s[i][2], s[i][3]));
#pragma unroll
            for (int off = 8; off > 0; off >>= 1)
                mx = fmaxf(mx, __shfl_xor_sync(0xffffffffu, mx, off));
            const float mn = fmaxf(m_i[i], mx);
            const float alpha = __expf(m_i[i] - mn);
            m_i[i] = mn;
            float rs = 0.f;
#pragma unroll
            for (int j = 0; j < 4; j++) {
                const float p = __expf(s[i][j] - mn);
                Ss[(r0 + i) * SS_STRIDE + tx + 16 * j] = p;
                rs += p;
            }
#pragma unroll
            for (int off = 8; off > 0; off >>= 1)
                rs += __shfl_xor_sync(0xffffffffu, rs, off);
            l_i[i] = l_i[i] * alpha + rs;
#pragma unroll
            for (int j = 0; j < 8; j++) o[i][j] *= alpha;
        }
        __syncthreads();

        // O += P V
#pragma unroll 4
        for (int kc = 0; kc < 64; kc++) {
            float p[4], vv[8];
#pragma unroll
            for (int i = 0; i < 4; i++) p[i] = Ss[(r0 + i) * SS_STRIDE + kc];
#pragma unroll
            for (int j = 0; j < 8; j++) vv[j] = Vs[kc * 128 + tx + 16 * j];
#pragma unroll
            for (int i = 0; i < 4; i++)
#pragma unroll
                for (int j = 0; j < 8; j++) o[i][j] += p[i] * vv[j];
        }
    }

    // normalize
#pragma unroll
    for (int i = 0; i < 4; i++) {
        const float inv = 1.f / l_i[i];
#pragma unroll
        for (int j = 0; j < 8; j++) o[i][j] *= inv;
    }

    // transposed store: Y[(b*C + h*128 + d) * T + (qb*64 + t)]
    const int b = bh >> 4, h = bh & 15;
    float* Ts = Ss;   // reuse as [32][65] staging
    const size_t ybase = ((size_t)b * CDIM + h * HDIM) * T_SEQ + qb * 64;

    for (int dc = 0; dc < 4; dc++) {
        __syncthreads();
#pragma unroll
        for (int u = 0; u < 2; u++) {
            const int j  = 2 * dc + u;
            const int dl = tx + 16 * u;        // (tx + 16*j) - 32*dc
#pragma unroll
            for (int i = 0; i < 4; i++)
                Ts[dl * SS_STRIDE + r0 + i] = o[i][j];
        }
        __syncthreads();
        for (int e = tid; e < 32 * 64; e += 256) {
            const int dl = e >> 6, tt = e & 63;
            Y[ybase + (size_t)(dc * 32 + dl) * T_SEQ + tt] = Ts[dl * SS_STRIDE + tt];
        }
    }
}

// ---------------------------------------------------------------------------
extern "C" void kernel_launch(void* const* d_in, const int* in_sizes, int n_in,
                              void* d_out, int out_size)
{
    (void)in_sizes; (void)n_in; (void)out_size;
    const float* x  = (const float*)d_in[0];
    const float* Wq = (const float*)d_in[1];
    const float* bq = (const float*)d_in[2];
    const float* Wk = (const float*)d_in[3];
    const float* bk = (const float*)d_in[4];
    const float* Wv = (const float*)d_in[5];
    const float* bv = (const float*)d_in[6];
    const float* Wp = (const float*)d_in[7];
    const float* bp = (const float*)d_in[8];
    float* out = (float*)d_out;

    float *Qp, *Kp, *Vp, *Yp;
    cudaGetSymbolAddress((void**)&Qp, g_Q);
    cudaGetSymbolAddress((void**)&Kp, g_K);
    cudaGetSymbolAddress((void**)&Vp, g_V);
    cudaGetSymbolAddress((void**)&Yp, g_Y);

    dim3 gg(CDIM / 128, MROWS / 128);   // (16, 32)

    gemm_nt<1><<<gg, 256>>>(x, Wq, bq, Qp, MROWS, CDIM, CDIM);
    gemm_nt<1><<<gg, 256>>>(x, Wk, bk, Kp, MROWS, CDIM, CDIM);
    gemm_nt<1><<<gg, 256>>>(x, Wv, bv, Vp, MROWS, CDIM, CDIM);

    cudaFuncSetAttribute(attn_kernel,
                         cudaFuncAttributeMaxDynamicSharedMemorySize,
                         ATTN_SMEM_BYTES);
    attn_kernel<<<dim3(T_SEQ / 64, BATCH * NHEAD), 256, ATTN_SMEM_BYTES>>>(Qp, Kp, Vp, Yp);

    gemm_nt<0><<<gg, 256>>>(Yp, Wp, bp, out, MROWS, CDIM, CDIM);
}

// round 3
// speedup vs baseline: 1.8862x; 1.8862x over previous
#include <cuda_runtime.h>
#include <cuda_bf16.h>
#include <cstdint>

#define T_SEQ  2048
#define NHEAD  16
#define HDIM   128
#define BATCH  2
#define CDIM   2048
#define MROWS  (BATCH * T_SEQ)   // 4096

// Scratch (device globals: allocation-free, graph-safe)
__device__ float g_Q[(size_t)BATCH * NHEAD * T_SEQ * HDIM];
__device__ float g_K[(size_t)BATCH * NHEAD * T_SEQ * HDIM];
__device__ float g_V[(size_t)BATCH * NHEAD * T_SEQ * HDIM];
__device__ float g_Y[(size_t)BATCH * T_SEQ * CDIM];

// ===========================================================================
// helpers
// ===========================================================================
__device__ __forceinline__ uint32_t smem_to_u32(const void* p) {
    uint32_t a;
    asm("{ .reg .u64 t; cvta.to.shared.u64 t, %1; cvt.u32.u64 %0, t; }"
        : "=r"(a) : "l"(p));
    return a;
}

// bf16 split helpers
__device__ __forceinline__ uint32_t bfp(float a, float b) {
    __nv_bfloat162 t = __floats2bfloat162_rn(a, b);
    return *reinterpret_cast<uint32_t*>(&t);
}
__device__ __forceinline__ float bres(float a) {
    return a - __bfloat162float(__float2bfloat16(a));
}

#define LDMX4(r0, r1, r2, r3, addr) \
    asm volatile("ldmatrix.sync.aligned.m8n8.x4.shared.b16 {%0,%1,%2,%3}, [%4];" \
                 : "=r"(r0), "=r"(r1), "=r"(r2), "=r"(r3) : "r"(addr))

#define MMA16816(c, a, b0, b1) \
    asm volatile("mma.sync.aligned.m16n8k16.row.col.f32.bf16.bf16.f32 " \
                 "{%0,%1,%2,%3}, {%4,%5,%6,%7}, {%8,%9}, {%0,%1,%2,%3};" \
                 : "+f"((c)[0]), "+f"((c)[1]), "+f"((c)[2]), "+f"((c)[3]) \
                 : "r"((a)[0]), "r"((a)[1]), "r"((a)[2]), "r"((a)[3]), \
                   "r"(b0), "r"(b1))

// ===========================================================================
// Tensor-core GEMM via mma.sync (portable ISA, runs on base sm_103 target):
// C(M,N) = A(M,K) @ W(N,K)^T + bias(N), fp32 in/out.
// bf16 hi/lo split, 3 MMA passes (hi*hi + hi*lo + lo*hi), fp32 reg accum.
// CTA tile 128x128, K-chunk 64 (SW128-swizzled smem, 128B rows), double
// buffered. 256 threads = 8 warps; warp (wm, wn) owns a 64x32 sub-tile.
// MODE 0: C[m*CDIM+n].  MODE 1: QKV scatter out[((b*H+h)*T+t)*HD+d].
// smem: buf b at b*65536: Ah(16K) Al(16K) Bh(16K) Bl(16K). Epilogue aliases
// smem as Ct[128][132] fp32.
// ===========================================================================
#define GEMM_SMEM_BYTES (2 * 65536)

template <int MODE>
__global__ void __launch_bounds__(256)
gemm_mma(const float* __restrict__ A, const float* __restrict__ W,
         const float* __restrict__ bias, float* __restrict__ C)
{
    extern __shared__ __align__(1024) char sm[];
    const uint32_t sbase = smem_to_u32(sm);

    const int tid  = threadIdx.x;
    const int wid  = tid >> 5;
    const int lane = tid & 31;
    const int wm   = wid >> 2;        // 0..1 -> m offset wm*64
    const int wn   = wid & 3;         // 0..3 -> n offset wn*32
    const int quad = lane >> 3;       // ldmatrix address group
    const int rr   = lane & 7;
    const int mBase = blockIdx.y * 128;
    const int nBase = blockIdx.x * 128;

    // threads 0-127 stage A rows [mBase,+128); 128-255 stage W rows [nBase,+128)
    const float* Mat = (tid < 128) ? (A + (size_t)mBase * CDIM)
                                   : (W + (size_t)nBase * CDIM);
    const int lt = tid & 127;
    const uint32_t hiOff = (tid < 128) ? 0u : 32768u;   // A vs B region

    float c[4][4][4];
#pragma unroll
    for (int mi = 0; mi < 4; mi++)
#pragma unroll
        for (int ni = 0; ni < 4; ni++)
#pragma unroll
            for (int k = 0; k < 4; k++) c[mi][ni][k] = 0.f;

    // per-lane ldmatrix row/col pieces
    const int arow0 = wm * 64 + (quad & 1) * 8 + rr;    // + mi*16
    const int acolq = (quad >> 1) * 8;                  // + sub*16
    const int brow0 = wn * 32 + (quad >> 1) * 8 + rr;   // + pair*16
    const int bcolq = (quad & 1) * 8;                   // + sub*16

    // stage helper: convert 16 float4 (128 floats = one 128x64 slice share)
    // into hi/lo bf16 smem with SW128 swizzle
    auto cvt_sts = [&](const float4* st, uint32_t hb, uint32_t lb) {
#pragma unroll
        for (int i = 0; i < 8; i++) {
            const int gi = lt + 128 * i;
            const int r = gi >> 3, g = gi & 7;
            const uint32_t off = (uint32_t)(r * 128 + g * 16);
            const uint32_t sw  = off ^ ((off >> 3) & 0x70);
            const float4 u = st[2 * i], v = st[2 * i + 1];
            const uint32_t h0 = bfp(u.x, u.y), h1 = bfp(u.z, u.w);
            const uint32_t h2 = bfp(v.x, v.y), h3 = bfp(v.z, v.w);
            const uint32_t l0 = bfp(bres(u.x), bres(u.y));
            const uint32_t l1 = bfp(bres(u.z), bres(u.w));
            const uint32_t l2 = bfp(bres(v.x), bres(v.y));
            const uint32_t l3 = bfp(bres(v.z), bres(v.w));
            asm volatile("st.shared.v4.b32 [%0], {%1,%2,%3,%4};"
                         :: "r"(hb + sw), "r"(h0), "r"(h1), "r"(h2), "r"(h3) : "memory");
            asm volatile("st.shared.v4.b32 [%0], {%1,%2,%3,%4};"
                         :: "r"(lb + sw), "r"(l0), "r"(l1), "r"(l2), "r"(l3) : "memory");
        }
    };

    auto compute = [&](int buf) {
        const uint32_t base = sbase + (uint32_t)buf * 65536u;
        const uint32_t Ah = base, Al = base + 16384u;
        const uint32_t Bh = base + 32768u, Bl = base + 49152u;
#pragma unroll
        for (int sub = 0; sub < 4; sub++) {
            const int kb = sub * 16;
            uint32_t bh[8], bl[8];
#pragma unroll
            for (int p = 0; p < 2; p++) {
                const uint32_t off = (uint32_t)((brow0 + p * 16) * 128 + (kb + bcolq) * 2);
                const uint32_t sw  = off ^ ((off >> 3) & 0x70);
                LDMX4(bh[4 * p], bh[4 * p + 1], bh[4 * p + 2], bh[4 * p + 3], Bh + sw);
                LDMX4(bl[4 * p], bl[4 * p + 1], bl[4 * p + 2], bl[4 * p + 3], Bl + sw);
            }
#pragma unroll
            for (int mi = 0; mi < 4; mi++) {
                uint32_t ah[4], al[4];
                const uint32_t off = (uint32_t)((arow0 + mi * 16) * 128 + (kb + acolq) * 2);
                const uint32_t sw  = off ^ ((off >> 3) & 0x70);
                LDMX4(ah[0], ah[1], ah[2], ah[3], Ah + sw);
                LDMX4(al[0], al[1], al[2], al[3], Al + sw);
#pragma unroll
                for (int ni = 0; ni < 4; ni++) {
                    MMA16816(c[mi][ni], ah, bh[2 * ni], bh[2 * ni + 1]);
                    MMA16816(c[mi][ni], ah, bl[2 * ni], bl[2 * ni + 1]);
                    MMA16816(c[mi][ni], al, bh[2 * ni], bh[2 * ni + 1]);
                }
            }
        }
    };

    // stage chunk 0
    {
        float4 st[16];
#pragma unroll
        for (int i = 0; i < 8; i++) {
            const int gi = lt + 128 * i;
            const int r = gi >> 3, g = gi & 7;
            const float* p = Mat + (size_t)r * CDIM + g * 8;
            st[2 * i]     = *(const float4*)p;
            st[2 * i + 1] = *(const float4*)(p + 4);
        }
        cvt_sts(st, sbase + hiOff, sbase + hiOff + 16384u);
    }
    __syncthreads();

    for (int kt = 0; kt < 32; kt++) {
        const int buf = kt & 1;
        float4 st[16];
        if (kt < 31) {
            const float* cp = Mat + (kt + 1) * 64;
#pragma unroll
            for (int i = 0; i < 8; i++) {
                const int gi = lt + 128 * i;
                const int r = gi >> 3, g = gi & 7;
                const float* p = cp + (size_t)r * CDIM + g * 8;
                st[2 * i]     = *(const float4*)p;
                st[2 * i + 1] = *(const float4*)(p + 4);
            }
        }
        compute(buf);
        if (kt < 31) {
            const uint32_t nb = sbase + (uint32_t)(buf ^ 1) * 65536u + hiOff;
            cvt_sts(st, nb, nb + 16384u);
            __syncthreads();
        }
    }

    // epilogue: fragments -> smem Ct[128][132] -> coalesced (or scattered) gmem
    __syncthreads();
    float* Ct = (float*)sm;
    const int g = lane >> 2, t2 = (lane & 3) * 2;
#pragma unroll
    for (int mi = 0; mi < 4; mi++) {
        const int row = wm * 64 + mi * 16 + g;
#pragma unroll
        for (int ni = 0; ni < 4; ni++) {
            const int col = wn * 32 + ni * 8 + t2;
            Ct[row * 132 + col]           = c[mi][ni][0];
            Ct[row * 132 + col + 1]       = c[mi][ni][1];
            Ct[(row + 8) * 132 + col]     = c[mi][ni][2];
            Ct[(row + 8) * 132 + col + 1] = c[mi][ni][3];
        }
    }
    __syncthreads();

    for (int idx = tid; idx < 128 * 32; idx += 256) {
        const int row = idx >> 5, c4 = (idx & 31) * 4;
        const int n = nBase + c4;
        const float4 bv = *(const float4*)&bias[n];
        float4 v;
        v.x = Ct[row * 132 + c4]     + bv.x;
        v.y = Ct[row * 132 + c4 + 1] + bv.y;
        v.z = Ct[row * 132 + c4 + 2] + bv.z;
        v.w = Ct[row * 132 + c4 + 3] + bv.w;
        const int m = mBase + row;
        if (MODE == 0) {
            *(float4*)&C[(size_t)m * CDIM + n] = v;
        } else {
            const int b = m >> 11, t = m & (T_SEQ - 1);
            const int h = n >> 7, d = n & (HDIM - 1);
            *(float4*)&C[(((size_t)(b * NHEAD + h)) * T_SEQ + t) * HDIM + d] = v;
        }
    }
}

// ===========================================================================
// Flash attention, causal (unchanged — fp32; next round's target).
// ===========================================================================
#define KS_STRIDE 132
#define SS_STRIDE 65
#define ATTN_SMEM_FLOATS (64*128 + 64*KS_STRIDE + 64*128 + 64*SS_STRIDE)
#define ATTN_SMEM_BYTES  (ATTN_SMEM_FLOATS * 4)

__global__ void __launch_bounds__(256)
attn_kernel(const float* __restrict__ Q, const float* __restrict__ K,
            const float* __restrict__ V, float* __restrict__ Y)
{
    extern __shared__ float smf[];
    float* Qs = smf;
    float* Ks = Qs + 64 * 128;
    float* Vs = Ks + 64 * KS_STRIDE;
    float* Ss = Vs + 64 * 128;

    const int tid = threadIdx.x;
    const int tx  = tid & 15;
    const int ty  = tid >> 4;
    const int r0  = ty * 4;
    const int qb  = blockIdx.x;
    const int bh  = blockIdx.y;

    const float* Qg = Q + ((size_t)bh * T_SEQ + qb * 64) * HDIM;
    for (int l = tid; l < 64 * 32; l += 256)
        ((float4*)Qs)[l] = ((const float4*)Qg)[l];

    float m_i[4], l_i[4], o[4][8];
#pragma unroll
    for (int i = 0; i < 4; i++) {
        m_i[i] = -1e30f; l_i[i] = 0.f;
#pragma unroll
        for (int j = 0; j < 8; j++) o[i][j] = 0.f;
    }

    const float scale = 0.08838834764831845f;

    for (int jb = 0; jb <= qb; jb++) {
        __syncthreads();
        const float* Kg = K + ((size_t)bh * T_SEQ + jb * 64) * HDIM;
        const float* Vg = V + ((size_t)bh * T_SEQ + jb * 64) * HDIM;
        for (int l = tid; l < 64 * 32; l += 256) {
            const int r = l >> 5, d4 = (l & 31) * 4;
            *(float4*)&Ks[r * KS_STRIDE + d4] = ((const float4*)Kg)[l];
            ((float4*)Vs)[l] = ((const float4*)Vg)[l];
        }
        __syncthreads();

        float s[4][4];
#pragma unroll
        for (int i = 0; i < 4; i++)
#pragma unroll
            for (int j = 0; j < 4; j++) s[i][j] = 0.f;

#pragma unroll 4
        for (int d4 = 0; d4 < 32; d4++) {
            float4 q4[4], k4[4];
#pragma unroll
            for (int i = 0; i < 4; i++)
                q4[i] = *(const float4*)&Qs[(r0 + i) * 128 + d4 * 4];
#pragma unroll
            for (int j = 0; j < 4; j++)
                k4[j] = *(const float4*)&Ks[(tx + 16 * j) * KS_STRIDE + d4 * 4];
#pragma unroll
            for (int i = 0; i < 4; i++)
#pragma unroll
                for (int j = 0; j < 4; j++)
                    s[i][j] += q4[i].x * k4[j].x + q4[i].y * k4[j].y +
                               q4[i].z * k4[j].z + q4[i].w * k4[j].w;
        }

        const bool diag = (jb == qb);
#pragma unroll
        for (int i = 0; i < 4; i++)
#pragma unroll
            for (int j = 0; j < 4; j++) {
                float v = s[i][j] * scale;
                if (diag && (tx + 16 * j > r0 + i)) v = -1e30f;
                s[i][j] = v;
            }

#pragma unroll
        for (int i = 0; i < 4; i++) {
            float mx = fmaxf(fmaxf(s[i][0], s[i][1]), fmaxf(s[i][2], s[i][3]));
#pragma unroll
            for (int off = 8; off > 0; off >>= 1)
                mx = fmaxf(mx, __shfl_xor_sync(0xffffffffu, mx, off));
            const float mn = fmaxf(m_i[i], mx);
            const float alpha = __expf(m_i[i] - mn);
            m_i[i] = mn;
            float rs = 0.f;
#pragma unroll
            for (int j = 0; j < 4; j++) {
                const float p = __expf(s[i][j] - mn);
                Ss[(r0 + i) * SS_STRIDE + tx + 16 * j] = p;
                rs += p;
            }
#pragma unroll
            for (int off = 8; off > 0; off >>= 1)
                rs += __shfl_xor_sync(0xffffffffu, rs, off);
            l_i[i] = l_i[i] * alpha + rs;
#pragma unroll
            for (int j = 0; j < 8; j++) o[i][j] *= alpha;
        }
        __syncthreads();

#pragma unroll 4
        for (int kc = 0; kc < 64; kc++) {
            float p[4], vv[8];
#pragma unroll
            for (int i = 0; i < 4; i++) p[i] = Ss[(r0 + i) * SS_STRIDE + kc];
#pragma unroll
            for (int j = 0; j < 8; j++) vv[j] = Vs[kc * 128 + tx + 16 * j];
#pragma unroll
            for (int i = 0; i < 4; i++)
#pragma unroll
                for (int j = 0; j < 8; j++) o[i][j] += p[i] * vv[j];
        }
    }

#pragma unroll
    for (int i = 0; i < 4; i++) {
        const float inv = 1.f / l_i[i];
#pragma unroll
        for (int j = 0; j < 8; j++) o[i][j] *= inv;
    }

    const int b = bh >> 4, h = bh & 15;
    float* Ts = Ss;
    const size_t ybase = ((size_t)b * CDIM + h * HDIM) * T_SEQ + qb * 64;

    for (int dc = 0; dc < 4; dc++) {
        __syncthreads();
#pragma unroll
        for (int u = 0; u < 2; u++) {
            const int j  = 2 * dc + u;
            const int dl = tx + 16 * u;
#pragma unroll
            for (int i = 0; i < 4; i++)
                Ts[dl * SS_STRIDE + r0 + i] = o[i][j];
        }
        __syncthreads();
        for (int e = tid; e < 32 * 64; e += 256) {
            const int dl = e >> 6, tt = e & 63;
            Y[ybase + (size_t)(dc * 32 + dl) * T_SEQ + tt] = Ts[dl * SS_STRIDE + tt];
        }
    }
}

// ===========================================================================
extern "C" void kernel_launch(void* const* d_in, const int* in_sizes, int n_in,
                              void* d_out, int out_size)
{
    (void)in_sizes; (void)n_in; (void)out_size;
    const float* x  = (const float*)d_in[0];
    const float* Wq = (const float*)d_in[1];
    const float* bq = (const float*)d_in[2];
    const float* Wk = (const float*)d_in[3];
    const float* bk = (const float*)d_in[4];
    const float* Wv = (const float*)d_in[5];
    const float* bv = (const float*)d_in[6];
    const float* Wp = (const float*)d_in[7];
    const float* bp = (const float*)d_in[8];
    float* out = (float*)d_out;

    float *Qp, *Kp, *Vp, *Yp;
    cudaGetSymbolAddress((void**)&Qp, g_Q);
    cudaGetSymbolAddress((void**)&Kp, g_K);
    cudaGetSymbolAddress((void**)&Vp, g_V);
    cudaGetSymbolAddress((void**)&Yp, g_Y);

    cudaFuncSetAttribute(gemm_mma<1>, cudaFuncAttributeMaxDynamicSharedMemorySize,
                         GEMM_SMEM_BYTES);
    cudaFuncSetAttribute(gemm_mma<0>, cudaFuncAttributeMaxDynamicSharedMemorySize,
                         GEMM_SMEM_BYTES);
    cudaFuncSetAttribute(attn_kernel, cudaFuncAttributeMaxDynamicSharedMemorySize,
                         ATTN_SMEM_BYTES);

    dim3 gg(CDIM / 128, MROWS / 128);   // (16, 32)

    gemm_mma<1><<<gg, 256, GEMM_SMEM_BYTES>>>(x, Wq, bq, Qp);
    gemm_mma<1><<<gg, 256, GEMM_SMEM_BYTES>>>(x, Wk, bk, Kp);
    gemm_mma<1><<<gg, 256, GEMM_SMEM_BYTES>>>(x, Wv, bv, Vp);

    attn_kernel<<<dim3(T_SEQ / 64, BATCH * NHEAD), 256, ATTN_SMEM_BYTES>>>(Qp, Kp, Vp, Yp);

    gemm_mma<0><<<gg, 256, GEMM_SMEM_BYTES>>>(Yp, Wp, bp, out);
}

// round 6
// speedup vs baseline: 2.7226x; 1.4434x over previous
#include <cuda_runtime.h>
#include <cuda_bf16.h>
#include <cstdint>

#define T_SEQ  2048
#define NHEAD  16
#define HDIM   128
#define BATCH  2
#define CDIM   2048
#define MROWS  (BATCH * T_SEQ)   // 4096

// Scratch (device globals: allocation-free, graph-safe)
__device__ float g_Q[(size_t)BATCH * NHEAD * T_SEQ * HDIM];
__device__ float g_K[(size_t)BATCH * NHEAD * T_SEQ * HDIM];
__device__ float g_V[(size_t)BATCH * NHEAD * T_SEQ * HDIM];
__device__ float g_Y[(size_t)BATCH * T_SEQ * CDIM];

// ===========================================================================
// helpers
// ===========================================================================
__device__ __forceinline__ uint32_t smem_to_u32(const void* p) {
    uint32_t a;
    asm("{ .reg .u64 t; cvta.to.shared.u64 t, %1; cvt.u32.u64 %0, t; }"
        : "=r"(a) : "l"(p));
    return a;
}

// bf16 split helpers
__device__ __forceinline__ uint32_t bfp(float a, float b) {
    __nv_bfloat162 t = __floats2bfloat162_rn(a, b);
    return *reinterpret_cast<uint32_t*>(&t);
}
__device__ __forceinline__ float bres(float a) {
    return a - __bfloat162float(__float2bfloat16(a));
}

#define LDMX4(r0, r1, r2, r3, addr) \
    asm volatile("ldmatrix.sync.aligned.m8n8.x4.shared.b16 {%0,%1,%2,%3}, [%4];" \
                 : "=r"(r0), "=r"(r1), "=r"(r2), "=r"(r3) : "r"(addr))

#define LDMX4T(r0, r1, r2, r3, addr) \
    asm volatile("ldmatrix.sync.aligned.m8n8.x4.trans.shared.b16 {%0,%1,%2,%3}, [%4];" \
                 : "=r"(r0), "=r"(r1), "=r"(r2), "=r"(r3) : "r"(addr))

#define MMA16816(c, a, b0, b1) \
    asm volatile("mma.sync.aligned.m16n8k16.row.col.f32.bf16.bf16.f32 " \
                 "{%0,%1,%2,%3}, {%4,%5,%6,%7}, {%8,%9}, {%0,%1,%2,%3};" \
                 : "+f"((c)[0]), "+f"((c)[1]), "+f"((c)[2]), "+f"((c)[3]) \
                 : "r"((a)[0]), "r"((a)[1]), "r"((a)[2]), "r"((a)[3]), \
                   "r"(b0), "r"(b1))

#define STSV4(addr, a, b, cc, d) \
    asm volatile("st.shared.v4.b32 [%0], {%1,%2,%3,%4};" \
                 :: "r"(addr), "r"(a), "r"(b), "r"(cc), "r"(d) : "memory")

#define STS32(addr, a) \
    asm volatile("st.shared.b32 [%0], %1;" :: "r"(addr), "r"(a) : "memory")

// ===========================================================================
// Tensor-core GEMM via mma.sync: C = A @ W^T + bias (unchanged from R3)
// ===========================================================================
#define GEMM_SMEM_BYTES (2 * 65536)

template <int MODE>
__global__ void __launch_bounds__(256)
gemm_mma(const float* __restrict__ A, const float* __restrict__ W,
         const float* __restrict__ bias, float* __restrict__ C)
{
    extern __shared__ __align__(1024) char sm[];
    const uint32_t sbase = smem_to_u32(sm);

    const int tid  = threadIdx.x;
    const int wid  = tid >> 5;
    const int lane = tid & 31;
    const int wm   = wid >> 2;
    const int wn   = wid & 3;
    const int quad = lane >> 3;
    const int rr   = lane & 7;
    const int mBase = blockIdx.y * 128;
    const int nBase = blockIdx.x * 128;

    const float* Mat = (tid < 128) ? (A + (size_t)mBase * CDIM)
                                   : (W + (size_t)nBase * CDIM);
    const int lt = tid & 127;
    const uint32_t hiOff = (tid < 128) ? 0u : 32768u;

    float c[4][4][4];
#pragma unroll
    for (int mi = 0; mi < 4; mi++)
#pragma unroll
        for (int ni = 0; ni < 4; ni++)
#pragma unroll
            for (int k = 0; k < 4; k++) c[mi][ni][k] = 0.f;

    const int arow0 = wm * 64 + (quad & 1) * 8 + rr;
    const int acolq = (quad >> 1) * 8;
    const int brow0 = wn * 32 + (quad >> 1) * 8 + rr;
    const int bcolq = (quad & 1) * 8;

    auto cvt_sts = [&](const float4* st, uint32_t hb, uint32_t lb) {
#pragma unroll
        for (int i = 0; i < 8; i++) {
            const int gi = lt + 128 * i;
            const int r = gi >> 3, g = gi & 7;
            const uint32_t off = (uint32_t)(r * 128 + g * 16);
            const uint32_t sw  = off ^ ((off >> 3) & 0x70);
            const float4 u = st[2 * i], v = st[2 * i + 1];
            STSV4(hb + sw, bfp(u.x, u.y), bfp(u.z, u.w), bfp(v.x, v.y), bfp(v.z, v.w));
            STSV4(lb + sw, bfp(bres(u.x), bres(u.y)), bfp(bres(u.z), bres(u.w)),
                           bfp(bres(v.x), bres(v.y)), bfp(bres(v.z), bres(v.w)));
        }
    };

    auto compute = [&](int buf) {
        const uint32_t base = sbase + (uint32_t)buf * 65536u;
        const uint32_t Ah = base, Al = base + 16384u;
        const uint32_t Bh = base + 32768u, Bl = base + 49152u;
#pragma unroll
        for (int sub = 0; sub < 4; sub++) {
            const int kb = sub * 16;
            uint32_t bh[8], bl[8];
#pragma unroll
            for (int p = 0; p < 2; p++) {
                const uint32_t off = (uint32_t)((brow0 + p * 16) * 128 + (kb + bcolq) * 2);
                const uint32_t sw  = off ^ ((off >> 3) & 0x70);
                LDMX4(bh[4 * p], bh[4 * p + 1], bh[4 * p + 2], bh[4 * p + 3], Bh + sw);
                LDMX4(bl[4 * p], bl[4 * p + 1], bl[4 * p + 2], bl[4 * p + 3], Bl + sw);
            }
#pragma unroll
            for (int mi = 0; mi < 4; mi++) {
                uint32_t ah[4], al[4];
                const uint32_t off = (uint32_t)((arow0 + mi * 16) * 128 + (kb + acolq) * 2);
                const uint32_t sw  = off ^ ((off >> 3) & 0x70);
                LDMX4(ah[0], ah[1], ah[2], ah[3], Ah + sw);
                LDMX4(al[0], al[1], al[2], al[3], Al + sw);
#pragma unroll
                for (int ni = 0; ni < 4; ni++) {
                    MMA16816(c[mi][ni], ah, bh[2 * ni], bh[2 * ni + 1]);
                    MMA16816(c[mi][ni], ah, bl[2 * ni], bl[2 * ni + 1]);
                    MMA16816(c[mi][ni], al, bh[2 * ni], bh[2 * ni + 1]);
                }
            }
        }
    };

    {
        float4 st[16];
#pragma unroll
        for (int i = 0; i < 8; i++) {
            const int gi = lt + 128 * i;
            const int r = gi >> 3, g = gi & 7;
            const float* p = Mat + (size_t)r * CDIM + g * 8;
            st[2 * i]     = *(const float4*)p;
            st[2 * i + 1] = *(const float4*)(p + 4);
        }
        cvt_sts(st, sbase + hiOff, sbase + hiOff + 16384u);
    }
    __syncthreads();

    for (int kt = 0; kt < 32; kt++) {
        const int buf = kt & 1;
        float4 st[16];
        if (kt < 31) {
            const float* cp = Mat + (kt + 1) * 64;
#pragma unroll
            for (int i = 0; i < 8; i++) {
                const int gi = lt + 128 * i;
                const int r = gi >> 3, g = gi & 7;
                const float* p = cp + (size_t)r * CDIM + g * 8;
                st[2 * i]     = *(const float4*)p;
                st[2 * i + 1] = *(const float4*)(p + 4);
            }
        }
        compute(buf);
        if (kt < 31) {
            const uint32_t nb = sbase + (uint32_t)(buf ^ 1) * 65536u + hiOff;
            cvt_sts(st, nb, nb + 16384u);
            __syncthreads();
        }
    }

    __syncthreads();
    float* Ct = (float*)sm;
    const int g2 = lane >> 2, t2 = (lane & 3) * 2;
#pragma unroll
    for (int mi = 0; mi < 4; mi++) {
        const int row = wm * 64 + mi * 16 + g2;
#pragma unroll
        for (int ni = 0; ni < 4; ni++) {
            const int col = wn * 32 + ni * 8 + t2;
            Ct[row * 132 + col]           = c[mi][ni][0];
            Ct[row * 132 + col + 1]       = c[mi][ni][1];
            Ct[(row + 8) * 132 + col]     = c[mi][ni][2];
            Ct[(row + 8) * 132 + col + 1] = c[mi][ni][3];
        }
    }
    __syncthreads();

    for (int idx = tid; idx < 128 * 32; idx += 256) {
        const int row = idx >> 5, c4 = (idx & 31) * 4;
        const int n = nBase + c4;
        const float4 bv = *(const float4*)&bias[n];
        float4 v;
        v.x = Ct[row * 132 + c4]     + bv.x;
        v.y = Ct[row * 132 + c4 + 1] + bv.y;
        v.z = Ct[row * 132 + c4 + 2] + bv.z;
        v.w = Ct[row * 132 + c4 + 3] + bv.w;
        const int m = mBase + row;
        if (MODE == 0) {
            *(float4*)&C[(size_t)m * CDIM + n] = v;
        } else {
            const int b = m >> 11, t = m & (T_SEQ - 1);
            const int h = n >> 7, d = n & (HDIM - 1);
            *(float4*)&C[(((size_t)(b * NHEAD + h)) * T_SEQ + t) * HDIM + d] = v;
        }
    }
}

// ===========================================================================
// Tensor-core flash attention, causal. CTA = (bh, 64 q rows), 8 warps (4x2).
// Fixed vs R4: softmax statistics (row max / row sum) are combined ACROSS the
// two wn-warps of each row group via a small smem exchange, so both halves of
// every P row use identical max/scale.
// smem: Qh Ql Kh Kl Vh Vl (16K ea), Ph Pl (8K ea), stats (1K).
// ===========================================================================
#define ATTN_STAT_OFF 114688u
#define ATTN_SMEM_BYTES (114688 + 1024)

__global__ void __launch_bounds__(256, 2)
attn_mma(const float* __restrict__ Q, const float* __restrict__ K,
         const float* __restrict__ V, float* __restrict__ Y)
{
    extern __shared__ __align__(1024) char sm[];
    const uint32_t sb = smem_to_u32(sm);
    const uint32_t QH = sb,           QL = sb + 16384u;
    const uint32_t KH = sb + 32768u,  KL = sb + 49152u;
    const uint32_t VH = sb + 65536u,  VL = sb + 81920u;
    const uint32_t PHs = sb + 98304u, PLs = sb + 106496u;
    float* Mst = (float*)(sm + ATTN_STAT_OFF);          // [2][64]
    float* Sst = (float*)(sm + ATTN_STAT_OFF + 512u);   // [2][64]

    const int tid  = threadIdx.x;
    const int lane = tid & 31;
    const int wid  = tid >> 5;
    const int wm   = wid >> 1;         // 0..3 : q rows wm*16
    const int wn   = wid & 1;          // 0..1 : key cols wn*32 / d cols wn*64
    const int quad = lane >> 3;
    const int rr   = lane & 7;
    const int g    = lane >> 2;
    const int tq   = lane & 3;
    const int qb   = (int)gridDim.x - 1 - (int)blockIdx.x;  // heavy blocks first
    const int bh   = blockIdx.y;

    // ---- stage Q (hi/lo, [64][128] bf16, 256B rows, row-XOR swizzle) ----
    {
        const float* Qg = Q + ((size_t)bh * T_SEQ + qb * 64) * HDIM;
        for (int c = tid; c < 1024; c += 256) {
            const int row = c >> 4, gg = c & 15;
            const float* p = Qg + row * 128 + gg * 8;
            const float4 u = *(const float4*)p, v = *(const float4*)(p + 4);
            const uint32_t off = (uint32_t)row * 256u +
                                 ((uint32_t)(gg * 16) ^ ((uint32_t)(row & 7) << 4));
            STSV4(QH + off, bfp(u.x, u.y), bfp(u.z, u.w), bfp(v.x, v.y), bfp(v.z, v.w));
            STSV4(QL + off, bfp(bres(u.x), bres(u.y)), bfp(bres(u.z), bres(u.w)),
                            bfp(bres(v.x), bres(v.y)), bfp(bres(v.z), bres(v.w)));
        }
    }

    float o[8][4];
#pragma unroll
    for (int nf = 0; nf < 8; nf++)
#pragma unroll
        for (int k = 0; k < 4; k++) o[nf][k] = 0.f;
    float m_i[2] = {-1e30f, -1e30f}, l_i[2] = {0.f, 0.f};

    const float scale = 0.08838834764831845f;   // 1/sqrt(128)

    for (int jb = 0; jb <= qb; jb++) {
        __syncthreads();   // prev-iter PV/stat reads done; Q stores done (iter 0)

        // ---- stage K, V tiles (hi/lo) ----
        {
            const float* Kg = K + ((size_t)bh * T_SEQ + jb * 64) * HDIM;
            const float* Vg = V + ((size_t)bh * T_SEQ + jb * 64) * HDIM;
            for (int c = tid; c < 1024; c += 256) {
                const int row = c >> 4, gg = c & 15;
                const uint32_t off = (uint32_t)row * 256u +
                                     ((uint32_t)(gg * 16) ^ ((uint32_t)(row & 7) << 4));
                const float* p = Kg + row * 128 + gg * 8;
                const float4 u = *(const float4*)p, v = *(const float4*)(p + 4);
                STSV4(KH + off, bfp(u.x, u.y), bfp(u.z, u.w), bfp(v.x, v.y), bfp(v.z, v.w));
                STSV4(KL + off, bfp(bres(u.x), bres(u.y)), bfp(bres(u.z), bres(u.w)),
                                bfp(bres(v.x), bres(v.y)), bfp(bres(v.z), bres(v.w)));
            }
            for (int c = tid; c < 1024; c += 256) {
                const int row = c >> 4, gg = c & 15;
                const uint32_t off = (uint32_t)row * 256u +
                                     ((uint32_t)(gg * 16) ^ ((uint32_t)(row & 7) << 4));
                const float* p = Vg + row * 128 + gg * 8;
                const float4 u = *(const float4*)p, v = *(const float4*)(p + 4);
                STSV4(VH + off, bfp(u.x, u.y), bfp(u.z, u.w), bfp(v.x, v.y), bfp(v.z, v.w));
                STSV4(VL + off, bfp(bres(u.x), bres(u.y)), bfp(bres(u.z), bres(u.w)),
                                bfp(bres(v.x), bres(v.y)), bfp(bres(v.z), bres(v.w)));
            }
        }
        __syncthreads();

        // ---- S = Q K^T (16x32 per warp, 3-pass hi/lo) ----
        float s[4][4];
#pragma unroll
        for (int ni = 0; ni < 4; ni++)
#pragma unroll
            for (int k = 0; k < 4; k++) s[ni][k] = 0.f;

#pragma unroll
        for (int kb = 0; kb < 8; kb++) {
            uint32_t ah[4], al[4], bh[8], bl[8];
            {
                const int arow = wm * 16 + (quad & 1) * 8 + rr;
                const uint32_t cb = (uint32_t)(kb * 32 + (quad >> 1) * 16);
                const uint32_t off = (uint32_t)arow * 256u + (cb ^ ((uint32_t)(arow & 7) << 4));
                LDMX4(ah[0], ah[1], ah[2], ah[3], QH + off);
                LDMX4(al[0], al[1], al[2], al[3], QL + off);
            }
#pragma unroll
            for (int p = 0; p < 2; p++) {
                const int krow = wn * 32 + p * 16 + (quad >> 1) * 8 + rr;
                const uint32_t cb = (uint32_t)(kb * 32 + (quad & 1) * 16);
                const uint32_t off = (uint32_t)krow * 256u + (cb ^ ((uint32_t)(krow & 7) << 4));
                LDMX4(bh[4 * p], bh[4 * p + 1], bh[4 * p + 2], bh[4 * p + 3], KH + off);
                LDMX4(bl[4 * p], bl[4 * p + 1], bl[4 * p + 2], bl[4 * p + 3], KL + off);
            }
#pragma unroll
            for (int ni = 0; ni < 4; ni++) {
                MMA16816(s[ni], ah, bh[2 * ni], bh[2 * ni + 1]);
                MMA16816(s[ni], ah, bl[2 * ni], bl[2 * ni + 1]);
                MMA16816(s[ni], al, bh[2 * ni], bh[2 * ni + 1]);
            }
        }

        // ---- scale + causal mask ----
        const bool diag = (jb == qb);
#pragma unroll
        for (int ni = 0; ni < 4; ni++)
#pragma unroll
            for (int j = 0; j < 4; j++) {
                float v = s[ni][j] * scale;
                if (diag) {
                    const int rloc = wm * 16 + g + ((j >> 1) << 3);
                    const int kloc = wn * 32 + ni * 8 + 2 * tq + (j & 1);
                    if (kloc > rloc) v = -1e30f;
                }
                s[ni][j] = v;
            }

        // ---- partial row max (this warp's 32 keys), publish to smem ----
        float pmx[2];
#pragma unroll
        for (int r = 0; r < 2; r++) {
            float mx = -1e30f;
#pragma unroll
            for (int ni = 0; ni < 4; ni++)
                mx = fmaxf(mx, fmaxf(s[ni][2 * r], s[ni][2 * r + 1]));
            mx = fmaxf(mx, __shfl_xor_sync(0xffffffffu, mx, 1));
            mx = fmaxf(mx, __shfl_xor_sync(0xffffffffu, mx, 2));
            pmx[r] = mx;
        }
        if (tq == 0) {
            Mst[wn * 64 + wm * 16 + g]     = pmx[0];
            Mst[wn * 64 + wm * 16 + g + 8] = pmx[1];
        }
        __syncthreads();

        // ---- combined max -> exp -> partial sums; store P hi/lo ----
        float alpha[2];
#pragma unroll
        for (int r = 0; r < 2; r++) {
            const int row = wm * 16 + g + r * 8;
            const float mx_all = fmaxf(Mst[row], Mst[64 + row]);
            const float mn = fmaxf(m_i[r], mx_all);
            alpha[r] = __expf(m_i[r] - mn);
            m_i[r] = mn;
            float sum = 0.f;
#pragma unroll
            for (int ni = 0; ni < 4; ni++) {
                const float p0 = __expf(s[ni][2 * r] - mn);
                const float p1 = __expf(s[ni][2 * r + 1] - mn);
                s[ni][2 * r] = p0; s[ni][2 * r + 1] = p1;
                sum += p0 + p1;
            }
            sum += __shfl_xor_sync(0xffffffffu, sum, 1);
            sum += __shfl_xor_sync(0xffffffffu, sum, 2);
            if (tq == 0) Sst[wn * 64 + row] = sum;
#pragma unroll
            for (int nf = 0; nf < 8; nf++) {
                o[nf][2 * r]     *= alpha[r];
                o[nf][2 * r + 1] *= alpha[r];
            }
        }

        // ---- store P hi/lo to smem ([64 q][64 key] bf16, SW128) ----
#pragma unroll
        for (int r = 0; r < 2; r++) {
            const int row = wm * 16 + g + r * 8;
            const uint32_t rbase = (uint32_t)row * 128u;
            const uint32_t rx = (uint32_t)(row & 7) << 4;
#pragma unroll
            for (int ni = 0; ni < 4; ni++) {
                const uint32_t cb = (uint32_t)((wn * 32 + ni * 8 + 2 * tq) * 2);
                const uint32_t off = rbase + (cb ^ rx);
                const float p0 = s[ni][2 * r], p1 = s[ni][2 * r + 1];
                STS32(PHs + off, bfp(p0, p1));
                STS32(PLs + off, bfp(bres(p0), bres(p1)));
            }
        }
        __syncthreads();

        // ---- fold combined sums into l_i ----
#pragma unroll
        for (int r = 0; r < 2; r++) {
            const int row = wm * 16 + g + r * 8;
            l_i[r] = l_i[r] * alpha[r] + Sst[row] + Sst[64 + row];
        }

        // ---- O += P V (16 q x 64 d per warp, 3-pass hi/lo, V via LDSM.T) ----
#pragma unroll
        for (int kb2 = 0; kb2 < 4; kb2++) {
            uint32_t aph[4], apl[4];
            {
                const int arow = wm * 16 + (quad & 1) * 8 + rr;
                const uint32_t cb = (uint32_t)(kb2 * 32 + (quad >> 1) * 16);
                const uint32_t off = (uint32_t)arow * 128u + (cb ^ ((uint32_t)(arow & 7) << 4));
                LDMX4(aph[0], aph[1], aph[2], aph[3], PHs + off);
                LDMX4(apl[0], apl[1], apl[2], apl[3], PLs + off);
            }
#pragma unroll
            for (int np = 0; np < 4; np++) {
                const int key = kb2 * 16 + (quad & 1) * 8 + rr;
                const uint32_t db = (uint32_t)(wn * 128 + np * 32 + (quad >> 1) * 16);
                const uint32_t off = (uint32_t)key * 256u + (db ^ ((uint32_t)(key & 7) << 4));
                uint32_t vh[4], vl[4];
                LDMX4T(vh[0], vh[1], vh[2], vh[3], VH + off);
                LDMX4T(vl[0], vl[1], vl[2], vl[3], VL + off);
                MMA16816(o[2 * np],     aph, vh[0], vh[1]);
                MMA16816(o[2 * np],     aph, vl[0], vl[1]);
                MMA16816(o[2 * np],     apl, vh[0], vh[1]);
                MMA16816(o[2 * np + 1], aph, vh[2], vh[3]);
                MMA16816(o[2 * np + 1], aph, vl[2], vl[3]);
                MMA16816(o[2 * np + 1], apl, vh[2], vh[3]);
            }
        }
    }

    // ---- epilogue: normalize, transpose-stage, store Y[b, h*128+d, t] ----
    __syncthreads();
    const float inv0 = 1.f / l_i[0], inv1 = 1.f / l_i[1];
    float* Od = (float*)sm;   // [128 d][68]
#pragma unroll
    for (int nf = 0; nf < 8; nf++) {
        const int d = wn * 64 + (nf >> 1) * 16 + (nf & 1) * 8 + 2 * tq;
        const int r0 = wm * 16 + g;
        Od[d * 68 + r0]           = o[nf][0] * inv0;
        Od[(d + 1) * 68 + r0]     = o[nf][1] * inv0;
        Od[d * 68 + r0 + 8]       = o[nf][2] * inv1;
        Od[(d + 1) * 68 + r0 + 8] = o[nf][3] * inv1;
    }
    __syncthreads();

    const int b = bh >> 4, h = bh & 15;
    const size_t ybase = ((size_t)(b * CDIM + h * HDIM)) * T_SEQ + (size_t)qb * 64;
    for (int idx = tid; idx < 2048; idx += 256) {
        const int d = idx >> 4, q4 = (idx & 15) * 4;
        const float4 v = *(const float4*)&Od[d * 68 + q4];
        *(float4*)&Y[ybase + (size_t)d * T_SEQ + q4] = v;
    }
}

// ===========================================================================
extern "C" void kernel_launch(void* const* d_in, const int* in_sizes, int n_in,
                              void* d_out, int out_size)
{
    (void)in_sizes; (void)n_in; (void)out_size;
    const float* x  = (const float*)d_in[0];
    const float* Wq = (const float*)d_in[1];
    const float* bq = (const float*)d_in[2];
    const float* Wk = (const float*)d_in[3];
    const float* bk = (const float*)d_in[4];
    const float* Wv = (const float*)d_in[5];
    const float* bv = (const float*)d_in[6];
    const float* Wp = (const float*)d_in[7];
    const float* bp = (const float*)d_in[8];
    float* out = (float*)d_out;

    float *Qp, *Kp, *Vp, *Yp;
    cudaGetSymbolAddress((void**)&Qp, g_Q);
    cudaGetSymbolAddress((void**)&Kp, g_K);
    cudaGetSymbolAddress((void**)&Vp, g_V);
    cudaGetSymbolAddress((void**)&Yp, g_Y);

    cudaFuncSetAttribute(gemm_mma<1>, cudaFuncAttributeMaxDynamicSharedMemorySize,
                         GEMM_SMEM_BYTES);
    cudaFuncSetAttribute(gemm_mma<0>, cudaFuncAttributeMaxDynamicSharedMemorySize,
                         GEMM_SMEM_BYTES);
    cudaFuncSetAttribute(attn_mma, cudaFuncAttributeMaxDynamicSharedMemorySize,
                         ATTN_SMEM_BYTES);

    dim3 gg(CDIM / 128, MROWS / 128);   // (16, 32)

    gemm_mma<1><<<gg, 256, GEMM_SMEM_BYTES>>>(x, Wq, bq, Qp);
    gemm_mma<1><<<gg, 256, GEMM_SMEM_BYTES>>>(x, Wk, bk, Kp);
    gemm_mma<1><<<gg, 256, GEMM_SMEM_BYTES>>>(x, Wv, bv, Vp);

    attn_mma<<<dim3(T_SEQ / 64, BATCH * NHEAD), 256, ATTN_SMEM_BYTES>>>(Qp, Kp, Vp, Yp);

    gemm_mma<0><<<gg, 256, GEMM_SMEM_BYTES>>>(Yp, Wp, bp, out);
}

// round 7
// speedup vs baseline: 3.1063x; 1.1410x over previous
#include <cuda_runtime.h>
#include <cuda_bf16.h>
#include <cstdint>

#define T_SEQ  2048
#define NHEAD  16
#define HDIM   128
#define BATCH  2
#define CDIM   2048
#define MROWS  (BATCH * T_SEQ)   // 4096

// ---------------------------------------------------------------------------
// Device-global scratch (allocation-free, graph-safe), all bf16 hi/lo pairs
// ---------------------------------------------------------------------------
__device__ __nv_bfloat16 g_xh[(size_t)MROWS * CDIM];
__device__ __nv_bfloat16 g_xl[(size_t)MROWS * CDIM];
__device__ __nv_bfloat16 g_Wh[4][(size_t)CDIM * CDIM];   // q,k,v,p
__device__ __nv_bfloat16 g_Wl[4][(size_t)CDIM * CDIM];
__device__ __nv_bfloat16 g_Qh[(size_t)BATCH * NHEAD * T_SEQ * HDIM];
__device__ __nv_bfloat16 g_Ql[(size_t)BATCH * NHEAD * T_SEQ * HDIM];
__device__ __nv_bfloat16 g_Kh[(size_t)BATCH * NHEAD * T_SEQ * HDIM];
__device__ __nv_bfloat16 g_Kl[(size_t)BATCH * NHEAD * T_SEQ * HDIM];
__device__ __nv_bfloat16 g_Vh[(size_t)BATCH * NHEAD * T_SEQ * HDIM];
__device__ __nv_bfloat16 g_Vl[(size_t)BATCH * NHEAD * T_SEQ * HDIM];
__device__ __nv_bfloat16 g_Yh[(size_t)BATCH * T_SEQ * CDIM];   // [b][c][t]
__device__ __nv_bfloat16 g_Yl[(size_t)BATCH * T_SEQ * CDIM];

// ===========================================================================
// helpers
// ===========================================================================
__device__ __forceinline__ uint32_t smem_to_u32(const void* p) {
    uint32_t a;
    asm("{ .reg .u64 t; cvta.to.shared.u64 t, %1; cvt.u32.u64 %0, t; }"
        : "=r"(a) : "l"(p));
    return a;
}

__device__ __forceinline__ uint32_t bfp(float a, float b) {
    __nv_bfloat162 t = __floats2bfloat162_rn(a, b);
    return *reinterpret_cast<uint32_t*>(&t);
}
__device__ __forceinline__ float bres(float a) {
    return a - __bfloat162float(__float2bfloat16(a));
}

#define LDMX4(r0, r1, r2, r3, addr) \
    asm volatile("ldmatrix.sync.aligned.m8n8.x4.shared.b16 {%0,%1,%2,%3}, [%4];" \
                 : "=r"(r0), "=r"(r1), "=r"(r2), "=r"(r3) : "r"(addr))

#define LDMX4T(r0, r1, r2, r3, addr) \
    asm volatile("ldmatrix.sync.aligned.m8n8.x4.trans.shared.b16 {%0,%1,%2,%3}, [%4];" \
                 : "=r"(r0), "=r"(r1), "=r"(r2), "=r"(r3) : "r"(addr))

#define MMA16816(c, a, b0, b1) \
    asm volatile("mma.sync.aligned.m16n8k16.row.col.f32.bf16.bf16.f32 " \
                 "{%0,%1,%2,%3}, {%4,%5,%6,%7}, {%8,%9}, {%0,%1,%2,%3};" \
                 : "+f"((c)[0]), "+f"((c)[1]), "+f"((c)[2]), "+f"((c)[3]) \
                 : "r"((a)[0]), "r"((a)[1]), "r"((a)[2]), "r"((a)[3]), \
                   "r"(b0), "r"(b1))

#define STSV4(addr, a, b, cc, d) \
    asm volatile("st.shared.v4.b32 [%0], {%1,%2,%3,%4};" \
                 :: "r"(addr), "r"(a), "r"(b), "r"(cc), "r"(d) : "memory")

#define STS32(addr, a) \
    asm volatile("st.shared.b32 [%0], %1;" :: "r"(addr), "r"(a) : "memory")

// ===========================================================================
// fp32 -> bf16 hi/lo split (bandwidth-bound, run once per tensor)
// ===========================================================================
__global__ void cvt_hilo(const float* __restrict__ in,
                         __nv_bfloat16* __restrict__ hi,
                         __nv_bfloat16* __restrict__ lo, int n4)
{
    const int i = blockIdx.x * blockDim.x + threadIdx.x;
    if (i >= n4) return;
    const float4 v = ((const float4*)in)[i];
    uint2 h, l;
    h.x = bfp(v.x, v.y); h.y = bfp(v.z, v.w);
    l.x = bfp(bres(v.x), bres(v.y)); l.y = bfp(bres(v.z), bres(v.w));
    ((uint2*)hi)[i] = h;
    ((uint2*)lo)[i] = l;
}

// ===========================================================================
// Tensor-core GEMM, bf16 hi/lo pre-split operands (no cvt in mainloop):
// C(M,N) = A(M,K) @ W(N,K)^T + bias(N), 3-pass hi/lo, fp32 accum.
// CTA 128x128, K-chunk 64, double-buffered 128B-row SW128 smem.
// MODE 0: fp32 C[m*CDIM+n].  MODE 1: bf16 hi/lo out at ((b*H+h)*T+t)*HD+d.
// ===========================================================================
#define GEMM_SMEM_BYTES (2 * 65536)

template <int MODE>
__global__ void __launch_bounds__(256)
gemm_bf(const __nv_bfloat16* __restrict__ Ah, const __nv_bfloat16* __restrict__ Al,
        const __nv_bfloat16* __restrict__ Bh, const __nv_bfloat16* __restrict__ Bl,
        const float* __restrict__ bias, float* __restrict__ C,
        __nv_bfloat16* __restrict__ Oh, __nv_bfloat16* __restrict__ Ol)
{
    extern __shared__ __align__(1024) char sm[];
    const uint32_t sbase = smem_to_u32(sm);

    const int tid  = threadIdx.x;
    const int wid  = tid >> 5;
    const int lane = tid & 31;
    const int wm   = wid >> 2;
    const int wn   = wid & 3;
    const int quad = lane >> 3;
    const int rr   = lane & 7;
    const int mBase = blockIdx.y * 128;
    const int nBase = blockIdx.x * 128;

    const __nv_bfloat16* MatH = (tid < 128) ? (Ah + (size_t)mBase * CDIM)
                                            : (Bh + (size_t)nBase * CDIM);
    const __nv_bfloat16* MatL = (tid < 128) ? (Al + (size_t)mBase * CDIM)
                                            : (Bl + (size_t)nBase * CDIM);
    const int lt = tid & 127;
    const uint32_t hiOff = (tid < 128) ? 0u : 32768u;

    float c[4][4][4];
#pragma unroll
    for (int mi = 0; mi < 4; mi++)
#pragma unroll
        for (int ni = 0; ni < 4; ni++)
#pragma unroll
            for (int k = 0; k < 4; k++) c[mi][ni][k] = 0.f;

    const int arow0 = wm * 64 + (quad & 1) * 8 + rr;
    const int acolq = (quad >> 1) * 8;
    const int brow0 = wn * 32 + (quad >> 1) * 8 + rr;
    const int bcolq = (quad & 1) * 8;

    // raw-copy staging: 8 uint4 hi + 8 uint4 lo per thread per chunk
    auto sts_tile = [&](const uint4* sh, const uint4* sl, uint32_t hb, uint32_t lb) {
#pragma unroll
        for (int i = 0; i < 8; i++) {
            const int gi = lt + 128 * i;
            const int r = gi >> 3, g = gi & 7;
            const uint32_t off = (uint32_t)(r * 128 + g * 16);
            const uint32_t sw  = off ^ ((off >> 3) & 0x70);
            STSV4(hb + sw, sh[i].x, sh[i].y, sh[i].z, sh[i].w);
            STSV4(lb + sw, sl[i].x, sl[i].y, sl[i].z, sl[i].w);
        }
    };
    auto ldg_tile = [&](int kt, uint4* sh, uint4* sl) {
#pragma unroll
        for (int i = 0; i < 8; i++) {
            const int gi = lt + 128 * i;
            const int r = gi >> 3, g = gi & 7;
            const size_t e = (size_t)r * CDIM + kt * 64 + g * 8;
            sh[i] = *(const uint4*)(MatH + e);
            sl[i] = *(const uint4*)(MatL + e);
        }
    };

    auto compute = [&](int buf) {
        const uint32_t base = sbase + (uint32_t)buf * 65536u;
        const uint32_t AhS = base, AlS = base + 16384u;
        const uint32_t BhS = base + 32768u, BlS = base + 49152u;
#pragma unroll
        for (int sub = 0; sub < 4; sub++) {
            const int kb = sub * 16;
            uint32_t bh[8], bl[8];
#pragma unroll
            for (int p = 0; p < 2; p++) {
                const uint32_t off = (uint32_t)((brow0 + p * 16) * 128 + (kb + bcolq) * 2);
                const uint32_t sw  = off ^ ((off >> 3) & 0x70);
                LDMX4(bh[4 * p], bh[4 * p + 1], bh[4 * p + 2], bh[4 * p + 3], BhS + sw);
                LDMX4(bl[4 * p], bl[4 * p + 1], bl[4 * p + 2], bl[4 * p + 3], BlS + sw);
            }
#pragma unroll
            for (int mi = 0; mi < 4; mi++) {
                uint32_t ah[4], al[4];
                const uint32_t off = (uint32_t)((arow0 + mi * 16) * 128 + (kb + acolq) * 2);
                const uint32_t sw  = off ^ ((off >> 3) & 0x70);
                LDMX4(ah[0], ah[1], ah[2], ah[3], AhS + sw);
                LDMX4(al[0], al[1], al[2], al[3], AlS + sw);
#pragma unroll
                for (int ni = 0; ni < 4; ni++) {
                    MMA16816(c[mi][ni], ah, bh[2 * ni], bh[2 * ni + 1]);
                    MMA16816(c[mi][ni], ah, bl[2 * ni], bl[2 * ni + 1]);
                    MMA16816(c[mi][ni], al, bh[2 * ni], bh[2 * ni + 1]);
                }
            }
        }
    };

    {
        uint4 sh[8], sl[8];
        ldg_tile(0, sh, sl);
        sts_tile(sh, sl, sbase + hiOff, sbase + hiOff + 16384u);
    }
    __syncthreads();

    for (int kt = 0; kt < 32; kt++) {
        const int buf = kt & 1;
        uint4 sh[8], sl[8];
        if (kt < 31) ldg_tile(kt + 1, sh, sl);
        compute(buf);
        if (kt < 31) {
            const uint32_t nb = sbase + (uint32_t)(buf ^ 1) * 65536u + hiOff;
            sts_tile(sh, sl, nb, nb + 16384u);
            __syncthreads();
        }
    }

    // epilogue: fragments -> smem Ct[128][132] fp32 -> gmem
    __syncthreads();
    float* Ct = (float*)sm;
    const int g2 = lane >> 2, t2 = (lane & 3) * 2;
#pragma unroll
    for (int mi = 0; mi < 4; mi++) {
        const int row = wm * 64 + mi * 16 + g2;
#pragma unroll
        for (int ni = 0; ni < 4; ni++) {
            const int col = wn * 32 + ni * 8 + t2;
            Ct[row * 132 + col]           = c[mi][ni][0];
            Ct[row * 132 + col + 1]       = c[mi][ni][1];
            Ct[(row + 8) * 132 + col]     = c[mi][ni][2];
            Ct[(row + 8) * 132 + col + 1] = c[mi][ni][3];
        }
    }
    __syncthreads();

    for (int idx = tid; idx < 128 * 32; idx += 256) {
        const int row = idx >> 5, c4 = (idx & 31) * 4;
        const int n = nBase + c4;
        const float4 bv = *(const float4*)&bias[n];
        float4 v;
        v.x = Ct[row * 132 + c4]     + bv.x;
        v.y = Ct[row * 132 + c4 + 1] + bv.y;
        v.z = Ct[row * 132 + c4 + 2] + bv.z;
        v.w = Ct[row * 132 + c4 + 3] + bv.w;
        const int m = mBase + row;
        if (MODE == 0) {
            *(float4*)&C[(size_t)m * CDIM + n] = v;
        } else {
            const int b = m >> 11, t = m & (T_SEQ - 1);
            const int h = n >> 7, d = n & (HDIM - 1);
            const size_t e = (((size_t)(b * NHEAD + h)) * T_SEQ + t) * HDIM + d;
            uint2 hh, ll;
            hh.x = bfp(v.x, v.y); hh.y = bfp(v.z, v.w);
            ll.x = bfp(bres(v.x), bres(v.y)); ll.y = bfp(bres(v.z), bres(v.w));
            *(uint2*)(Oh + e) = hh;
            *(uint2*)(Ol + e) = ll;
        }
    }
}

// ===========================================================================
// Tensor-core flash attention, causal. Inputs pre-split bf16 hi/lo (raw-copy
// staging, no cvt). Cross-warp softmax stats via smem (R6 fix). Output Y
// written as bf16 hi/lo, transposed [b][h*128+d][t].
// ===========================================================================
#define ATTN_STAT_OFF 114688u
#define ATTN_SMEM_BYTES (114688 + 1024)

__global__ void __launch_bounds__(256, 2)
attn_mma(const __nv_bfloat16* __restrict__ Qh, const __nv_bfloat16* __restrict__ Ql,
         const __nv_bfloat16* __restrict__ Kh, const __nv_bfloat16* __restrict__ Kl,
         const __nv_bfloat16* __restrict__ Vh, const __nv_bfloat16* __restrict__ Vl,
         __nv_bfloat16* __restrict__ Yh, __nv_bfloat16* __restrict__ Yl)
{
    extern __shared__ __align__(1024) char sm[];
    const uint32_t sb = smem_to_u32(sm);
    const uint32_t QHs = sb,          QLs = sb + 16384u;
    const uint32_t KHs = sb + 32768u, KLs = sb + 49152u;
    const uint32_t VHs = sb + 65536u, VLs = sb + 81920u;
    const uint32_t PHs = sb + 98304u, PLs = sb + 106496u;
    float* Mst = (float*)(sm + ATTN_STAT_OFF);          // [2][64]
    float* Sst = (float*)(sm + ATTN_STAT_OFF + 512u);   // [2][64]

    const int tid  = threadIdx.x;
    const int lane = tid & 31;
    const int wid  = tid >> 5;
    const int wm   = wid >> 1;
    const int wn   = wid & 1;
    const int quad = lane >> 3;
    const int rr   = lane & 7;
    const int g    = lane >> 2;
    const int tq   = lane & 3;
    const int qb   = (int)gridDim.x - 1 - (int)blockIdx.x;
    const int bh   = blockIdx.y;

    // ---- stage Q hi/lo (raw uint4 copy, [64][256B] rows, row-XOR swizzle) ----
    {
        const size_t base = ((size_t)bh * T_SEQ + qb * 64) * HDIM;
        const uint4* qh4 = (const uint4*)(Qh + base);
        const uint4* ql4 = (const uint4*)(Ql + base);
        for (int c = tid; c < 1024; c += 256) {
            const int row = c >> 4, gg = c & 15;
            const uint32_t off = (uint32_t)row * 256u +
                                 ((uint32_t)(gg * 16) ^ ((uint32_t)(row & 7) << 4));
            const uint4 vh = qh4[c], vl = ql4[c];
            STSV4(QHs + off, vh.x, vh.y, vh.z, vh.w);
            STSV4(QLs + off, vl.x, vl.y, vl.z, vl.w);
        }
    }

    float o[8][4];
#pragma unroll
    for (int nf = 0; nf < 8; nf++)
#pragma unroll
        for (int k = 0; k < 4; k++) o[nf][k] = 0.f;
    float m_i[2] = {-1e30f, -1e30f}, l_i[2] = {0.f, 0.f};

    const float scale = 0.08838834764831845f;   // 1/sqrt(128)

    for (int jb = 0; jb <= qb; jb++) {
        __syncthreads();

        // ---- stage K, V hi/lo (raw uint4 copies) ----
        {
            const size_t base = ((size_t)bh * T_SEQ + jb * 64) * HDIM;
            const uint4* kh4 = (const uint4*)(Kh + base);
            const uint4* kl4 = (const uint4*)(Kl + base);
            const uint4* vh4 = (const uint4*)(Vh + base);
            const uint4* vl4 = (const uint4*)(Vl + base);
            for (int c = tid; c < 1024; c += 256) {
                const int row = c >> 4, gg = c & 15;
                const uint32_t off = (uint32_t)row * 256u +
                                     ((uint32_t)(gg * 16) ^ ((uint32_t)(row & 7) << 4));
                const uint4 a = kh4[c], b2 = kl4[c], cc = vh4[c], d2 = vl4[c];
                STSV4(KHs + off, a.x, a.y, a.z, a.w);
                STSV4(KLs + off, b2.x, b2.y, b2.z, b2.w);
                STSV4(VHs + off, cc.x, cc.y, cc.z, cc.w);
                STSV4(VLs + off, d2.x, d2.y, d2.z, d2.w);
            }
        }
        __syncthreads();

        // ---- S = Q K^T (16x32 per warp, 3-pass hi/lo) ----
        float s[4][4];
#pragma unroll
        for (int ni = 0; ni < 4; ni++)
#pragma unroll
            for (int k = 0; k < 4; k++) s[ni][k] = 0.f;

#pragma unroll
        for (int kb = 0; kb < 8; kb++) {
            uint32_t ah[4], al[4], bh2[8], bl2[8];
            {
                const int arow = wm * 16 + (quad & 1) * 8 + rr;
                const uint32_t cb = (uint32_t)(kb * 32 + (quad >> 1) * 16);
                const uint32_t off = (uint32_t)arow * 256u + (cb ^ ((uint32_t)(arow & 7) << 4));
                LDMX4(ah[0], ah[1], ah[2], ah[3], QHs + off);
                LDMX4(al[0], al[1], al[2], al[3], QLs + off);
            }
#pragma unroll
            for (int p = 0; p < 2; p++) {
                const int krow = wn * 32 + p * 16 + (quad >> 1) * 8 + rr;
                const uint32_t cb = (uint32_t)(kb * 32 + (quad & 1) * 16);
                const uint32_t off = (uint32_t)krow * 256u + (cb ^ ((uint32_t)(krow & 7) << 4));
                LDMX4(bh2[4 * p], bh2[4 * p + 1], bh2[4 * p + 2], bh2[4 * p + 3], KHs + off);
                LDMX4(bl2[4 * p], bl2[4 * p + 1], bl2[4 * p + 2], bl2[4 * p + 3], KLs + off);
            }
#pragma unroll
            for (int ni = 0; ni < 4; ni++) {
                MMA16816(s[ni], ah, bh2[2 * ni], bh2[2 * ni + 1]);
                MMA16816(s[ni], ah, bl2[2 * ni], bl2[2 * ni + 1]);
                MMA16816(s[ni], al, bh2[2 * ni], bh2[2 * ni + 1]);
            }
        }

        // ---- scale + causal mask ----
        const bool diag = (jb == qb);
#pragma unroll
        for (int ni = 0; ni < 4; ni++)
#pragma unroll
            for (int j = 0; j < 4; j++) {
                float v = s[ni][j] * scale;
                if (diag) {
                    const int rloc = wm * 16 + g + ((j >> 1) << 3);
                    const int kloc = wn * 32 + ni * 8 + 2 * tq + (j & 1);
                    if (kloc > rloc) v = -1e30f;
                }
                s[ni][j] = v;
            }

        // ---- partial row max, publish ----
        float pmx[2];
#pragma unroll
        for (int r = 0; r < 2; r++) {
            float mx = -1e30f;
#pragma unroll
            for (int ni = 0; ni < 4; ni++)
                mx = fmaxf(mx, fmaxf(s[ni][2 * r], s[ni][2 * r + 1]));
            mx = fmaxf(mx, __shfl_xor_sync(0xffffffffu, mx, 1));
            mx = fmaxf(mx, __shfl_xor_sync(0xffffffffu, mx, 2));
            pmx[r] = mx;
        }
        if (tq == 0) {
            Mst[wn * 64 + wm * 16 + g]     = pmx[0];
            Mst[wn * 64 + wm * 16 + g + 8] = pmx[1];
        }
        __syncthreads();

        // ---- combined max -> exp -> partial sums ----
        float alpha[2];
#pragma unroll
        for (int r = 0; r < 2; r++) {
            const int row = wm * 16 + g + r * 8;
            const float mx_all = fmaxf(Mst[row], Mst[64 + row]);
            const float mn = fmaxf(m_i[r], mx_all);
            alpha[r] = __expf(m_i[r] - mn);
            m_i[r] = mn;
            float sum = 0.f;
#pragma unroll
            for (int ni = 0; ni < 4; ni++) {
                const float p0 = __expf(s[ni][2 * r] - mn);
                const float p1 = __expf(s[ni][2 * r + 1] - mn);
                s[ni][2 * r] = p0; s[ni][2 * r + 1] = p1;
                sum += p0 + p1;
            }
            sum += __shfl_xor_sync(0xffffffffu, sum, 1);
            sum += __shfl_xor_sync(0xffffffffu, sum, 2);
            if (tq == 0) Sst[wn * 64 + row] = sum;
#pragma unroll
            for (int nf = 0; nf < 8; nf++) {
                o[nf][2 * r]     *= alpha[r];
                o[nf][2 * r + 1] *= alpha[r];
            }
        }

        // ---- store P hi/lo ([64][128B] SW128) ----
#pragma unroll
        for (int r = 0; r < 2; r++) {
            const int row = wm * 16 + g + r * 8;
            const uint32_t rbase = (uint32_t)row * 128u;
            const uint32_t rx = (uint32_t)(row & 7) << 4;
#pragma unroll
            for (int ni = 0; ni < 4; ni++) {
                const uint32_t cb = (uint32_t)((wn * 32 + ni * 8 + 2 * tq) * 2);
                const uint32_t off = rbase + (cb ^ rx);
                const float p0 = s[ni][2 * r], p1 = s[ni][2 * r + 1];
                STS32(PHs + off, bfp(p0, p1));
                STS32(PLs + off, bfp(bres(p0), bres(p1)));
            }
        }
        __syncthreads();

#pragma unroll
        for (int r = 0; r < 2; r++) {
            const int row = wm * 16 + g + r * 8;
            l_i[r] = l_i[r] * alpha[r] + Sst[row] + Sst[64 + row];
        }

        // ---- O += P V (3-pass hi/lo, V via LDSM.T) ----
#pragma unroll
        for (int kb2 = 0; kb2 < 4; kb2++) {
            uint32_t aph[4], apl[4];
            {
                const int arow = wm * 16 + (quad & 1) * 8 + rr;
                const uint32_t cb = (uint32_t)(kb2 * 32 + (quad >> 1) * 16);
                const uint32_t off = (uint32_t)arow * 128u + (cb ^ ((uint32_t)(arow & 7) << 4));
                LDMX4(aph[0], aph[1], aph[2], aph[3], PHs + off);
                LDMX4(apl[0], apl[1], apl[2], apl[3], PLs + off);
            }
#pragma unroll
            for (int np = 0; np < 4; np++) {
                const int key = kb2 * 16 + (quad & 1) * 8 + rr;
                const uint32_t db = (uint32_t)(wn * 128 + np * 32 + (quad >> 1) * 16);
                const uint32_t off = (uint32_t)key * 256u + (db ^ ((uint32_t)(key & 7) << 4));
                uint32_t vh[4], vl[4];
                LDMX4T(vh[0], vh[1], vh[2], vh[3], VHs + off);
                LDMX4T(vl[0], vl[1], vl[2], vl[3], VLs + off);
                MMA16816(o[2 * np],     aph, vh[0], vh[1]);
                MMA16816(o[2 * np],     aph, vl[0], vl[1]);
                MMA16816(o[2 * np],     apl, vh[0], vh[1]);
                MMA16816(o[2 * np + 1], aph, vh[2], vh[3]);
                MMA16816(o[2 * np + 1], aph, vl[2], vl[3]);
                MMA16816(o[2 * np + 1], apl, vh[2], vh[3]);
            }
        }
    }

    // ---- epilogue: normalize, transpose-stage, store Y hi/lo ----
    __syncthreads();
    const float inv0 = 1.f / l_i[0], inv1 = 1.f / l_i[1];
    float* Od = (float*)sm;   // [128 d][68]
#pragma unroll
    for (int nf = 0; nf < 8; nf++) {
        const int d = wn * 64 + (nf >> 1) * 16 + (nf & 1) * 8 + 2 * tq;
        const int r0 = wm * 16 + g;
        Od[d * 68 + r0]           = o[nf][0] * inv0;
        Od[(d + 1) * 68 + r0]     = o[nf][1] * inv0;
        Od[d * 68 + r0 + 8]       = o[nf][2] * inv1;
        Od[(d + 1) * 68 + r0 + 8] = o[nf][3] * inv1;
    }
    __syncthreads();

    const int b = bh >> 4, h = bh & 15;
    const size_t ybase = ((size_t)(b * CDIM + h * HDIM)) * T_SEQ + (size_t)qb * 64;
    for (int idx = tid; idx < 2048; idx += 256) {
        const int d = idx >> 4, q4 = (idx & 15) * 4;
        const float4 v = *(const float4*)&Od[d * 68 + q4];
        uint2 hh, ll;
        hh.x = bfp(v.x, v.y); hh.y = bfp(v.z, v.w);
        ll.x = bfp(bres(v.x), bres(v.y)); ll.y = bfp(bres(v.z), bres(v.w));
        *(uint2*)(Yh + ybase + (size_t)d * T_SEQ + q4) = hh;
        *(uint2*)(Yl + ybase + (size_t)d * T_SEQ + q4) = ll;
    }
}

// ===========================================================================
extern "C" void kernel_launch(void* const* d_in, const int* in_sizes, int n_in,
                              void* d_out, int out_size)
{
    (void)in_sizes; (void)n_in; (void)out_size;
    const float* x  = (const float*)d_in[0];
    const float* Wq = (const float*)d_in[1];
    const float* bq = (const float*)d_in[2];
    const float* Wk = (const float*)d_in[3];
    const float* bk = (const float*)d_in[4];
    const float* Wv = (const float*)d_in[5];
    const float* bv = (const float*)d_in[6];
    const float* Wp = (const float*)d_in[7];
    const float* bp = (const float*)d_in[8];
    float* out = (float*)d_out;

    __nv_bfloat16 *xh, *xl, *Wh, *Wl, *Qh, *Ql, *Kh, *Kl, *Vh, *Vl, *Yh, *Yl;
    cudaGetSymbolAddress((void**)&xh, g_xh);
    cudaGetSymbolAddress((void**)&xl, g_xl);
    cudaGetSymbolAddress((void**)&Wh, g_Wh);
    cudaGetSymbolAddress((void**)&Wl, g_Wl);
    cudaGetSymbolAddress((void**)&Qh, g_Qh);
    cudaGetSymbolAddress((void**)&Ql, g_Ql);
    cudaGetSymbolAddress((void**)&Kh, g_Kh);
    cudaGetSymbolAddress((void**)&Kl, g_Kl);
    cudaGetSymbolAddress((void**)&Vh, g_Vh);
    cudaGetSymbolAddress((void**)&Vl, g_Vl);
    cudaGetSymbolAddress((void**)&Yh, g_Yh);
    cudaGetSymbolAddress((void**)&Yl, g_Yl);

    cudaFuncSetAttribute(gemm_bf<0>, cudaFuncAttributeMaxDynamicSharedMemorySize,
                         GEMM_SMEM_BYTES);
    cudaFuncSetAttribute(gemm_bf<1>, cudaFuncAttributeMaxDynamicSharedMemorySize,
                         GEMM_SMEM_BYTES);
    cudaFuncSetAttribute(attn_mma, cudaFuncAttributeMaxDynamicSharedMemorySize,
                         ATTN_SMEM_BYTES);

    const size_t WSZ = (size_t)CDIM * CDIM;

    // pre-split fp32 -> bf16 hi/lo (bandwidth-bound)
    {
        const int n4x = MROWS * CDIM / 4;
        const int n4w = CDIM * CDIM / 4;
        cvt_hilo<<<(n4x + 255) / 256, 256>>>(x,  xh, xl, n4x);
        cvt_hilo<<<(n4w + 255) / 256, 256>>>(Wq, Wh + 0 * WSZ, Wl + 0 * WSZ, n4w);
        cvt_hilo<<<(n4w + 255) / 256, 256>>>(Wk, Wh + 1 * WSZ, Wl + 1 * WSZ, n4w);
        cvt_hilo<<<(n4w + 255) / 256, 256>>>(Wv, Wh + 2 * WSZ, Wl + 2 * WSZ, n4w);
        cvt_hilo<<<(n4w + 255) / 256, 256>>>(Wp, Wh + 3 * WSZ, Wl + 3 * WSZ, n4w);
    }

    dim3 gg(CDIM / 128, MROWS / 128);   // (16, 32)

    gemm_bf<1><<<gg, 256, GEMM_SMEM_BYTES>>>(xh, xl, Wh + 0 * WSZ, Wl + 0 * WSZ,
                                             bq, nullptr, Qh, Ql);
    gemm_bf<1><<<gg, 256, GEMM_SMEM_BYTES>>>(xh, xl, Wh + 1 * WSZ, Wl + 1 * WSZ,
                                             bk, nullptr, Kh, Kl);
    gemm_bf<1><<<gg, 256, GEMM_SMEM_BYTES>>>(xh, xl, Wh + 2 * WSZ, Wl + 2 * WSZ,
                                             bv, nullptr, Vh, Vl);

    attn_mma<<<dim3(T_SEQ / 64, BATCH * NHEAD), 256, ATTN_SMEM_BYTES>>>(
        Qh, Ql, Kh, Kl, Vh, Vl, Yh, Yl);

    gemm_bf<0><<<gg, 256, GEMM_SMEM_BYTES>>>(Yh, Yl, Wh + 3 * WSZ, Wl + 3 * WSZ,
                                             bp, out, nullptr, nullptr);
}

// round 8
// speedup vs baseline: 3.3714x; 1.0853x over previous
#include <cuda_runtime.h>
#include <cuda_bf16.h>
#include <cstdint>

#define T_SEQ  2048
#define NHEAD  16
#define HDIM   128
#define BATCH  2
#define CDIM   2048
#define MROWS  (BATCH * T_SEQ)   // 4096

// ---------------------------------------------------------------------------
// Device-global scratch (allocation-free, graph-safe), all bf16 hi/lo pairs
// ---------------------------------------------------------------------------
__device__ __nv_bfloat16 g_xh[(size_t)MROWS * CDIM];
__device__ __nv_bfloat16 g_xl[(size_t)MROWS * CDIM];
__device__ __nv_bfloat16 g_Wh[4][(size_t)CDIM * CDIM];   // q,k,v,p
__device__ __nv_bfloat16 g_Wl[4][(size_t)CDIM * CDIM];
__device__ __nv_bfloat16 g_Qh[(size_t)BATCH * NHEAD * T_SEQ * HDIM];
__device__ __nv_bfloat16 g_Ql[(size_t)BATCH * NHEAD * T_SEQ * HDIM];
__device__ __nv_bfloat16 g_Kh[(size_t)BATCH * NHEAD * T_SEQ * HDIM];
__device__ __nv_bfloat16 g_Kl[(size_t)BATCH * NHEAD * T_SEQ * HDIM];
__device__ __nv_bfloat16 g_Vh[(size_t)BATCH * NHEAD * T_SEQ * HDIM];
__device__ __nv_bfloat16 g_Vl[(size_t)BATCH * NHEAD * T_SEQ * HDIM];
__device__ __nv_bfloat16 g_Yh[(size_t)BATCH * T_SEQ * CDIM];   // [b][c][t]
__device__ __nv_bfloat16 g_Yl[(size_t)BATCH * T_SEQ * CDIM];

// ===========================================================================
// helpers
// ===========================================================================
__device__ __forceinline__ uint32_t smem_to_u32(const void* p) {
    uint32_t a;
    asm("{ .reg .u64 t; cvta.to.shared.u64 t, %1; cvt.u32.u64 %0, t; }"
        : "=r"(a) : "l"(p));
    return a;
}

__device__ __forceinline__ uint32_t bfp(float a, float b) {
    __nv_bfloat162 t = __floats2bfloat162_rn(a, b);
    return *reinterpret_cast<uint32_t*>(&t);
}
__device__ __forceinline__ float bres(float a) {
    return a - __bfloat162float(__float2bfloat16(a));
}

#define LDMX4(r0, r1, r2, r3, addr) \
    asm volatile("ldmatrix.sync.aligned.m8n8.x4.shared.b16 {%0,%1,%2,%3}, [%4];" \
                 : "=r"(r0), "=r"(r1), "=r"(r2), "=r"(r3) : "r"(addr))

#define LDMX4T(r0, r1, r2, r3, addr) \
    asm volatile("ldmatrix.sync.aligned.m8n8.x4.trans.shared.b16 {%0,%1,%2,%3}, [%4];" \
                 : "=r"(r0), "=r"(r1), "=r"(r2), "=r"(r3) : "r"(addr))

#define MMA16816(c, a, b0, b1) \
    asm volatile("mma.sync.aligned.m16n8k16.row.col.f32.bf16.bf16.f32 " \
                 "{%0,%1,%2,%3}, {%4,%5,%6,%7}, {%8,%9}, {%0,%1,%2,%3};" \
                 : "+f"((c)[0]), "+f"((c)[1]), "+f"((c)[2]), "+f"((c)[3]) \
                 : "r"((a)[0]), "r"((a)[1]), "r"((a)[2]), "r"((a)[3]), \
                   "r"(b0), "r"(b1))

#define STSV4(addr, a, b, cc, d) \
    asm volatile("st.shared.v4.b32 [%0], {%1,%2,%3,%4};" \
                 :: "r"(addr), "r"(a), "r"(b), "r"(cc), "r"(d) : "memory")

#define CPASYNC16(saddr, gptr) \
    asm volatile("cp.async.cg.shared.global [%0], [%1], 16;" \
                 :: "r"(saddr), "l"(gptr) : "memory")
#define CPCOMMIT() asm volatile("cp.async.commit_group;" ::: "memory")
#define CPWAIT1()  asm volatile("cp.async.wait_group 1;" ::: "memory")
#define CPWAIT0()  asm volatile("cp.async.wait_group 0;" ::: "memory")

// ===========================================================================
// fp32 -> bf16 hi/lo split (bandwidth-bound, run once per tensor)
// ===========================================================================
__global__ void cvt_hilo(const float* __restrict__ in,
                         __nv_bfloat16* __restrict__ hi,
                         __nv_bfloat16* __restrict__ lo, int n4)
{
    const int i = blockIdx.x * blockDim.x + threadIdx.x;
    if (i >= n4) return;
    const float4 v = ((const float4*)in)[i];
    uint2 h, l;
    h.x = bfp(v.x, v.y); h.y = bfp(v.z, v.w);
    l.x = bfp(bres(v.x), bres(v.y)); l.y = bfp(bres(v.z), bres(v.w));
    ((uint2*)hi)[i] = h;
    ((uint2*)lo)[i] = l;
}

// ===========================================================================
// Tensor-core GEMM, pre-split bf16 hi/lo. CTA tile 64x128 (M x N), K-chunk 64,
// double-buffered 96KB smem -> 2 CTAs/SM. 8 warps = 2(m) x 4(n), warp 32x32.
// MODE 0: fp32 C[m*CDIM+n].  MODE 1: bf16 hi/lo out at ((b*H+h)*T+t)*HD+d.
// Per-buf layout: Ah 0 (8K), Al 8K, Bh 16K (16K), Bl 32K; buf stride 48K.
// ===========================================================================
#define GEMM_SMEM_BYTES (2 * 49152)

template <int MODE>
__global__ void __launch_bounds__(256, 2)
gemm_bf(const __nv_bfloat16* __restrict__ Ah, const __nv_bfloat16* __restrict__ Al,
        const __nv_bfloat16* __restrict__ Bh, const __nv_bfloat16* __restrict__ Bl,
        const float* __restrict__ bias, float* __restrict__ C,
        __nv_bfloat16* __restrict__ Oh, __nv_bfloat16* __restrict__ Ol)
{
    extern __shared__ __align__(1024) char sm[];
    const uint32_t sbase = smem_to_u32(sm);

    const int tid  = threadIdx.x;
    const int wid  = tid >> 5;
    const int lane = tid & 31;
    const int wm   = wid >> 2;        // 0..1 -> rows wm*32
    const int wn   = wid & 3;         // 0..3 -> cols wn*32
    const int quad = lane >> 3;
    const int rr   = lane & 7;
    const int mBase = blockIdx.y * 64;
    const int nBase = blockIdx.x * 128;

    const __nv_bfloat16* Agh = Ah + (size_t)mBase * CDIM;
    const __nv_bfloat16* Agl = Al + (size_t)mBase * CDIM;
    const __nv_bfloat16* Bgh = Bh + (size_t)nBase * CDIM;
    const __nv_bfloat16* Bgl = Bl + (size_t)nBase * CDIM;

    float c[2][4][4];
#pragma unroll
    for (int mi = 0; mi < 2; mi++)
#pragma unroll
        for (int ni = 0; ni < 4; ni++)
#pragma unroll
            for (int k = 0; k < 4; k++) c[mi][ni][k] = 0.f;

    const int arow0 = wm * 32 + (quad & 1) * 8 + rr;
    const int acolq = (quad >> 1) * 8;
    const int brow0 = wn * 32 + (quad >> 1) * 8 + rr;
    const int bcolq = (quad & 1) * 8;

    auto ldg_tile = [&](int kt, uint4* sa, uint4* sal, uint4* sb, uint4* sbl) {
#pragma unroll
        for (int i = 0; i < 2; i++) {
            const int idx = tid + 256 * i;
            const int r = idx >> 3, g = idx & 7;
            const size_t e = (size_t)r * CDIM + kt * 64 + g * 8;
            sa[i]  = *(const uint4*)(Agh + e);
            sal[i] = *(const uint4*)(Agl + e);
        }
#pragma unroll
        for (int i = 0; i < 4; i++) {
            const int idx = tid + 256 * i;
            const int r = idx >> 3, g = idx & 7;
            const size_t e = (size_t)r * CDIM + kt * 64 + g * 8;
            sb[i]  = *(const uint4*)(Bgh + e);
            sbl[i] = *(const uint4*)(Bgl + e);
        }
    };
    auto sts_tile = [&](uint32_t base, const uint4* sa, const uint4* sal,
                        const uint4* sb, const uint4* sbl) {
#pragma unroll
        for (int i = 0; i < 2; i++) {
            const int idx = tid + 256 * i;
            const int r = idx >> 3, g = idx & 7;
            const uint32_t off = (uint32_t)(r * 128 + g * 16);
            const uint32_t sw  = off ^ ((off >> 3) & 0x70);
            STSV4(base + sw,         sa[i].x,  sa[i].y,  sa[i].z,  sa[i].w);
            STSV4(base + 8192u + sw, sal[i].x, sal[i].y, sal[i].z, sal[i].w);
        }
#pragma unroll
        for (int i = 0; i < 4; i++) {
            const int idx = tid + 256 * i;
            const int r = idx >> 3, g = idx & 7;
            const uint32_t off = (uint32_t)(r * 128 + g * 16);
            const uint32_t sw  = off ^ ((off >> 3) & 0x70);
            STSV4(base + 16384u + sw, sb[i].x,  sb[i].y,  sb[i].z,  sb[i].w);
            STSV4(base + 32768u + sw, sbl[i].x, sbl[i].y, sbl[i].z, sbl[i].w);
        }
    };

    auto compute = [&](int buf) {
        const uint32_t base = sbase + (uint32_t)buf * 49152u;
        const uint32_t AhS = base, AlS = base + 8192u;
        const uint32_t BhS = base + 16384u, BlS = base + 32768u;
#pragma unroll
        for (int sub = 0; sub < 4; sub++) {
            const int kb = sub * 16;
            uint32_t bh[8], bl[8];
#pragma unroll
            for (int p = 0; p < 2; p++) {
                const uint32_t off = (uint32_t)((brow0 + p * 16) * 128 + (kb + bcolq) * 2);
                const uint32_t sw  = off ^ ((off >> 3) & 0x70);
                LDMX4(bh[4 * p], bh[4 * p + 1], bh[4 * p + 2], bh[4 * p + 3], BhS + sw);
                LDMX4(bl[4 * p], bl[4 * p + 1], bl[4 * p + 2], bl[4 * p + 3], BlS + sw);
            }
#pragma unroll
            for (int mi = 0; mi < 2; mi++) {
                uint32_t ah[4], al[4];
                const uint32_t off = (uint32_t)((arow0 + mi * 16) * 128 + (kb + acolq) * 2);
                const uint32_t sw  = off ^ ((off >> 3) & 0x70);
                LDMX4(ah[0], ah[1], ah[2], ah[3], AhS + sw);
                LDMX4(al[0], al[1], al[2], al[3], AlS + sw);
#pragma unroll
                for (int ni = 0; ni < 4; ni++) {
                    MMA16816(c[mi][ni], ah, bh[2 * ni], bh[2 * ni + 1]);
                    MMA16816(c[mi][ni], ah, bl[2 * ni], bl[2 * ni + 1]);
                    MMA16816(c[mi][ni], al, bh[2 * ni], bh[2 * ni + 1]);
                }
            }
        }
    };

    {
        uint4 sa[2], sal[2], sb[4], sbl[4];
        ldg_tile(0, sa, sal, sb, sbl);
        sts_tile(sbase, sa, sal, sb, sbl);
    }
    __syncthreads();

    for (int kt = 0; kt < 32; kt++) {
        const int buf = kt & 1;
        uint4 sa[2], sal[2], sb[4], sbl[4];
        if (kt < 31) ldg_tile(kt + 1, sa, sal, sb, sbl);
        compute(buf);
        if (kt < 31) {
            sts_tile(sbase + (uint32_t)(buf ^ 1) * 49152u, sa, sal, sb, sbl);
            __syncthreads();
        }
    }

    // epilogue: fragments -> smem Ct[64][132] fp32 -> gmem
    __syncthreads();
    float* Ct = (float*)sm;
    const int g2 = lane >> 2, t2 = (lane & 3) * 2;
#pragma unroll
    for (int mi = 0; mi < 2; mi++) {
        const int row = wm * 32 + mi * 16 + g2;
#pragma unroll
        for (int ni = 0; ni < 4; ni++) {
            const int col = wn * 32 + ni * 8 + t2;
            Ct[row * 132 + col]           = c[mi][ni][0];
            Ct[row * 132 + col + 1]       = c[mi][ni][1];
            Ct[(row + 8) * 132 + col]     = c[mi][ni][2];
            Ct[(row + 8) * 132 + col + 1] = c[mi][ni][3];
        }
    }
    __syncthreads();

    for (int idx = tid; idx < 64 * 32; idx += 256) {
        const int row = idx >> 5, c4 = (idx & 31) * 4;
        const int n = nBase + c4;
        const float4 bv = *(const float4*)&bias[n];
        float4 v;
        v.x = Ct[row * 132 + c4]     + bv.x;
        v.y = Ct[row * 132 + c4 + 1] + bv.y;
        v.z = Ct[row * 132 + c4 + 2] + bv.z;
        v.w = Ct[row * 132 + c4 + 3] + bv.w;
        const int m = mBase + row;
        if (MODE == 0) {
            *(float4*)&C[(size_t)m * CDIM + n] = v;
        } else {
            const int b = m >> 11, t = m & (T_SEQ - 1);
            const int h = n >> 7, d = n & (HDIM - 1);
            const size_t e = (((size_t)(b * NHEAD + h)) * T_SEQ + t) * HDIM + d;
            uint2 hh, ll;
            hh.x = bfp(v.x, v.y); hh.y = bfp(v.z, v.w);
            ll.x = bfp(bres(v.x), bres(v.y)); ll.y = bfp(bres(v.z), bres(v.w));
            *(uint2*)(Oh + e) = hh;
            *(uint2*)(Ol + e) = ll;
        }
    }
}

// ===========================================================================
// FA2-style tensor-core flash attention, causal. CTA = (bh, 128 q rows),
// 8 warps, each warp owns 16 q rows x ALL 64 keys -> warp-local softmax
// (no stat smem, no stat syncs). P stays in registers (C-frag -> A-frag
// repack). K/V double-buffered via cp.async, prefetched during compute.
// smem: Qh 0 (32K), Ql 32K; KV buf b at 64K + b*64K: KH 0, KL 16K, VH 32K,
// VL 48K. Total 192KB -> 1 CTA/SM. Epilogue aliases smem as Od[128][132].
// ===========================================================================
#define ATTN_SMEM_BYTES 196608

__global__ void __launch_bounds__(256, 1)
attn_mma(const __nv_bfloat16* __restrict__ Qh, const __nv_bfloat16* __restrict__ Ql,
         const __nv_bfloat16* __restrict__ Kh, const __nv_bfloat16* __restrict__ Kl,
         const __nv_bfloat16* __restrict__ Vh, const __nv_bfloat16* __restrict__ Vl,
         __nv_bfloat16* __restrict__ Yh, __nv_bfloat16* __restrict__ Yl)
{
    extern __shared__ __align__(1024) char sm[];
    const uint32_t sb = smem_to_u32(sm);
    const uint32_t QHs = sb, QLs = sb + 32768u;

    const int tid  = threadIdx.x;
    const int lane = tid & 31;
    const int w    = tid >> 5;        // warp 0..7 -> q rows w*16..+15
    const int quad = lane >> 3;
    const int rr   = lane & 7;
    const int g    = lane >> 2;
    const int tq   = lane & 3;
    const int qb   = (int)gridDim.x - 1 - (int)blockIdx.x;  // heavy first
    const int bh   = blockIdx.y;

    const size_t headbase = (size_t)bh * T_SEQ * HDIM;
    const int jend = 2 * qb + 1;

    // cp.async stage of K/V hi/lo for block jb into buffer b
    auto stage_kv = [&](int jb, int b) {
        const size_t base = headbase + (size_t)jb * 64 * HDIM;
        const char* kh = (const char*)(Kh + base);
        const char* kl = (const char*)(Kl + base);
        const char* vh = (const char*)(Vh + base);
        const char* vl = (const char*)(Vl + base);
        const uint32_t bufb = sb + 65536u + (uint32_t)b * 65536u;
#pragma unroll
        for (int i = 0; i < 4; i++) {
            const int c = tid + 256 * i;
            const int row = c >> 4, gg = c & 15;
            const uint32_t off = (uint32_t)row * 256u +
                                 ((uint32_t)(gg * 16) ^ ((uint32_t)(row & 7) << 4));
            const size_t gb = (size_t)c * 16;
            CPASYNC16(bufb + off,           kh + gb);
            CPASYNC16(bufb + 16384u + off,  kl + gb);
            CPASYNC16(bufb + 32768u + off,  vh + gb);
            CPASYNC16(bufb + 49152u + off,  vl + gb);
        }
    };

    // preload K/V block 0, then stage Q (direct STS)
    stage_kv(0, 0);
    CPCOMMIT();
    {
        const size_t base = headbase + (size_t)qb * 128 * HDIM;
        const uint4* qh4 = (const uint4*)(Qh + base);
        const uint4* ql4 = (const uint4*)(Ql + base);
#pragma unroll
        for (int i = 0; i < 8; i++) {
            const int c = tid + 256 * i;
            const int row = c >> 4, gg = c & 15;
            const uint32_t off = (uint32_t)row * 256u +
                                 ((uint32_t)(gg * 16) ^ ((uint32_t)(row & 7) << 4));
            const uint4 vh = qh4[c], vl = ql4[c];
            STSV4(QHs + off, vh.x, vh.y, vh.z, vh.w);
            STSV4(QLs + off, vl.x, vl.y, vl.z, vl.w);
        }
    }

    float o[16][4];
#pragma unroll
    for (int nd = 0; nd < 16; nd++)
#pragma unroll
        for (int k = 0; k < 4; k++) o[nd][k] = 0.f;
    float m_i[2] = {-1e30f, -1e30f}, l_i[2] = {0.f, 0.f};

    const float scale = 0.08838834764831845f;   // 1/sqrt(128)
    const int R0 = qb * 128 + w * 16;           // warp's first q row

    for (int jb = 0; jb <= jend; jb++) {
        const int buf = jb & 1;
        if (jb < jend) { stage_kv(jb + 1, buf ^ 1); CPCOMMIT(); }
        if (jb < jend) { CPWAIT1(); } else { CPWAIT0(); }
        __syncthreads();   // K/V block jb visible to all warps

        if (jb * 64 <= R0 + 15) {   // warp has at least one unmasked key
            const uint32_t KHb = sb + 65536u + (uint32_t)buf * 65536u;
            const uint32_t KLb = KHb + 16384u;
            const uint32_t VHb = KHb + 32768u;
            const uint32_t VLb = KHb + 49152u;

            // ---- S = Q K^T : 16 rows x 64 keys, 3-pass hi/lo ----
            float s[8][4];
#pragma unroll
            for (int ni = 0; ni < 8; ni++)
#pragma unroll
                for (int k = 0; k < 4; k++) s[ni][k] = 0.f;

#pragma unroll
            for (int kb = 0; kb < 8; kb++) {
                uint32_t ah[4], al[4];
                {
                    const int arow = w * 16 + (quad & 1) * 8 + rr;
                    const uint32_t cb = (uint32_t)(kb * 32 + (quad >> 1) * 16);
                    const uint32_t off = (uint32_t)arow * 256u +
                                         (cb ^ ((uint32_t)(arow & 7) << 4));
                    LDMX4(ah[0], ah[1], ah[2], ah[3], QHs + off);
                    LDMX4(al[0], al[1], al[2], al[3], QLs + off);
                }
#pragma unroll
                for (int p = 0; p < 4; p++) {
                    uint32_t bh2[4], bl2[4];
                    const int krow = p * 16 + (quad >> 1) * 8 + rr;
                    const uint32_t cb = (uint32_t)(kb * 32 + (quad & 1) * 16);
                    const uint32_t off = (uint32_t)krow * 256u +
                                         (cb ^ ((uint32_t)(krow & 7) << 4));
                    LDMX4(bh2[0], bh2[1], bh2[2], bh2[3], KHb + off);
                    LDMX4(bl2[0], bl2[1], bl2[2], bl2[3], KLb + off);
                    MMA16816(s[2 * p],     ah, bh2[0], bh2[1]);
                    MMA16816(s[2 * p],     ah, bl2[0], bl2[1]);
                    MMA16816(s[2 * p],     al, bh2[0], bh2[1]);
                    MMA16816(s[2 * p + 1], ah, bh2[2], bh2[3]);
                    MMA16816(s[2 * p + 1], ah, bl2[2], bl2[3]);
                    MMA16816(s[2 * p + 1], al, bh2[2], bh2[3]);
                }
            }

            // ---- scale + causal mask ----
            const bool needmask = (jb * 64 + 63 > R0);
#pragma unroll
            for (int ni = 0; ni < 8; ni++)
#pragma unroll
                for (int j = 0; j < 4; j++) {
                    float v = s[ni][j] * scale;
                    if (needmask) {
                        const int rglob = R0 + g + ((j >> 1) << 3);
                        const int kglob = jb * 64 + ni * 8 + 2 * tq + (j & 1);
                        if (kglob > rglob) v = -1e30f;
                    }
                    s[ni][j] = v;
                }

            // ---- warp-local online softmax (rows g, g+8) ----
            float alpha[2];
#pragma unroll
            for (int r = 0; r < 2; r++) {
                float mx = -1e30f;
#pragma unroll
                for (int ni = 0; ni < 8; ni++)
                    mx = fmaxf(mx, fmaxf(s[ni][2 * r], s[ni][2 * r + 1]));
                mx = fmaxf(mx, __shfl_xor_sync(0xffffffffu, mx, 1));
                mx = fmaxf(mx, __shfl_xor_sync(0xffffffffu, mx, 2));
                const float mn = fmaxf(m_i[r], mx);
                alpha[r] = __expf(m_i[r] - mn);
                m_i[r] = mn;
                float sum = 0.f;
#pragma unroll
                for (int ni = 0; ni < 8; ni++) {
                    const float p0 = __expf(s[ni][2 * r] - mn);
                    const float p1 = __expf(s[ni][2 * r + 1] - mn);
                    s[ni][2 * r] = p0; s[ni][2 * r + 1] = p1;
                    sum += p0 + p1;
                }
                sum += __shfl_xor_sync(0xffffffffu, sum, 1);
                sum += __shfl_xor_sync(0xffffffffu, sum, 2);
                l_i[r] = l_i[r] * alpha[r] + sum;
#pragma unroll
                for (int nd = 0; nd < 16; nd++) {
                    o[nd][2 * r]     *= alpha[r];
                    o[nd][2 * r + 1] *= alpha[r];
                }
            }

            // ---- O += P V : P packed from S frags in registers ----
#pragma unroll
            for (int kc = 0; kc < 4; kc++) {
                uint32_t aph[4], apl[4];
                const float* s0 = s[2 * kc];
                const float* s1 = s[2 * kc + 1];
                aph[0] = bfp(s0[0], s0[1]);
                aph[1] = bfp(s0[2], s0[3]);
                aph[2] = bfp(s1[0], s1[1]);
                aph[3] = bfp(s1[2], s1[3]);
                apl[0] = bfp(bres(s0[0]), bres(s0[1]));
                apl[1] = bfp(bres(s0[2]), bres(s0[3]));
                apl[2] = bfp(bres(s1[0]), bres(s1[1]));
                apl[3] = bfp(bres(s1[2]), bres(s1[3]));
#pragma unroll
                for (int nd = 0; nd < 8; nd++) {
                    const int key = kc * 16 + (quad & 1) * 8 + rr;
                    const uint32_t db = (uint32_t)(nd * 32 + (quad >> 1) * 16);
                    const uint32_t off = (uint32_t)key * 256u +
                                         (db ^ ((uint32_t)(key & 7) << 4));
                    uint32_t vh[4], vl[4];
                    LDMX4T(vh[0], vh[1], vh[2], vh[3], VHb + off);
                    LDMX4T(vl[0], vl[1], vl[2], vl[3], VLb + off);
                    MMA16816(o[2 * nd],     aph, vh[0], vh[1]);
                    MMA16816(o[2 * nd],     aph, vl[0], vl[1]);
                    MMA16816(o[2 * nd],     apl, vh[0], vh[1]);
                    MMA16816(o[2 * nd + 1], aph, vh[2], vh[3]);
                    MMA16816(o[2 * nd + 1], aph, vl[2], vl[3]);
                    MMA16816(o[2 * nd + 1], apl, vh[2], vh[3]);
                }
            }
        }
        __syncthreads();   // all warps done reading buf before it is re-filled
    }

    // ---- epilogue: normalize, transpose-stage, store Y hi/lo [d][t] ----
    const float inv0 = 1.f / l_i[0], inv1 = 1.f / l_i[1];
    float* Od = (float*)sm;   // [128 d][132]
#pragma unroll
    for (int nd = 0; nd < 16; nd++) {
        const int d = nd * 8 + 2 * tq;
        const int t0 = w * 16 + g;
        Od[d * 132 + t0]           = o[nd][0] * inv0;
        Od[(d + 1) * 132 + t0]     = o[nd][1] * inv0;
        Od[d * 132 + t0 + 8]       = o[nd][2] * inv1;
        Od[(d + 1) * 132 + t0 + 8] = o[nd][3] * inv1;
    }
    __syncthreads();

    const int b = bh >> 4, h = bh & 15;
    const size_t ybase = ((size_t)(b * CDIM + h * HDIM)) * T_SEQ + (size_t)qb * 128;
    for (int idx = tid; idx < 128 * 32; idx += 256) {
        const int d = idx >> 5, q4 = (idx & 31) * 4;
        const float4 v = *(const float4*)&Od[d * 132 + q4];
        uint2 hh, ll;
        hh.x = bfp(v.x, v.y); hh.y = bfp(v.z, v.w);
        ll.x = bfp(bres(v.x), bres(v.y)); ll.y = bfp(bres(v.z), bres(v.w));
        *(uint2*)(Yh + ybase + (size_t)d * T_SEQ + q4) = hh;
        *(uint2*)(Yl + ybase + (size_t)d * T_SEQ + q4) = ll;
    }
}

// ===========================================================================
extern "C" void kernel_launch(void* const* d_in, const int* in_sizes, int n_in,
                              void* d_out, int out_size)
{
    (void)in_sizes; (void)n_in; (void)out_size;
    const float* x  = (const float*)d_in[0];
    const float* Wq = (const float*)d_in[1];
    const float* bq = (const float*)d_in[2];
    const float* Wk = (const float*)d_in[3];
    const float* bk = (const float*)d_in[4];
    const float* Wv = (const float*)d_in[5];
    const float* bv = (const float*)d_in[6];
    const float* Wp = (const float*)d_in[7];
    const float* bp = (const float*)d_in[8];
    float* out = (float*)d_out;

    __nv_bfloat16 *xh, *xl, *Wh, *Wl, *Qh, *Ql, *Kh, *Kl, *Vh, *Vl, *Yh, *Yl;
    cudaGetSymbolAddress((void**)&xh, g_xh);
    cudaGetSymbolAddress((void**)&xl, g_xl);
    cudaGetSymbolAddress((void**)&Wh, g_Wh);
    cudaGetSymbolAddress((void**)&Wl, g_Wl);
    cudaGetSymbolAddress((void**)&Qh, g_Qh);
    cudaGetSymbolAddress((void**)&Ql, g_Ql);
    cudaGetSymbolAddress((void**)&Kh, g_Kh);
    cudaGetSymbolAddress((void**)&Kl, g_Kl);
    cudaGetSymbolAddress((void**)&Vh, g_Vh);
    cudaGetSymbolAddress((void**)&Vl, g_Vl);
    cudaGetSymbolAddress((void**)&Yh, g_Yh);
    cudaGetSymbolAddress((void**)&Yl, g_Yl);

    cudaFuncSetAttribute(gemm_bf<0>, cudaFuncAttributeMaxDynamicSharedMemorySize,
                         GEMM_SMEM_BYTES);
    cudaFuncSetAttribute(gemm_bf<1>, cudaFuncAttributeMaxDynamicSharedMemorySize,
                         GEMM_SMEM_BYTES);
    cudaFuncSetAttribute(attn_mma, cudaFuncAttributeMaxDynamicSharedMemorySize,
                         ATTN_SMEM_BYTES);

    const size_t WSZ = (size_t)CDIM * CDIM;

    // pre-split fp32 -> bf16 hi/lo (bandwidth-bound)
    {
        const int n4x = MROWS * CDIM / 4;
        const int n4w = CDIM * CDIM / 4;
        cvt_hilo<<<(n4x + 255) / 256, 256>>>(x,  xh, xl, n4x);
        cvt_hilo<<<(n4w + 255) / 256, 256>>>(Wq, Wh + 0 * WSZ, Wl + 0 * WSZ, n4w);
        cvt_hilo<<<(n4w + 255) / 256, 256>>>(Wk, Wh + 1 * WSZ, Wl + 1 * WSZ, n4w);
        cvt_hilo<<<(n4w + 255) / 256, 256>>>(Wv, Wh + 2 * WSZ, Wl + 2 * WSZ, n4w);
        cvt_hilo<<<(n4w + 255) / 256, 256>>>(Wp, Wh + 3 * WSZ, Wl + 3 * WSZ, n4w);
    }

    dim3 gg(CDIM / 128, MROWS / 64);   // (16, 64)

    gemm_bf<1><<<gg, 256, GEMM_SMEM_BYTES>>>(xh, xl, Wh + 0 * WSZ, Wl + 0 * WSZ,
                                             bq, nullptr, Qh, Ql);
    gemm_bf<1><<<gg, 256, GEMM_SMEM_BYTES>>>(xh, xl, Wh + 1 * WSZ, Wl + 1 * WSZ,
                                             bk, nullptr, Kh, Kl);
    gemm_bf<1><<<gg, 256, GEMM_SMEM_BYTES>>>(xh, xl, Wh + 2 * WSZ, Wl + 2 * WSZ,
                                             bv, nullptr, Vh, Vl);

    attn_mma<<<dim3(T_SEQ / 128, BATCH * NHEAD), 256, ATTN_SMEM_BYTES>>>(
        Qh, Ql, Kh, Kl, Vh, Vl, Yh, Yl);

    gemm_bf<0><<<gg, 256, GEMM_SMEM_BYTES>>>(Yh, Yl, Wh + 3 * WSZ, Wl + 3 * WSZ,
                                             bp, out, nullptr, nullptr);
}

// round 9
// speedup vs baseline: 5.5020x; 1.6320x over previous
#include <cuda_runtime.h>
#include <cuda_fp16.h>
#include <cstdint>

#define T_SEQ  2048
#define NHEAD  16
#define HDIM   128
#define BATCH  2
#define CDIM   2048
#define MROWS  (BATCH * T_SEQ)   // 4096

// ---------------------------------------------------------------------------
// Device-global scratch (allocation-free, graph-safe), fp16
// x, Q, P, Y carry hi/lo pairs (exact); W, K, V are fp16-rounded (hi only).
// ---------------------------------------------------------------------------
__device__ __half g_xh[(size_t)MROWS * CDIM];
__device__ __half g_xl[(size_t)MROWS * CDIM];
__device__ __half g_Wh[4][(size_t)CDIM * CDIM];   // q,k,v,p
__device__ __half g_Qh[(size_t)BATCH * NHEAD * T_SEQ * HDIM];
__device__ __half g_Ql[(size_t)BATCH * NHEAD * T_SEQ * HDIM];
__device__ __half g_Kh[(size_t)BATCH * NHEAD * T_SEQ * HDIM];
__device__ __half g_Vh[(size_t)BATCH * NHEAD * T_SEQ * HDIM];
__device__ __half g_Yh[(size_t)BATCH * T_SEQ * CDIM];   // [b][c][t]
__device__ __half g_Yl[(size_t)BATCH * T_SEQ * CDIM];

// ===========================================================================
// helpers
// ===========================================================================
__device__ __forceinline__ uint32_t smem_to_u32(const void* p) {
    uint32_t a;
    asm("{ .reg .u64 t; cvta.to.shared.u64 t, %1; cvt.u32.u64 %0, t; }"
        : "=r"(a) : "l"(p));
    return a;
}

__device__ __forceinline__ uint32_t hfp(float a, float b) {
    __half2 t = __floats2half2_rn(a, b);
    return *reinterpret_cast<uint32_t*>(&t);
}
__device__ __forceinline__ float hres(float a) {
    return a - __half2float(__float2half_rn(a));
}

#define LDMX4(r0, r1, r2, r3, addr) \
    asm volatile("ldmatrix.sync.aligned.m8n8.x4.shared.b16 {%0,%1,%2,%3}, [%4];" \
                 : "=r"(r0), "=r"(r1), "=r"(r2), "=r"(r3) : "r"(addr))

#define LDMX4T(r0, r1, r2, r3, addr) \
    asm volatile("ldmatrix.sync.aligned.m8n8.x4.trans.shared.b16 {%0,%1,%2,%3}, [%4];" \
                 : "=r"(r0), "=r"(r1), "=r"(r2), "=r"(r3) : "r"(addr))

#define MMA16816(c, a, b0, b1) \
    asm volatile("mma.sync.aligned.m16n8k16.row.col.f32.f16.f16.f32 " \
                 "{%0,%1,%2,%3}, {%4,%5,%6,%7}, {%8,%9}, {%0,%1,%2,%3};" \
                 : "+f"((c)[0]), "+f"((c)[1]), "+f"((c)[2]), "+f"((c)[3]) \
                 : "r"((a)[0]), "r"((a)[1]), "r"((a)[2]), "r"((a)[3]), \
                   "r"(b0), "r"(b1))

#define STSV4(addr, a, b, cc, d) \
    asm volatile("st.shared.v4.b32 [%0], {%1,%2,%3,%4};" \
                 :: "r"(addr), "r"(a), "r"(b), "r"(cc), "r"(d) : "memory")

#define CPASYNC16(saddr, gptr) \
    asm volatile("cp.async.cg.shared.global [%0], [%1], 16;" \
                 :: "r"(saddr), "l"(gptr) : "memory")
#define CPCOMMIT() asm volatile("cp.async.commit_group;" ::: "memory")
#define CPWAIT1()  asm volatile("cp.async.wait_group 1;" ::: "memory")
#define CPWAIT0()  asm volatile("cp.async.wait_group 0;" ::: "memory")

// ===========================================================================
// fp32 -> fp16 splits (bandwidth-bound, run once per tensor)
// ===========================================================================
__global__ void cvt_hilo(const float* __restrict__ in,
                         __half* __restrict__ hi, __half* __restrict__ lo, int n4)
{
    const int i = blockIdx.x * blockDim.x + threadIdx.x;
    if (i >= n4) return;
    const float4 v = ((const float4*)in)[i];
    uint2 h, l;
    h.x = hfp(v.x, v.y); h.y = hfp(v.z, v.w);
    l.x = hfp(hres(v.x), hres(v.y)); l.y = hfp(hres(v.z), hres(v.w));
    ((uint2*)hi)[i] = h;
    ((uint2*)lo)[i] = l;
}

__global__ void cvt_hi(const float* __restrict__ in, __half* __restrict__ hi, int n4)
{
    const int i = blockIdx.x * blockDim.x + threadIdx.x;
    if (i >= n4) return;
    const float4 v = ((const float4*)in)[i];
    uint2 h;
    h.x = hfp(v.x, v.y); h.y = hfp(v.z, v.w);
    ((uint2*)hi)[i] = h;
}

// ===========================================================================
// Tensor-core GEMM, fp16 2-pass (A hi/lo corrected, B fp16-rounded):
// C(M,N) = A(M,K) @ W(N,K)^T + bias(N).
// CTA tile 64x128, K-chunk 64, double-buffered 64KB smem -> 2 CTAs/SM.
// MODE 0: fp32 C out.  MODE 1: fused QKV (grid.x=48, mat=blockIdx.x>>4);
//   mat 0 -> Q hi/lo, mat 1 -> K hi, mat 2 -> V hi, all in head layout.
// Per-buf layout: Ah 0 (8K), Al 8K, Bh 16K (16K); buf stride 32K.
// ===========================================================================
#define GEMM_SMEM_BYTES 65536

template <int MODE>
__global__ void __launch_bounds__(256, 2)
gemm_h(const __half* __restrict__ Ah, const __half* __restrict__ Al,
       const __half* __restrict__ Wh,
       const float* __restrict__ b0, const float* __restrict__ b1,
       const float* __restrict__ b2,
       float* __restrict__ C,
       __half* __restrict__ Qo, __half* __restrict__ Qlo,
       __half* __restrict__ Ko, __half* __restrict__ Vo)
{
    extern __shared__ __align__(1024) char sm[];
    const uint32_t sbase = smem_to_u32(sm);

    const int tid  = threadIdx.x;
    const int wid  = tid >> 5;
    const int lane = tid & 31;
    const int wm   = wid >> 2;        // 0..1 -> rows wm*32
    const int wn   = wid & 3;         // 0..3 -> cols wn*32
    const int quad = lane >> 3;
    const int rr   = lane & 7;
    const int mat  = (MODE == 1) ? ((int)blockIdx.x >> 4) : 0;
    const int nbx  = (MODE == 1) ? ((int)blockIdx.x & 15) : (int)blockIdx.x;
    const int mBase = blockIdx.y * 64;
    const int nBase = nbx * 128;

    const __half* Agh = Ah + (size_t)mBase * CDIM;
    const __half* Agl = Al + (size_t)mBase * CDIM;
    const __half* Bgh = Wh + (size_t)mat * CDIM * CDIM + (size_t)nBase * CDIM;
    const float* bias = (MODE == 0) ? b0 : (mat == 0 ? b0 : (mat == 1 ? b1 : b2));

    float c[2][4][4];
#pragma unroll
    for (int mi = 0; mi < 2; mi++)
#pragma unroll
        for (int ni = 0; ni < 4; ni++)
#pragma unroll
            for (int k = 0; k < 4; k++) c[mi][ni][k] = 0.f;

    const int arow0 = wm * 32 + (quad & 1) * 8 + rr;
    const int acolq = (quad >> 1) * 8;
    const int brow0 = wn * 32 + (quad >> 1) * 8 + rr;
    const int bcolq = (quad & 1) * 8;

    auto ldg_tile = [&](int kt, uint4* sa, uint4* sal, uint4* sb) {
#pragma unroll
        for (int i = 0; i < 2; i++) {
            const int idx = tid + 256 * i;
            const int r = idx >> 3, g = idx & 7;
            const size_t e = (size_t)r * CDIM + kt * 64 + g * 8;
            sa[i]  = *(const uint4*)(Agh + e);
            sal[i] = *(const uint4*)(Agl + e);
        }
#pragma unroll
        for (int i = 0; i < 4; i++) {
            const int idx = tid + 256 * i;
            const int r = idx >> 3, g = idx & 7;
            const size_t e = (size_t)r * CDIM + kt * 64 + g * 8;
            sb[i] = *(const uint4*)(Bgh + e);
        }
    };
    auto sts_tile = [&](uint32_t base, const uint4* sa, const uint4* sal,
                        const uint4* sb) {
#pragma unroll
        for (int i = 0; i < 2; i++) {
            const int idx = tid + 256 * i;
            const int r = idx >> 3, g = idx & 7;
            const uint32_t off = (uint32_t)(r * 128 + g * 16);
            const uint32_t sw  = off ^ ((off >> 3) & 0x70);
            STSV4(base + sw,         sa[i].x,  sa[i].y,  sa[i].z,  sa[i].w);
            STSV4(base + 8192u + sw, sal[i].x, sal[i].y, sal[i].z, sal[i].w);
        }
#pragma unroll
        for (int i = 0; i < 4; i++) {
            const int idx = tid + 256 * i;
            const int r = idx >> 3, g = idx & 7;
            const uint32_t off = (uint32_t)(r * 128 + g * 16);
            const uint32_t sw  = off ^ ((off >> 3) & 0x70);
            STSV4(base + 16384u + sw, sb[i].x, sb[i].y, sb[i].z, sb[i].w);
        }
    };

    auto compute = [&](int buf) {
        const uint32_t base = sbase + (uint32_t)buf * 32768u;
        const uint32_t AhS = base, AlS = base + 8192u, BhS = base + 16384u;
#pragma unroll
        for (int sub = 0; sub < 4; sub++) {
            const int kb = sub * 16;
            uint32_t bh[8];
#pragma unroll
            for (int p = 0; p < 2; p++) {
                const uint32_t off = (uint32_t)((brow0 + p * 16) * 128 + (kb + bcolq) * 2);
                const uint32_t sw  = off ^ ((off >> 3) & 0x70);
                LDMX4(bh[4 * p], bh[4 * p + 1], bh[4 * p + 2], bh[4 * p + 3], BhS + sw);
            }
#pragma unroll
            for (int mi = 0; mi < 2; mi++) {
                uint32_t ah[4], al[4];
                const uint32_t off = (uint32_t)((arow0 + mi * 16) * 128 + (kb + acolq) * 2);
                const uint32_t sw  = off ^ ((off >> 3) & 0x70);
                LDMX4(ah[0], ah[1], ah[2], ah[3], AhS + sw);
                LDMX4(al[0], al[1], al[2], al[3], AlS + sw);
#pragma unroll
                for (int ni = 0; ni < 4; ni++) {
                    MMA16816(c[mi][ni], ah, bh[2 * ni], bh[2 * ni + 1]);
                    MMA16816(c[mi][ni], al, bh[2 * ni], bh[2 * ni + 1]);
                }
            }
        }
    };

    {
        uint4 sa[2], sal[2], sb[4];
        ldg_tile(0, sa, sal, sb);
        sts_tile(sbase, sa, sal, sb);
    }
    __syncthreads();

    for (int kt = 0; kt < 32; kt++) {
        const int buf = kt & 1;
        uint4 sa[2], sal[2], sb[4];
        if (kt < 31) ldg_tile(kt + 1, sa, sal, sb);
        compute(buf);
        if (kt < 31) {
            sts_tile(sbase + (uint32_t)(buf ^ 1) * 32768u, sa, sal, sb);
            __syncthreads();
        }
    }

    // epilogue: fragments -> smem Ct[64][132] fp32 -> gmem
    __syncthreads();
    float* Ct = (float*)sm;
    const int g2 = lane >> 2, t2 = (lane & 3) * 2;
#pragma unroll
    for (int mi = 0; mi < 2; mi++) {
        const int row = wm * 32 + mi * 16 + g2;
#pragma unroll
        for (int ni = 0; ni < 4; ni++) {
            const int col = wn * 32 + ni * 8 + t2;
            Ct[row * 132 + col]           = c[mi][ni][0];
            Ct[row * 132 + col + 1]       = c[mi][ni][1];
            Ct[(row + 8) * 132 + col]     = c[mi][ni][2];
            Ct[(row + 8) * 132 + col + 1] = c[mi][ni][3];
        }
    }
    __syncthreads();

    for (int idx = tid; idx < 64 * 32; idx += 256) {
        const int row = idx >> 5, c4 = (idx & 31) * 4;
        const int n = nBase + c4;
        const float4 bv = *(const float4*)&bias[n];
        float4 v;
        v.x = Ct[row * 132 + c4]     + bv.x;
        v.y = Ct[row * 132 + c4 + 1] + bv.y;
        v.z = Ct[row * 132 + c4 + 2] + bv.z;
        v.w = Ct[row * 132 + c4 + 3] + bv.w;
        const int m = mBase + row;
        if (MODE == 0) {
            *(float4*)&C[(size_t)m * CDIM + n] = v;
        } else {
            const int b = m >> 11, t = m & (T_SEQ - 1);
            const int h = n >> 7, d = n & (HDIM - 1);
            const size_t e = (((size_t)(b * NHEAD + h)) * T_SEQ + t) * HDIM + d;
            uint2 hh;
            hh.x = hfp(v.x, v.y); hh.y = hfp(v.z, v.w);
            if (mat == 0) {
                uint2 ll;
                ll.x = hfp(hres(v.x), hres(v.y)); ll.y = hfp(hres(v.z), hres(v.w));
                *(uint2*)(Qo + e)  = hh;
                *(uint2*)(Qlo + e) = ll;
            } else {
                __half* dst = (mat == 1) ? Ko : Vo;
                *(uint2*)(dst + e) = hh;
            }
        }
    }
}

// ===========================================================================
// FA2-style tensor-core flash attention, causal, fp16 2-pass.
// CTA = (bh, 128 q rows), 8 warps, warp-local softmax, P in registers
// (hi/lo split on pack), K/V fp16 hi-only, cp.async double-buffered.
// smem: Qh 0 (32K), Ql 32K; KV buf b at 64K + b*32K: KH 0 (16K), VH 16K.
// Total 128KB. Epilogue aliases smem as Od[128][132] fp32.
// ===========================================================================
#define ATTN_SMEM_BYTES 131072

__global__ void __launch_bounds__(256, 1)
attn_mma(const __half* __restrict__ Qh, const __half* __restrict__ Ql,
         const __half* __restrict__ Kh, const __half* __restrict__ Vh,
         __half* __restrict__ Yh, __half* __restrict__ Yl)
{
    extern __shared__ __align__(1024) char sm[];
    const uint32_t sb = smem_to_u32(sm);
    const uint32_t QHs = sb, QLs = sb + 32768u;

    const int tid  = threadIdx.x;
    const int lane = tid & 31;
    const int w    = tid >> 5;
    const int quad = lane >> 3;
    const int rr   = lane & 7;
    const int g    = lane >> 2;
    const int tq   = lane & 3;
    const int qb   = (int)gridDim.x - 1 - (int)blockIdx.x;  // heavy first
    const int bh   = blockIdx.y;

    const size_t headbase = (size_t)bh * T_SEQ * HDIM;
    const int jend = 2 * qb + 1;

    auto stage_kv = [&](int jb, int b) {
        const size_t base = headbase + (size_t)jb * 64 * HDIM;
        const char* kh = (const char*)(Kh + base);
        const char* vh = (const char*)(Vh + base);
        const uint32_t bufb = sb + 65536u + (uint32_t)b * 32768u;
#pragma unroll
        for (int i = 0; i < 4; i++) {
            const int c = tid + 256 * i;
            const int row = c >> 4, gg = c & 15;
            const uint32_t off = (uint32_t)row * 256u +
                                 ((uint32_t)(gg * 16) ^ ((uint32_t)(row & 7) << 4));
            const size_t gb = (size_t)c * 16;
            CPASYNC16(bufb + off,          kh + gb);
            CPASYNC16(bufb + 16384u + off, vh + gb);
        }
    };

    stage_kv(0, 0);
    CPCOMMIT();
    {
        const size_t base = headbase + (size_t)qb * 128 * HDIM;
        const uint4* qh4 = (const uint4*)(Qh + base);
        const uint4* ql4 = (const uint4*)(Ql + base);
#pragma unroll
        for (int i = 0; i < 8; i++) {
            const int c = tid + 256 * i;
            const int row = c >> 4, gg = c & 15;
            const uint32_t off = (uint32_t)row * 256u +
                                 ((uint32_t)(gg * 16) ^ ((uint32_t)(row & 7) << 4));
            const uint4 vh = qh4[c], vl = ql4[c];
            STSV4(QHs + off, vh.x, vh.y, vh.z, vh.w);
            STSV4(QLs + off, vl.x, vl.y, vl.z, vl.w);
        }
    }

    float o[16][4];
#pragma unroll
    for (int nd = 0; nd < 16; nd++)
#pragma unroll
        for (int k = 0; k < 4; k++) o[nd][k] = 0.f;
    float m_i[2] = {-1e30f, -1e30f}, l_i[2] = {0.f, 0.f};

    const float scale = 0.08838834764831845f;   // 1/sqrt(128)
    const int R0 = qb * 128 + w * 16;

    for (int jb = 0; jb <= jend; jb++) {
        const int buf = jb & 1;
        if (jb < jend) { stage_kv(jb + 1, buf ^ 1); CPCOMMIT(); }
        if (jb < jend) { CPWAIT1(); } else { CPWAIT0(); }
        __syncthreads();

        if (jb * 64 <= R0 + 15) {
            const uint32_t KHb = sb + 65536u + (uint32_t)buf * 32768u;
            const uint32_t VHb = KHb + 16384u;

            // ---- S = Q K^T : 16 rows x 64 keys, 2-pass (Q hi/lo, K fp16) ----
            float s[8][4];
#pragma unroll
            for (int ni = 0; ni < 8; ni++)
#pragma unroll
                for (int k = 0; k < 4; k++) s[ni][k] = 0.f;

#pragma unroll
            for (int kb = 0; kb < 8; kb++) {
                uint32_t ah[4], al[4];
                {
                    const int arow = w * 16 + (quad & 1) * 8 + rr;
                    const uint32_t cb = (uint32_t)(kb * 32 + (quad >> 1) * 16);
                    const uint32_t off = (uint32_t)arow * 256u +
                                         (cb ^ ((uint32_t)(arow & 7) << 4));
                    LDMX4(ah[0], ah[1], ah[2], ah[3], QHs + off);
                    LDMX4(al[0], al[1], al[2], al[3], QLs + off);
                }
#pragma unroll
                for (int p = 0; p < 4; p++) {
                    uint32_t bh2[4];
                    const int krow = p * 16 + (quad >> 1) * 8 + rr;
                    const uint32_t cb = (uint32_t)(kb * 32 + (quad & 1) * 16);
                    const uint32_t off = (uint32_t)krow * 256u +
                                         (cb ^ ((uint32_t)(krow & 7) << 4));
                    LDMX4(bh2[0], bh2[1], bh2[2], bh2[3], KHb + off);
                    MMA16816(s[2 * p],     ah, bh2[0], bh2[1]);
                    MMA16816(s[2 * p],     al, bh2[0], bh2[1]);
                    MMA16816(s[2 * p + 1], ah, bh2[2], bh2[3]);
                    MMA16816(s[2 * p + 1], al, bh2[2], bh2[3]);
                }
            }

            // ---- scale + causal mask ----
            const bool needmask = (jb * 64 + 63 > R0);
#pragma unroll
            for (int ni = 0; ni < 8; ni++)
#pragma unroll
                for (int j = 0; j < 4; j++) {
                    float v = s[ni][j] * scale;
                    if (needmask) {
                        const int rglob = R0 + g + ((j >> 1) << 3);
                        const int kglob = jb * 64 + ni * 8 + 2 * tq + (j & 1);
                        if (kglob > rglob) v = -1e30f;
                    }
                    s[ni][j] = v;
                }

            // ---- warp-local online softmax (rows g, g+8) ----
            float alpha[2];
#pragma unroll
            for (int r = 0; r < 2; r++) {
                float mx = -1e30f;
#pragma unroll
                for (int ni = 0; ni < 8; ni++)
                    mx = fmaxf(mx, fmaxf(s[ni][2 * r], s[ni][2 * r + 1]));
                mx = fmaxf(mx, __shfl_xor_sync(0xffffffffu, mx, 1));
                mx = fmaxf(mx, __shfl_xor_sync(0xffffffffu, mx, 2));
                const float mn = fmaxf(m_i[r], mx);
                alpha[r] = __expf(m_i[r] - mn);
                m_i[r] = mn;
                float sum = 0.f;
#pragma unroll
                for (int ni = 0; ni < 8; ni++) {
                    const float p0 = __expf(s[ni][2 * r] - mn);
                    const float p1 = __expf(s[ni][2 * r + 1] - mn);
                    s[ni][2 * r] = p0; s[ni][2 * r + 1] = p1;
                    sum += p0 + p1;
                }
                sum += __shfl_xor_sync(0xffffffffu, sum, 1);
                sum += __shfl_xor_sync(0xffffffffu, sum, 2);
                l_i[r] = l_i[r] * alpha[r] + sum;
#pragma unroll
                for (int nd = 0; nd < 16; nd++) {
                    o[nd][2 * r]     *= alpha[r];
                    o[nd][2 * r + 1] *= alpha[r];
                }
            }

            // ---- O += P V : P hi/lo packed in regs, V fp16 (2-pass) ----
#pragma unroll
            for (int kc = 0; kc < 4; kc++) {
                uint32_t aph[4], apl[4];
                const float* s0 = s[2 * kc];
                const float* s1 = s[2 * kc + 1];
                aph[0] = hfp(s0[0], s0[1]);
                aph[1] = hfp(s0[2], s0[3]);
                aph[2] = hfp(s1[0], s1[1]);
                aph[3] = hfp(s1[2], s1[3]);
                apl[0] = hfp(hres(s0[0]), hres(s0[1]));
                apl[1] = hfp(hres(s0[2]), hres(s0[3]));
                apl[2] = hfp(hres(s1[0]), hres(s1[1]));
                apl[3] = hfp(hres(s1[2]), hres(s1[3]));
#pragma unroll
                for (int nd = 0; nd < 8; nd++) {
                    const int key = kc * 16 + (quad & 1) * 8 + rr;
                    const uint32_t db = (uint32_t)(nd * 32 + (quad >> 1) * 16);
                    const uint32_t off = (uint32_t)key * 256u +
                                         (db ^ ((uint32_t)(key & 7) << 4));
                    uint32_t vh[4];
                    LDMX4T(vh[0], vh[1], vh[2], vh[3], VHb + off);
                    MMA16816(o[2 * nd],     aph, vh[0], vh[1]);
                    MMA16816(o[2 * nd],     apl, vh[0], vh[1]);
                    MMA16816(o[2 * nd + 1], aph, vh[2], vh[3]);
                    MMA16816(o[2 * nd + 1], apl, vh[2], vh[3]);
                }
            }
        }
        __syncthreads();
    }

    // ---- epilogue: normalize, transpose-stage, store Y hi/lo [d][t] ----
    const float inv0 = 1.f / l_i[0], inv1 = 1.f / l_i[1];
    float* Od = (float*)sm;   // [128 d][132]
#pragma unroll
    for (int nd = 0; nd < 16; nd++) {
        const int d = nd * 8 + 2 * tq;
        const int t0 = w * 16 + g;
        Od[d * 132 + t0]           = o[nd][0] * inv0;
        Od[(d + 1) * 132 + t0]     = o[nd][1] * inv0;
        Od[d * 132 + t0 + 8]       = o[nd][2] * inv1;
        Od[(d + 1) * 132 + t0 + 8] = o[nd][3] * inv1;
    }
    __syncthreads();

    const int b = bh >> 4, h = bh & 15;
    const size_t ybase = ((size_t)(b * CDIM + h * HDIM)) * T_SEQ + (size_t)qb * 128;
    for (int idx = tid; idx < 128 * 32; idx += 256) {
        const int d = idx >> 5, q4 = (idx & 31) * 4;
        const float4 v = *(const float4*)&Od[d * 132 + q4];
        uint2 hh, ll;
        hh.x = hfp(v.x, v.y); hh.y = hfp(v.z, v.w);
        ll.x = hfp(hres(v.x), hres(v.y)); ll.y = hfp(hres(v.z), hres(v.w));
        *(uint2*)(Yh + ybase + (size_t)d * T_SEQ + q4) = hh;
        *(uint2*)(Yl + ybase + (size_t)d * T_SEQ + q4) = ll;
    }
}

// ===========================================================================
extern "C" void kernel_launch(void* const* d_in, const int* in_sizes, int n_in,
                              void* d_out, int out_size)
{
    (void)in_sizes; (void)n_in; (void)out_size;
    const float* x  = (const float*)d_in[0];
    const float* Wq = (const float*)d_in[1];
    const float* bq = (const float*)d_in[2];
    const float* Wk = (const float*)d_in[3];
    const float* bk = (const float*)d_in[4];
    const float* Wv = (const float*)d_in[5];
    const float* bv = (const float*)d_in[6];
    const float* Wp = (const float*)d_in[7];
    const float* bp = (const float*)d_in[8];
    float* out = (float*)d_out;

    __half *xh, *xl, *Wh, *Qh, *Ql, *Kh, *Vh, *Yh, *Yl;
    cudaGetSymbolAddress((void**)&xh, g_xh);
    cudaGetSymbolAddress((void**)&xl, g_xl);
    cudaGetSymbolAddress((void**)&Wh, g_Wh);
    cudaGetSymbolAddress((void**)&Qh, g_Qh);
    cudaGetSymbolAddress((void**)&Ql, g_Ql);
    cudaGetSymbolAddress((void**)&Kh, g_Kh);
    cudaGetSymbolAddress((void**)&Vh, g_Vh);
    cudaGetSymbolAddress((void**)&Yh, g_Yh);
    cudaGetSymbolAddress((void**)&Yl, g_Yl);

    cudaFuncSetAttribute(gemm_h<0>, cudaFuncAttributeMaxDynamicSharedMemorySize,
                         GEMM_SMEM_BYTES);
    cudaFuncSetAttribute(gemm_h<1>, cudaFuncAttributeMaxDynamicSharedMemorySize,
                         GEMM_SMEM_BYTES);
    cudaFuncSetAttribute(attn_mma, cudaFuncAttributeMaxDynamicSharedMemorySize,
                         ATTN_SMEM_BYTES);

    const size_t WSZ = (size_t)CDIM * CDIM;

    // pre-split fp32 -> fp16 (x: hi/lo; weights: hi only)
    {
        const int n4x = MROWS * CDIM / 4;
        const int n4w = CDIM * CDIM / 4;
        cvt_hilo<<<(n4x + 255) / 256, 256>>>(x, xh, xl, n4x);
        cvt_hi<<<(n4w + 255) / 256, 256>>>(Wq, Wh + 0 * WSZ, n4w);
        cvt_hi<<<(n4w + 255) / 256, 256>>>(Wk, Wh + 1 * WSZ, n4w);
        cvt_hi<<<(n4w + 255) / 256, 256>>>(Wv, Wh + 2 * WSZ, n4w);
        cvt_hi<<<(n4w + 255) / 256, 256>>>(Wp, Wh + 3 * WSZ, n4w);
    }

    // fused QKV GEMM: grid.x = 3 mats x 16 n-tiles
    gemm_h<1><<<dim3(48, MROWS / 64), 256, GEMM_SMEM_BYTES>>>(
        xh, xl, Wh, bq, bk, bv, nullptr, Qh, Ql, Kh, Vh);

    attn_mma<<<dim3(T_SEQ / 128, BATCH * NHEAD), 256, ATTN_SMEM_BYTES>>>(
        Qh, Ql, Kh, Vh, Yh, Yl);

    gemm_h<0><<<dim3(16, MROWS / 64), 256, GEMM_SMEM_BYTES>>>(
        Yh, Yl, Wh + 3 * WSZ, bp, nullptr, nullptr, out,
        nullptr, nullptr, nullptr, nullptr);
}

// round 10
// speedup vs baseline: 5.9912x; 1.0889x over previous
#include <cuda_runtime.h>
#include <cuda_fp16.h>
#include <cstdint>

#define T_SEQ  2048
#define NHEAD  16
#define HDIM   128
#define BATCH  2
#define CDIM   2048
#define MROWS  (BATCH * T_SEQ)   // 4096

// ---------------------------------------------------------------------------
// Device-global scratch (allocation-free, graph-safe), fp16
// x, Q, P, Y carry hi/lo pairs (exact); W, K, V are fp16-rounded (hi only).
// ---------------------------------------------------------------------------
__device__ __half g_xh[(size_t)MROWS * CDIM];
__device__ __half g_xl[(size_t)MROWS * CDIM];
__device__ __half g_Wh[4][(size_t)CDIM * CDIM];   // q,k,v,p
__device__ __half g_Qh[(size_t)BATCH * NHEAD * T_SEQ * HDIM];
__device__ __half g_Ql[(size_t)BATCH * NHEAD * T_SEQ * HDIM];
__device__ __half g_Kh[(size_t)BATCH * NHEAD * T_SEQ * HDIM];
__device__ __half g_Vh[(size_t)BATCH * NHEAD * T_SEQ * HDIM];
__device__ __half g_Yh[(size_t)BATCH * T_SEQ * CDIM];   // [b][c][t]
__device__ __half g_Yl[(size_t)BATCH * T_SEQ * CDIM];

// ===========================================================================
// helpers
// ===========================================================================
__device__ __forceinline__ uint32_t smem_to_u32(const void* p) {
    uint32_t a;
    asm("{ .reg .u64 t; cvta.to.shared.u64 t, %1; cvt.u32.u64 %0, t; }"
        : "=r"(a) : "l"(p));
    return a;
}

__device__ __forceinline__ uint32_t hfp(float a, float b) {
    __half2 t = __floats2half2_rn(a, b);
    return *reinterpret_cast<uint32_t*>(&t);
}
__device__ __forceinline__ float hres(float a) {
    return a - __half2float(__float2half_rn(a));
}

#define LDMX4(r0, r1, r2, r3, addr) \
    asm volatile("ldmatrix.sync.aligned.m8n8.x4.shared.b16 {%0,%1,%2,%3}, [%4];" \
                 : "=r"(r0), "=r"(r1), "=r"(r2), "=r"(r3) : "r"(addr))

#define LDMX4T(r0, r1, r2, r3, addr) \
    asm volatile("ldmatrix.sync.aligned.m8n8.x4.trans.shared.b16 {%0,%1,%2,%3}, [%4];" \
                 : "=r"(r0), "=r"(r1), "=r"(r2), "=r"(r3) : "r"(addr))

#define MMA16816(c, a, b0, b1) \
    asm volatile("mma.sync.aligned.m16n8k16.row.col.f32.f16.f16.f32 " \
                 "{%0,%1,%2,%3}, {%4,%5,%6,%7}, {%8,%9}, {%0,%1,%2,%3};" \
                 : "+f"((c)[0]), "+f"((c)[1]), "+f"((c)[2]), "+f"((c)[3]) \
                 : "r"((a)[0]), "r"((a)[1]), "r"((a)[2]), "r"((a)[3]), \
                   "r"(b0), "r"(b1))

#define STSV4(addr, a, b, cc, d) \
    asm volatile("st.shared.v4.b32 [%0], {%1,%2,%3,%4};" \
                 :: "r"(addr), "r"(a), "r"(b), "r"(cc), "r"(d) : "memory")

#define CPASYNC16(saddr, gptr) \
    asm volatile("cp.async.cg.shared.global [%0], [%1], 16;" \
                 :: "r"(saddr), "l"(gptr) : "memory")
#define CPCOMMIT() asm volatile("cp.async.commit_group;" ::: "memory")
#define CPWAIT1()  asm volatile("cp.async.wait_group 1;" ::: "memory")
#define CPWAIT0()  asm volatile("cp.async.wait_group 0;" ::: "memory")

// ===========================================================================
// fused fp32 -> fp16 conversion: x (hi/lo) + 4 weights (hi) in ONE launch
// ===========================================================================
#define N4X (MROWS * CDIM / 4)
#define N4W (CDIM * CDIM / 4)

__global__ void cvt_all(const float* __restrict__ x,
                        __half* __restrict__ xh, __half* __restrict__ xl,
                        const float* __restrict__ Wq, const float* __restrict__ Wk,
                        const float* __restrict__ Wv, const float* __restrict__ Wp,
                        __half* __restrict__ Wh)
{
    const int i = blockIdx.x * blockDim.x + threadIdx.x;
    if (i < N4X) {
        const float4 v = ((const float4*)x)[i];
        uint2 h, l;
        h.x = hfp(v.x, v.y); h.y = hfp(v.z, v.w);
        l.x = hfp(hres(v.x), hres(v.y)); l.y = hfp(hres(v.z), hres(v.w));
        ((uint2*)xh)[i] = h;
        ((uint2*)xl)[i] = l;
    } else {
        const int j = i - N4X;
        const int mat = j >> 20;            // j / N4W (N4W = 2^20)
        const int k   = j & (N4W - 1);
        if (mat < 4) {
            const float* W = (mat == 0) ? Wq : (mat == 1) ? Wk
                                             : (mat == 2) ? Wv : Wp;
            const float4 v = ((const float4*)W)[k];
            uint2 h;
            h.x = hfp(v.x, v.y); h.y = hfp(v.z, v.w);
            ((uint2*)(Wh + (size_t)mat * CDIM * CDIM))[k] = h;
        }
    }
}

// ===========================================================================
// Tensor-core GEMM, fp16 2-pass (A hi/lo corrected, B fp16-rounded):
// C(M,N) = A(M,K) @ W(N,K)^T + bias(N).
// CTA tile 64x128, K-chunk 64, 3-stage cp.async pipeline (96KB) -> 2 CTAs/SM.
// MODE 0: fp32 C out.  MODE 1: fused QKV (grid.x=48, mat=blockIdx.x>>4).
// Per-stage layout (32KB): Ah 0 (8K), Al 8K, Bh 16K (16K).
// ===========================================================================
#define GEMM_SMEM_BYTES 98304

template <int MODE>
__global__ void __launch_bounds__(256, 2)
gemm_h(const __half* __restrict__ Ah, const __half* __restrict__ Al,
       const __half* __restrict__ Wh,
       const float* __restrict__ b0, const float* __restrict__ b1,
       const float* __restrict__ b2,
       float* __restrict__ C,
       __half* __restrict__ Qo, __half* __restrict__ Qlo,
       __half* __restrict__ Ko, __half* __restrict__ Vo)
{
    extern __shared__ __align__(1024) char sm[];
    const uint32_t sbase = smem_to_u32(sm);

    const int tid  = threadIdx.x;
    const int wid  = tid >> 5;
    const int lane = tid & 31;
    const int wm   = wid >> 2;        // 0..1 -> rows wm*32
    const int wn   = wid & 3;         // 0..3 -> cols wn*32
    const int quad = lane >> 3;
    const int rr   = lane & 7;
    const int mat  = (MODE == 1) ? ((int)blockIdx.x >> 4) : 0;
    const int nbx  = (MODE == 1) ? ((int)blockIdx.x & 15) : (int)blockIdx.x;
    const int mBase = blockIdx.y * 64;
    const int nBase = nbx * 128;

    const __half* Agh = Ah + (size_t)mBase * CDIM;
    const __half* Agl = Al + (size_t)mBase * CDIM;
    const __half* Bgh = Wh + (size_t)mat * CDIM * CDIM + (size_t)nBase * CDIM;
    const float* bias = (MODE == 0) ? b0 : (mat == 0 ? b0 : (mat == 1 ? b1 : b2));

    float c[2][4][4];
#pragma unroll
    for (int mi = 0; mi < 2; mi++)
#pragma unroll
        for (int ni = 0; ni < 4; ni++)
#pragma unroll
            for (int k = 0; k < 4; k++) c[mi][ni][k] = 0.f;

    const int arow0 = wm * 32 + (quad & 1) * 8 + rr;
    const int acolq = (quad >> 1) * 8;
    const int brow0 = wn * 32 + (quad >> 1) * 8 + rr;
    const int bcolq = (quad & 1) * 8;

    // cp.async staging of chunk kt into stage stg (no register round-trip)
    auto stage_load = [&](int kt, int stg) {
        const uint32_t base = sbase + (uint32_t)stg * 32768u;
#pragma unroll
        for (int i = 0; i < 2; i++) {
            const int idx = tid + 256 * i;
            const int r = idx >> 3, g = idx & 7;
            const uint32_t off = (uint32_t)(r * 128 + g * 16);
            const uint32_t sw  = off ^ ((off >> 3) & 0x70);
            const size_t e = (size_t)r * CDIM + kt * 64 + g * 8;
            CPASYNC16(base + sw,         (const char*)(Agh + e));
            CPASYNC16(base + 8192u + sw, (const char*)(Agl + e));
        }
#pragma unroll
        for (int i = 0; i < 4; i++) {
            const int idx = tid + 256 * i;
            const int r = idx >> 3, g = idx & 7;
            const uint32_t off = (uint32_t)(r * 128 + g * 16);
            const uint32_t sw  = off ^ ((off >> 3) & 0x70);
            const size_t e = (size_t)r * CDIM + kt * 64 + g * 8;
            CPASYNC16(base + 16384u + sw, (const char*)(Bgh + e));
        }
    };

    auto compute = [&](int stg) {
        const uint32_t base = sbase + (uint32_t)stg * 32768u;
        const uint32_t AhS = base, AlS = base + 8192u, BhS = base + 16384u;
#pragma unroll
        for (int sub = 0; sub < 4; sub++) {
            const int kb = sub * 16;
            uint32_t bh[8];
#pragma unroll
            for (int p = 0; p < 2; p++) {
                const uint32_t off = (uint32_t)((brow0 + p * 16) * 128 + (kb + bcolq) * 2);
                const uint32_t sw  = off ^ ((off >> 3) & 0x70);
                LDMX4(bh[4 * p], bh[4 * p + 1], bh[4 * p + 2], bh[4 * p + 3], BhS + sw);
            }
#pragma unroll
            for (int mi = 0; mi < 2; mi++) {
                uint32_t ah[4], al[4];
                const uint32_t off = (uint32_t)((arow0 + mi * 16) * 128 + (kb + acolq) * 2);
                const uint32_t sw  = off ^ ((off >> 3) & 0x70);
                LDMX4(ah[0], ah[1], ah[2], ah[3], AhS + sw);
                LDMX4(al[0], al[1], al[2], al[3], AlS + sw);
#pragma unroll
                for (int ni = 0; ni < 4; ni++) {
                    MMA16816(c[mi][ni], ah, bh[2 * ni], bh[2 * ni + 1]);
                    MMA16816(c[mi][ni], al, bh[2 * ni], bh[2 * ni + 1]);
                }
            }
        }
    };

    stage_load(0, 0); CPCOMMIT();
    stage_load(1, 1); CPCOMMIT();

    int stg = 0;
    for (int kt = 0; kt < 32; kt++) {
        if (kt + 1 < 32) { CPWAIT1(); } else { CPWAIT0(); }
        __syncthreads();   // chunk kt visible to all; prev compute on stage (kt+2)%3 done
        if (kt + 2 < 32) {
            int ns = stg + 2; if (ns >= 3) ns -= 3;
            stage_load(kt + 2, ns);
            CPCOMMIT();
        }
        compute(stg);
        if (++stg == 3) stg = 0;
    }

    // epilogue: fragments -> smem Ct[64][132] fp32 -> gmem
    __syncthreads();
    float* Ct = (float*)sm;
    const int g2 = lane >> 2, t2 = (lane & 3) * 2;
#pragma unroll
    for (int mi = 0; mi < 2; mi++) {
        const int row = wm * 32 + mi * 16 + g2;
#pragma unroll
        for (int ni = 0; ni < 4; ni++) {
            const int col = wn * 32 + ni * 8 + t2;
            Ct[row * 132 + col]           = c[mi][ni][0];
            Ct[row * 132 + col + 1]       = c[mi][ni][1];
            Ct[(row + 8) * 132 + col]     = c[mi][ni][2];
            Ct[(row + 8) * 132 + col + 1] = c[mi][ni][3];
        }
    }
    __syncthreads();

    for (int idx = tid; idx < 64 * 32; idx += 256) {
        const int row = idx >> 5, c4 = (idx & 31) * 4;
        const int n = nBase + c4;
        const float4 bv = *(const float4*)&bias[n];
        float4 v;
        v.x = Ct[row * 132 + c4]     + bv.x;
        v.y = Ct[row * 132 + c4 + 1] + bv.y;
        v.z = Ct[row * 132 + c4 + 2] + bv.z;
        v.w = Ct[row * 132 + c4 + 3] + bv.w;
        const int m = mBase + row;
        if (MODE == 0) {
            *(float4*)&C[(size_t)m * CDIM + n] = v;
        } else {
            const int b = m >> 11, t = m & (T_SEQ - 1);
            const int h = n >> 7, d = n & (HDIM - 1);
            const size_t e = (((size_t)(b * NHEAD + h)) * T_SEQ + t) * HDIM + d;
            uint2 hh;
            hh.x = hfp(v.x, v.y); hh.y = hfp(v.z, v.w);
            if (mat == 0) {
                uint2 ll;
                ll.x = hfp(hres(v.x), hres(v.y)); ll.y = hfp(hres(v.z), hres(v.w));
                *(uint2*)(Qo + e)  = hh;
                *(uint2*)(Qlo + e) = ll;
            } else {
                __half* dst = (mat == 1) ? Ko : Vo;
                *(uint2*)(dst + e) = hh;
            }
        }
    }
}

// ===========================================================================
// FA2-style tensor-core flash attention, causal, fp16 2-pass (unchanged R9).
// ===========================================================================
#define ATTN_SMEM_BYTES 131072

__global__ void __launch_bounds__(256, 1)
attn_mma(const __half* __restrict__ Qh, const __half* __restrict__ Ql,
         const __half* __restrict__ Kh, const __half* __restrict__ Vh,
         __half* __restrict__ Yh, __half* __restrict__ Yl)
{
    extern __shared__ __align__(1024) char sm[];
    const uint32_t sb = smem_to_u32(sm);
    const uint32_t QHs = sb, QLs = sb + 32768u;

    const int tid  = threadIdx.x;
    const int lane = tid & 31;
    const int w    = tid >> 5;
    const int quad = lane >> 3;
    const int rr   = lane & 7;
    const int g    = lane >> 2;
    const int tq   = lane & 3;
    const int qb   = (int)gridDim.x - 1 - (int)blockIdx.x;  // heavy first
    const int bh   = blockIdx.y;

    const size_t headbase = (size_t)bh * T_SEQ * HDIM;
    const int jend = 2 * qb + 1;

    auto stage_kv = [&](int jb, int b) {
        const size_t base = headbase + (size_t)jb * 64 * HDIM;
        const char* kh = (const char*)(Kh + base);
        const char* vh = (const char*)(Vh + base);
        const uint32_t bufb = sb + 65536u + (uint32_t)b * 32768u;
#pragma unroll
        for (int i = 0; i < 4; i++) {
            const int c = tid + 256 * i;
            const int row = c >> 4, gg = c & 15;
            const uint32_t off = (uint32_t)row * 256u +
                                 ((uint32_t)(gg * 16) ^ ((uint32_t)(row & 7) << 4));
            const size_t gb = (size_t)c * 16;
            CPASYNC16(bufb + off,          kh + gb);
            CPASYNC16(bufb + 16384u + off, vh + gb);
        }
    };

    stage_kv(0, 0);
    CPCOMMIT();
    {
        const size_t base = headbase + (size_t)qb * 128 * HDIM;
        const uint4* qh4 = (const uint4*)(Qh + base);
        const uint4* ql4 = (const uint4*)(Ql + base);
#pragma unroll
        for (int i = 0; i < 8; i++) {
            const int c = tid + 256 * i;
            const int row = c >> 4, gg = c & 15;
            const uint32_t off = (uint32_t)row * 256u +
                                 ((uint32_t)(gg * 16) ^ ((uint32_t)(row & 7) << 4));
            const uint4 vh = qh4[c], vl = ql4[c];
            STSV4(QHs + off, vh.x, vh.y, vh.z, vh.w);
            STSV4(QLs + off, vl.x, vl.y, vl.z, vl.w);
        }
    }

    float o[16][4];
#pragma unroll
    for (int nd = 0; nd < 16; nd++)
#pragma unroll
        for (int k = 0; k < 4; k++) o[nd][k] = 0.f;
    float m_i[2] = {-1e30f, -1e30f}, l_i[2] = {0.f, 0.f};

    const float scale = 0.08838834764831845f;   // 1/sqrt(128)
    const int R0 = qb * 128 + w * 16;

    for (int jb = 0; jb <= jend; jb++) {
        const int buf = jb & 1;
        if (jb < jend) { stage_kv(jb + 1, buf ^ 1); CPCOMMIT(); }
        if (jb < jend) { CPWAIT1(); } else { CPWAIT0(); }
        __syncthreads();

        if (jb * 64 <= R0 + 15) {
            const uint32_t KHb = sb + 65536u + (uint32_t)buf * 32768u;
            const uint32_t VHb = KHb + 16384u;

            // ---- S = Q K^T : 16 rows x 64 keys, 2-pass (Q hi/lo, K fp16) ----
            float s[8][4];
#pragma unroll
            for (int ni = 0; ni < 8; ni++)
#pragma unroll
                for (int k = 0; k < 4; k++) s[ni][k] = 0.f;

#pragma unroll
            for (int kb = 0; kb < 8; kb++) {
                uint32_t ah[4], al[4];
                {
                    const int arow = w * 16 + (quad & 1) * 8 + rr;
                    const uint32_t cb = (uint32_t)(kb * 32 + (quad >> 1) * 16);
                    const uint32_t off = (uint32_t)arow * 256u +
                                         (cb ^ ((uint32_t)(arow & 7) << 4));
                    LDMX4(ah[0], ah[1], ah[2], ah[3], QHs + off);
                    LDMX4(al[0], al[1], al[2], al[3], QLs + off);
                }
#pragma unroll
                for (int p = 0; p < 4; p++) {
                    uint32_t bh2[4];
                    const int krow = p * 16 + (quad >> 1) * 8 + rr;
                    const uint32_t cb = (uint32_t)(kb * 32 + (quad & 1) * 16);
                    const uint32_t off = (uint32_t)krow * 256u +
                                         (cb ^ ((uint32_t)(krow & 7) << 4));
                    LDMX4(bh2[0], bh2[1], bh2[2], bh2[3], KHb + off);
                    MMA16816(s[2 * p],     ah, bh2[0], bh2[1]);
                    MMA16816(s[2 * p],     al, bh2[0], bh2[1]);
                    MMA16816(s[2 * p + 1], ah, bh2[2], bh2[3]);
                    MMA16816(s[2 * p + 1], al, bh2[2], bh2[3]);
                }
            }

            // ---- scale + causal mask ----
            const bool needmask = (jb * 64 + 63 > R0);
#pragma unroll
            for (int ni = 0; ni < 8; ni++)
#pragma unroll
                for (int j = 0; j < 4; j++) {
                    float v = s[ni][j] * scale;
                    if (needmask) {
                        const int rglob = R0 + g + ((j >> 1) << 3);
                        const int kglob = jb * 64 + ni * 8 + 2 * tq + (j & 1);
                        if (kglob > rglob) v = -1e30f;
                    }
                    s[ni][j] = v;
                }

            // ---- warp-local online softmax (rows g, g+8) ----
            float alpha[2];
#pragma unroll
            for (int r = 0; r < 2; r++) {
                float mx = -1e30f;
#pragma unroll
                for (int ni = 0; ni < 8; ni++)
                    mx = fmaxf(mx, fmaxf(s[ni][2 * r], s[ni][2 * r + 1]));
                mx = fmaxf(mx, __shfl_xor_sync(0xffffffffu, mx, 1));
                mx = fmaxf(mx, __shfl_xor_sync(0xffffffffu, mx, 2));
                const float mn = fmaxf(m_i[r], mx);
                alpha[r] = __expf(m_i[r] - mn);
                m_i[r] = mn;
                float sum = 0.f;
#pragma unroll
                for (int ni = 0; ni < 8; ni++) {
                    const float p0 = __expf(s[ni][2 * r] - mn);
                    const float p1 = __expf(s[ni][2 * r + 1] - mn);
                    s[ni][2 * r] = p0; s[ni][2 * r + 1] = p1;
                    sum += p0 + p1;
                }
                sum += __shfl_xor_sync(0xffffffffu, sum, 1);
                sum += __shfl_xor_sync(0xffffffffu, sum, 2);
                l_i[r] = l_i[r] * alpha[r] + sum;
#pragma unroll
                for (int nd = 0; nd < 16; nd++) {
                    o[nd][2 * r]     *= alpha[r];
                    o[nd][2 * r + 1] *= alpha[r];
                }
            }

            // ---- O += P V : P hi/lo packed in regs, V fp16 (2-pass) ----
#pragma unroll
            for (int kc = 0; kc < 4; kc++) {
                uint32_t aph[4], apl[4];
                const float* s0 = s[2 * kc];
                const float* s1 = s[2 * kc + 1];
                aph[0] = hfp(s0[0], s0[1]);
                aph[1] = hfp(s0[2], s0[3]);
                aph[2] = hfp(s1[0], s1[1]);
                aph[3] = hfp(s1[2], s1[3]);
                apl[0] = hfp(hres(s0[0]), hres(s0[1]));
                apl[1] = hfp(hres(s0[2]), hres(s0[3]));
                apl[2] = hfp(hres(s1[0]), hres(s1[1]));
                apl[3] = hfp(hres(s1[2]), hres(s1[3]));
#pragma unroll
                for (int nd = 0; nd < 8; nd++) {
                    const int key = kc * 16 + (quad & 1) * 8 + rr;
                    const uint32_t db = (uint32_t)(nd * 32 + (quad >> 1) * 16);
                    const uint32_t off = (uint32_t)key * 256u +
                                         (db ^ ((uint32_t)(key & 7) << 4));
                    uint32_t vh[4];
                    LDMX4T(vh[0], vh[1], vh[2], vh[3], VHb + off);
                    MMA16816(o[2 * nd],     aph, vh[0], vh[1]);
                    MMA16816(o[2 * nd],     apl, vh[0], vh[1]);
                    MMA16816(o[2 * nd + 1], aph, vh[2], vh[3]);
                    MMA16816(o[2 * nd + 1], apl, vh[2], vh[3]);
                }
            }
        }
        __syncthreads();
    }

    // ---- epilogue: normalize, transpose-stage, store Y hi/lo [d][t] ----
    const float inv0 = 1.f / l_i[0], inv1 = 1.f / l_i[1];
    float* Od = (float*)sm;   // [128 d][132]
#pragma unroll
    for (int nd = 0; nd < 16; nd++) {
        const int d = nd * 8 + 2 * tq;
        const int t0 = w * 16 + g;
        Od[d * 132 + t0]           = o[nd][0] * inv0;
        Od[(d + 1) * 132 + t0]     = o[nd][1] * inv0;
        Od[d * 132 + t0 + 8]       = o[nd][2] * inv1;
        Od[(d + 1) * 132 + t0 + 8] = o[nd][3] * inv1;
    }
    __syncthreads();

    const int b = bh >> 4, h = bh & 15;
    const size_t ybase = ((size_t)(b * CDIM + h * HDIM)) * T_SEQ + (size_t)qb * 128;
    for (int idx = tid; idx < 128 * 32; idx += 256) {
        const int d = idx >> 5, q4 = (idx & 31) * 4;
        const float4 v = *(const float4*)&Od[d * 132 + q4];
        uint2 hh, ll;
        hh.x = hfp(v.x, v.y); hh.y = hfp(v.z, v.w);
        ll.x = hfp(hres(v.x), hres(v.y)); ll.y = hfp(hres(v.z), hres(v.w));
        *(uint2*)(Yh + ybase + (size_t)d * T_SEQ + q4) = hh;
        *(uint2*)(Yl + ybase + (size_t)d * T_SEQ + q4) = ll;
    }
}

// ===========================================================================
extern "C" void kernel_launch(void* const* d_in, const int* in_sizes, int n_in,
                              void* d_out, int out_size)
{
    (void)in_sizes; (void)n_in; (void)out_size;
    const float* x  = (const float*)d_in[0];
    const float* Wq = (const float*)d_in[1];
    const float* bq = (const float*)d_in[2];
    const float* Wk = (const float*)d_in[3];
    const float* bk = (const float*)d_in[4];
    const float* Wv = (const float*)d_in[5];
    const float* bv = (const float*)d_in[6];
    const float* Wp = (const float*)d_in[7];
    const float* bp = (const float*)d_in[8];
    float* out = (float*)d_out;

    __half *xh, *xl, *Wh, *Qh, *Ql, *Kh, *Vh, *Yh, *Yl;
    cudaGetSymbolAddress((void**)&xh, g_xh);
    cudaGetSymbolAddress((void**)&xl, g_xl);
    cudaGetSymbolAddress((void**)&Wh, g_Wh);
    cudaGetSymbolAddress((void**)&Qh, g_Qh);
    cudaGetSymbolAddress((void**)&Ql, g_Ql);
    cudaGetSymbolAddress((void**)&Kh, g_Kh);
    cudaGetSymbolAddress((void**)&Vh, g_Vh);
    cudaGetSymbolAddress((void**)&Yh, g_Yh);
    cudaGetSymbolAddress((void**)&Yl, g_Yl);

    cudaFuncSetAttribute(gemm_h<0>, cudaFuncAttributeMaxDynamicSharedMemorySize,
                         GEMM_SMEM_BYTES);
    cudaFuncSetAttribute(gemm_h<1>, cudaFuncAttributeMaxDynamicSharedMemorySize,
                         GEMM_SMEM_BYTES);
    cudaFuncSetAttribute(attn_mma, cudaFuncAttributeMaxDynamicSharedMemorySize,
                         ATTN_SMEM_BYTES);

    const size_t WSZ = (size_t)CDIM * CDIM;

    // fused conversion pass (x hi/lo + all 4 weights hi)
    {
        const int total = N4X + 4 * N4W;
        cvt_all<<<(total + 255) / 256, 256>>>(x, xh, xl, Wq, Wk, Wv, Wp, Wh);
    }

    // fused QKV GEMM: grid.x = 3 mats x 16 n-tiles
    gemm_h<1><<<dim3(48, MROWS / 64), 256, GEMM_SMEM_BYTES>>>(
        xh, xl, Wh, bq, bk, bv, nullptr, Qh, Ql, Kh, Vh);

    attn_mma<<<dim3(T_SEQ / 128, BATCH * NHEAD), 256, ATTN_SMEM_BYTES>>>(
        Qh, Ql, Kh, Vh, Yh, Yl);

    gemm_h<0><<<dim3(16, MROWS / 64), 256, GEMM_SMEM_BYTES>>>(
        Yh, Yl, Wh + 3 * WSZ, bp, nullptr, nullptr, out,
        nullptr, nullptr, nullptr, nullptr);
}

// round 11
// speedup vs baseline: 6.1005x; 1.0182x over previous
#include <cuda_runtime.h>
#include <cuda_fp16.h>
#include <cstdint>

#define T_SEQ  2048
#define NHEAD  16
#define HDIM   128
#define BATCH  2
#define CDIM   2048
#define MROWS  (BATCH * T_SEQ)   // 4096

// ---------------------------------------------------------------------------
// Device-global scratch (allocation-free, graph-safe), fp16
// x, Q, P, Y carry hi/lo pairs (exact); W, K, V are fp16-rounded (hi only).
// ---------------------------------------------------------------------------
__device__ __half g_xh[(size_t)MROWS * CDIM];
__device__ __half g_xl[(size_t)MROWS * CDIM];
__device__ __half g_Wh[4][(size_t)CDIM * CDIM];   // q,k,v,p
__device__ __half g_Qh[(size_t)BATCH * NHEAD * T_SEQ * HDIM];
__device__ __half g_Ql[(size_t)BATCH * NHEAD * T_SEQ * HDIM];
__device__ __half g_Kh[(size_t)BATCH * NHEAD * T_SEQ * HDIM];
__device__ __half g_Vh[(size_t)BATCH * NHEAD * T_SEQ * HDIM];
__device__ __half g_Yh[(size_t)BATCH * T_SEQ * CDIM];   // [b][c][t]
__device__ __half g_Yl[(size_t)BATCH * T_SEQ * CDIM];

// ===========================================================================
// helpers
// ===========================================================================
__device__ __forceinline__ uint32_t smem_to_u32(const void* p) {
    uint32_t a;
    asm("{ .reg .u64 t; cvta.to.shared.u64 t, %1; cvt.u32.u64 %0, t; }"
        : "=r"(a) : "l"(p));
    return a;
}

__device__ __forceinline__ uint32_t hfp(float a, float b) {
    __half2 t = __floats2half2_rn(a, b);
    return *reinterpret_cast<uint32_t*>(&t);
}
__device__ __forceinline__ float hres(float a) {
    return a - __half2float(__float2half_rn(a));
}

#define LDMX4(r0, r1, r2, r3, addr) \
    asm volatile("ldmatrix.sync.aligned.m8n8.x4.shared.b16 {%0,%1,%2,%3}, [%4];" \
                 : "=r"(r0), "=r"(r1), "=r"(r2), "=r"(r3) : "r"(addr))

#define LDMX4T(r0, r1, r2, r3, addr) \
    asm volatile("ldmatrix.sync.aligned.m8n8.x4.trans.shared.b16 {%0,%1,%2,%3}, [%4];" \
                 : "=r"(r0), "=r"(r1), "=r"(r2), "=r"(r3) : "r"(addr))

#define MMA16816(c, a, b0, b1) \
    asm volatile("mma.sync.aligned.m16n8k16.row.col.f32.f16.f16.f32 " \
                 "{%0,%1,%2,%3}, {%4,%5,%6,%7}, {%8,%9}, {%0,%1,%2,%3};" \
                 : "+f"((c)[0]), "+f"((c)[1]), "+f"((c)[2]), "+f"((c)[3]) \
                 : "r"((a)[0]), "r"((a)[1]), "r"((a)[2]), "r"((a)[3]), \
                   "r"(b0), "r"(b1))

#define STSV4(addr, a, b, cc, d) \
    asm volatile("st.shared.v4.b32 [%0], {%1,%2,%3,%4};" \
                 :: "r"(addr), "r"(a), "r"(b), "r"(cc), "r"(d) : "memory")

#define CPASYNC16(saddr, gptr) \
    asm volatile("cp.async.cg.shared.global [%0], [%1], 16;" \
                 :: "r"(saddr), "l"(gptr) : "memory")
#define CPCOMMIT() asm volatile("cp.async.commit_group;" ::: "memory")
#define CPWAIT1()  asm volatile("cp.async.wait_group 1;" ::: "memory")
#define CPWAIT0()  asm volatile("cp.async.wait_group 0;" ::: "memory")

// ===========================================================================
// fused fp32 -> fp16 conversion: x (hi/lo) + 4 weights (hi) in ONE launch
// ===========================================================================
#define N4X (MROWS * CDIM / 4)
#define N4W (CDIM * CDIM / 4)

__global__ void cvt_all(const float* __restrict__ x,
                        __half* __restrict__ xh, __half* __restrict__ xl,
                        const float* __restrict__ Wq, const float* __restrict__ Wk,
                        const float* __restrict__ Wv, const float* __restrict__ Wp,
                        __half* __restrict__ Wh)
{
    const int i = blockIdx.x * blockDim.x + threadIdx.x;
    if (i < N4X) {
        const float4 v = ((const float4*)x)[i];
        uint2 h, l;
        h.x = hfp(v.x, v.y); h.y = hfp(v.z, v.w);
        l.x = hfp(hres(v.x), hres(v.y)); l.y = hfp(hres(v.z), hres(v.w));
        ((uint2*)xh)[i] = h;
        ((uint2*)xl)[i] = l;
    } else {
        const int j = i - N4X;
        const int mat = j >> 20;            // j / N4W (N4W = 2^20)
        const int k   = j & (N4W - 1);
        if (mat < 4) {
            const float* W = (mat == 0) ? Wq : (mat == 1) ? Wk
                                             : (mat == 2) ? Wv : Wp;
            const float4 v = ((const float4*)W)[k];
            uint2 h;
            h.x = hfp(v.x, v.y); h.y = hfp(v.z, v.w);
            ((uint2*)(Wh + (size_t)mat * CDIM * CDIM))[k] = h;
        }
    }
}

// ===========================================================================
// Tensor-core GEMM, fp16 2-pass (A hi/lo corrected, B fp16-rounded):
// C(M,N) = A(M,K) @ W(N,K)^T + bias(N).
// CTA tile 64x256, warp tile 32x64 (8 warps = 2m x 4n), K-chunk 64,
// 2-stage cp.async (96KB) -> 2 CTAs/SM. MMA:LDSM = 4.0 per warp.
// MODE 0: fp32 C out (grid.x=8).  MODE 1: fused QKV (grid.x=24, mat=bx>>3).
// Per-stage (48KB): Ah 0 (8K), Al 8K, Bh 16K (32K).
// ===========================================================================
#define GEMM_SMEM_BYTES 98304

template <int MODE>
__global__ void __launch_bounds__(256, 2)
gemm_h(const __half* __restrict__ Ah, const __half* __restrict__ Al,
       const __half* __restrict__ Wh,
       const float* __restrict__ b0, const float* __restrict__ b1,
       const float* __restrict__ b2,
       float* __restrict__ C,
       __half* __restrict__ Qo, __half* __restrict__ Qlo,
       __half* __restrict__ Ko, __half* __restrict__ Vo)
{
    extern __shared__ __align__(1024) char sm[];
    const uint32_t sbase = smem_to_u32(sm);

    const int tid  = threadIdx.x;
    const int wid  = tid >> 5;
    const int lane = tid & 31;
    const int wm   = wid >> 2;        // 0..1 -> rows wm*32
    const int wn   = wid & 3;         // 0..3 -> cols wn*64
    const int quad = lane >> 3;
    const int rr   = lane & 7;
    const int mat  = (MODE == 1) ? ((int)blockIdx.x >> 3) : 0;
    const int nbx  = (MODE == 1) ? ((int)blockIdx.x & 7) : (int)blockIdx.x;
    const int mBase = blockIdx.y * 64;
    const int nBase = nbx * 256;

    const __half* Agh = Ah + (size_t)mBase * CDIM;
    const __half* Agl = Al + (size_t)mBase * CDIM;
    const __half* Bgh = Wh + (size_t)mat * CDIM * CDIM + (size_t)nBase * CDIM;
    const float* bias = (MODE == 0) ? b0 : (mat == 0 ? b0 : (mat == 1 ? b1 : b2));

    float c[2][8][4];
#pragma unroll
    for (int mi = 0; mi < 2; mi++)
#pragma unroll
        for (int ni = 0; ni < 8; ni++)
#pragma unroll
            for (int k = 0; k < 4; k++) c[mi][ni][k] = 0.f;

    const int arow0 = wm * 32 + (quad & 1) * 8 + rr;
    const int acolq = (quad >> 1) * 8;
    const int brow0 = wn * 64 + (quad >> 1) * 8 + rr;
    const int bcolq = (quad & 1) * 8;

    // cp.async staging of chunk kt into stage stg
    auto stage_load = [&](int kt, int stg) {
        const uint32_t base = sbase + (uint32_t)stg * 49152u;
#pragma unroll
        for (int i = 0; i < 2; i++) {
            const int idx = tid + 256 * i;
            const int r = idx >> 3, g = idx & 7;
            const uint32_t off = (uint32_t)(r * 128 + g * 16);
            const uint32_t sw  = off ^ ((off >> 3) & 0x70);
            const size_t e = (size_t)r * CDIM + kt * 64 + g * 8;
            CPASYNC16(base + sw,         (const char*)(Agh + e));
            CPASYNC16(base + 8192u + sw, (const char*)(Agl + e));
        }
#pragma unroll
        for (int i = 0; i < 8; i++) {
            const int idx = tid + 256 * i;
            const int r = idx >> 3, g = idx & 7;
            const uint32_t off = (uint32_t)(r * 128 + g * 16);
            const uint32_t sw  = off ^ ((off >> 3) & 0x70);
            const size_t e = (size_t)r * CDIM + kt * 64 + g * 8;
            CPASYNC16(base + 16384u + sw, (const char*)(Bgh + e));
        }
    };

    auto compute = [&](int stg) {
        const uint32_t base = sbase + (uint32_t)stg * 49152u;
        const uint32_t AhS = base, AlS = base + 8192u, BhS = base + 16384u;
#pragma unroll
        for (int sub = 0; sub < 4; sub++) {
            const int kb = sub * 16;
            uint32_t bh[16];
#pragma unroll
            for (int p = 0; p < 4; p++) {
                const uint32_t off = (uint32_t)((brow0 + p * 16) * 128 + (kb + bcolq) * 2);
                const uint32_t sw  = off ^ ((off >> 3) & 0x70);
                LDMX4(bh[4 * p], bh[4 * p + 1], bh[4 * p + 2], bh[4 * p + 3], BhS + sw);
            }
#pragma unroll
            for (int mi = 0; mi < 2; mi++) {
                uint32_t ah[4], al[4];
                const uint32_t off = (uint32_t)((arow0 + mi * 16) * 128 + (kb + acolq) * 2);
                const uint32_t sw  = off ^ ((off >> 3) & 0x70);
                LDMX4(ah[0], ah[1], ah[2], ah[3], AhS + sw);
                LDMX4(al[0], al[1], al[2], al[3], AlS + sw);
#pragma unroll
                for (int ni = 0; ni < 8; ni++) {
                    MMA16816(c[mi][ni], ah, bh[2 * ni], bh[2 * ni + 1]);
                    MMA16816(c[mi][ni], al, bh[2 * ni], bh[2 * ni + 1]);
                }
            }
        }
    };

    stage_load(0, 0); CPCOMMIT();

    for (int kt = 0; kt < 32; kt++) {
        const int stg = kt & 1;
        if (kt + 1 < 32) { stage_load(kt + 1, stg ^ 1); CPCOMMIT(); }
        if (kt + 1 < 32) { CPWAIT1(); } else { CPWAIT0(); }
        __syncthreads();   // chunk kt staged & visible
        compute(stg);
        __syncthreads();   // all warps done with stage stg before re-staging
    }

    // epilogue: fragments -> smem Ct[64][260] fp32 -> gmem
    float* Ct = (float*)sm;
    const int g2 = lane >> 2, t2 = (lane & 3) * 2;
#pragma unroll
    for (int mi = 0; mi < 2; mi++) {
        const int row = wm * 32 + mi * 16 + g2;
#pragma unroll
        for (int ni = 0; ni < 8; ni++) {
            const int col = wn * 64 + ni * 8 + t2;
            Ct[row * 260 + col]           = c[mi][ni][0];
            Ct[row * 260 + col + 1]       = c[mi][ni][1];
            Ct[(row + 8) * 260 + col]     = c[mi][ni][2];
            Ct[(row + 8) * 260 + col + 1] = c[mi][ni][3];
        }
    }
    __syncthreads();

    for (int idx = tid; idx < 64 * 64; idx += 256) {
        const int row = idx >> 6, c4 = (idx & 63) * 4;
        const int n = nBase + c4;
        const float4 bv = *(const float4*)&bias[n];
        float4 v;
        v.x = Ct[row * 260 + c4]     + bv.x;
        v.y = Ct[row * 260 + c4 + 1] + bv.y;
        v.z = Ct[row * 260 + c4 + 2] + bv.z;
        v.w = Ct[row * 260 + c4 + 3] + bv.w;
        const int m = mBase + row;
        if (MODE == 0) {
            *(float4*)&C[(size_t)m * CDIM + n] = v;
        } else {
            const int b = m >> 11, t = m & (T_SEQ - 1);
            const int h = n >> 7, d = n & (HDIM - 1);
            const size_t e = (((size_t)(b * NHEAD + h)) * T_SEQ + t) * HDIM + d;
            uint2 hh;
            hh.x = hfp(v.x, v.y); hh.y = hfp(v.z, v.w);
            if (mat == 0) {
                uint2 ll;
                ll.x = hfp(hres(v.x), hres(v.y)); ll.y = hfp(hres(v.z), hres(v.w));
                *(uint2*)(Qo + e)  = hh;
                *(uint2*)(Qlo + e) = ll;
            } else {
                __half* dst = (mat == 1) ? Ko : Vo;
                *(uint2*)(dst + e) = hh;
            }
        }
    }
}

// ===========================================================================
// FA2-style tensor-core flash attention, causal, fp16 2-pass (unchanged R9).
// ===========================================================================
#define ATTN_SMEM_BYTES 131072

__global__ void __launch_bounds__(256, 1)
attn_mma(const __half* __restrict__ Qh, const __half* __restrict__ Ql,
         const __half* __restrict__ Kh, const __half* __restrict__ Vh,
         __half* __restrict__ Yh, __half* __restrict__ Yl)
{
    extern __shared__ __align__(1024) char sm[];
    const uint32_t sb = smem_to_u32(sm);
    const uint32_t QHs = sb, QLs = sb + 32768u;

    const int tid  = threadIdx.x;
    const int lane = tid & 31;
    const int w    = tid >> 5;
    const int quad = lane >> 3;
    const int rr   = lane & 7;
    const int g    = lane >> 2;
    const int tq   = lane & 3;
    const int qb   = (int)gridDim.x - 1 - (int)blockIdx.x;  // heavy first
    const int bh   = blockIdx.y;

    const size_t headbase = (size_t)bh * T_SEQ * HDIM;
    const int jend = 2 * qb + 1;

    auto stage_kv = [&](int jb, int b) {
        const size_t base = headbase + (size_t)jb * 64 * HDIM;
        const char* kh = (const char*)(Kh + base);
        const char* vh = (const char*)(Vh + base);
        const uint32_t bufb = sb + 65536u + (uint32_t)b * 32768u;
#pragma unroll
        for (int i = 0; i < 4; i++) {
            const int c = tid + 256 * i;
            const int row = c >> 4, gg = c & 15;
            const uint32_t off = (uint32_t)row * 256u +
                                 ((uint32_t)(gg * 16) ^ ((uint32_t)(row & 7) << 4));
            const size_t gb = (size_t)c * 16;
            CPASYNC16(bufb + off,          kh + gb);
            CPASYNC16(bufb + 16384u + off, vh + gb);
        }
    };

    stage_kv(0, 0);
    CPCOMMIT();
    {
        const size_t base = headbase + (size_t)qb * 128 * HDIM;
        const uint4* qh4 = (const uint4*)(Qh + base);
        const uint4* ql4 = (const uint4*)(Ql + base);
#pragma unroll
        for (int i = 0; i < 8; i++) {
            const int c = tid + 256 * i;
            const int row = c >> 4, gg = c & 15;
            const uint32_t off = (uint32_t)row * 256u +
                                 ((uint32_t)(gg * 16) ^ ((uint32_t)(row & 7) << 4));
            const uint4 vh = qh4[c], vl = ql4[c];
            STSV4(QHs + off, vh.x, vh.y, vh.z, vh.w);
            STSV4(QLs + off, vl.x, vl.y, vl.z, vl.w);
        }
    }

    float o[16][4];
#pragma unroll
    for (int nd = 0; nd < 16; nd++)
#pragma unroll
        for (int k = 0; k < 4; k++) o[nd][k] = 0.f;
    float m_i[2] = {-1e30f, -1e30f}, l_i[2] = {0.f, 0.f};

    const float scale = 0.08838834764831845f;   // 1/sqrt(128)
    const int R0 = qb * 128 + w * 16;

    for (int jb = 0; jb <= jend; jb++) {
        const int buf = jb & 1;
        if (jb < jend) { stage_kv(jb + 1, buf ^ 1); CPCOMMIT(); }
        if (jb < jend) { CPWAIT1(); } else { CPWAIT0(); }
        __syncthreads();

        if (jb * 64 <= R0 + 15) {
            const uint32_t KHb = sb + 65536u + (uint32_t)buf * 32768u;
            const uint32_t VHb = KHb + 16384u;

            // ---- S = Q K^T : 16 rows x 64 keys, 2-pass (Q hi/lo, K fp16) ----
            float s[8][4];
#pragma unroll
            for (int ni = 0; ni < 8; ni++)
#pragma unroll
                for (int k = 0; k < 4; k++) s[ni][k] = 0.f;

#pragma unroll
            for (int kb = 0; kb < 8; kb++) {
                uint32_t ah[4], al[4];
                {
                    const int arow = w * 16 + (quad & 1) * 8 + rr;
                    const uint32_t cb = (uint32_t)(kb * 32 + (quad >> 1) * 16);
                    const uint32_t off = (uint32_t)arow * 256u +
                                         (cb ^ ((uint32_t)(arow & 7) << 4));
                    LDMX4(ah[0], ah[1], ah[2], ah[3], QHs + off);
                    LDMX4(al[0], al[1], al[2], al[3], QLs + off);
                }
#pragma unroll
                for (int p = 0; p < 4; p++) {
                    uint32_t bh2[4];
                    const int krow = p * 16 + (quad >> 1) * 8 + rr;
                    const uint32_t cb = (uint32_t)(kb * 32 + (quad & 1) * 16);
                    const uint32_t off = (uint32_t)krow * 256u +
                                         (cb ^ ((uint32_t)(krow & 7) << 4));
                    LDMX4(bh2[0], bh2[1], bh2[2], bh2[3], KHb + off);
                    MMA16816(s[2 * p],     ah, bh2[0], bh2[1]);
                    MMA16816(s[2 * p],     al, bh2[0], bh2[1]);
                    MMA16816(s[2 * p + 1], ah, bh2[2], bh2[3]);
                    MMA16816(s[2 * p + 1], al, bh2[2], bh2[3]);
                }
            }

            // ---- scale + causal mask ----
            const bool needmask = (jb * 64 + 63 > R0);
#pragma unroll
            for (int ni = 0; ni < 8; ni++)
#pragma unroll
                for (int j = 0; j < 4; j++) {
                    float v = s[ni][j] * scale;
                    if (needmask) {
                        const int rglob = R0 + g + ((j >> 1) << 3);
                        const int kglob = jb * 64 + ni * 8 + 2 * tq + (j & 1);
                        if (kglob > rglob) v = -1e30f;
                    }
                    s[ni][j] = v;
                }

            // ---- warp-local online softmax (rows g, g+8) ----
            float alpha[2];
#pragma unroll
            for (int r = 0; r < 2; r++) {
                float mx = -1e30f;
#pragma unroll
                for (int ni = 0; ni < 8; ni++)
                    mx = fmaxf(mx, fmaxf(s[ni][2 * r], s[ni][2 * r + 1]));
                mx = fmaxf(mx, __shfl_xor_sync(0xffffffffu, mx, 1));
                mx = fmaxf(mx, __shfl_xor_sync(0xffffffffu, mx, 2));
                const float mn = fmaxf(m_i[r], mx);
                alpha[r] = __expf(m_i[r] - mn);
                m_i[r] = mn;
                float sum = 0.f;
#pragma unroll
                for (int ni = 0; ni < 8; ni++) {
                    const float p0 = __expf(s[ni][2 * r] - mn);
                    const float p1 = __expf(s[ni][2 * r + 1] - mn);
                    s[ni][2 * r] = p0; s[ni][2 * r + 1] = p1;
                    sum += p0 + p1;
                }
                sum += __shfl_xor_sync(0xffffffffu, sum, 1);
                sum += __shfl_xor_sync(0xffffffffu, sum, 2);
                l_i[r] = l_i[r] * alpha[r] + sum;
#pragma unroll
                for (int nd = 0; nd < 16; nd++) {
                    o[nd][2 * r]     *= alpha[r];
                    o[nd][2 * r + 1] *= alpha[r];
                }
            }

            // ---- O += P V : P hi/lo packed in regs, V fp16 (2-pass) ----
#pragma unroll
            for (int kc = 0; kc < 4; kc++) {
                uint32_t aph[4], apl[4];
                const float* s0 = s[2 * kc];
                const float* s1 = s[2 * kc + 1];
                aph[0] = hfp(s0[0], s0[1]);
                aph[1] = hfp(s0[2], s0[3]);
                aph[2] = hfp(s1[0], s1[1]);
                aph[3] = hfp(s1[2], s1[3]);
                apl[0] = hfp(hres(s0[0]), hres(s0[1]));
                apl[1] = hfp(hres(s0[2]), hres(s0[3]));
                apl[2] = hfp(hres(s1[0]), hres(s1[1]));
                apl[3] = hfp(hres(s1[2]), hres(s1[3]));
#pragma unroll
                for (int nd = 0; nd < 8; nd++) {
                    const int key = kc * 16 + (quad & 1) * 8 + rr;
                    const uint32_t db = (uint32_t)(nd * 32 + (quad >> 1) * 16);
                    const uint32_t off = (uint32_t)key * 256u +
                                         (db ^ ((uint32_t)(key & 7) << 4));
                    uint32_t vh[4];
                    LDMX4T(vh[0], vh[1], vh[2], vh[3], VHb + off);
                    MMA16816(o[2 * nd],     aph, vh[0], vh[1]);
                    MMA16816(o[2 * nd],     apl, vh[0], vh[1]);
                    MMA16816(o[2 * nd + 1], aph, vh[2], vh[3]);
                    MMA16816(o[2 * nd + 1], apl, vh[2], vh[3]);
                }
            }
        }
        __syncthreads();
    }

    // ---- epilogue: normalize, transpose-stage, store Y hi/lo [d][t] ----
    const float inv0 = 1.f / l_i[0], inv1 = 1.f / l_i[1];
    float* Od = (float*)sm;   // [128 d][132]
#pragma unroll
    for (int nd = 0; nd < 16; nd++) {
        const int d = nd * 8 + 2 * tq;
        const int t0 = w * 16 + g;
        Od[d * 132 + t0]           = o[nd][0] * inv0;
        Od[(d + 1) * 132 + t0]     = o[nd][1] * inv0;
        Od[d * 132 + t0 + 8]       = o[nd][2] * inv1;
        Od[(d + 1) * 132 + t0 + 8] = o[nd][3] * inv1;
    }
    __syncthreads();

    const int b = bh >> 4, h = bh & 15;
    const size_t ybase = ((size_t)(b * CDIM + h * HDIM)) * T_SEQ + (size_t)qb * 128;
    for (int idx = tid; idx < 128 * 32; idx += 256) {
        const int d = idx >> 5, q4 = (idx & 31) * 4;
        const float4 v = *(const float4*)&Od[d * 132 + q4];
        uint2 hh, ll;
        hh.x = hfp(v.x, v.y); hh.y = hfp(v.z, v.w);
        ll.x = hfp(hres(v.x), hres(v.y)); ll.y = hfp(hres(v.z), hres(v.w));
        *(uint2*)(Yh + ybase + (size_t)d * T_SEQ + q4) = hh;
        *(uint2*)(Yl + ybase + (size_t)d * T_SEQ + q4) = ll;
    }
}

// ===========================================================================
extern "C" void kernel_launch(void* const* d_in, const int* in_sizes, int n_in,
                              void* d_out, int out_size)
{
    (void)in_sizes; (void)n_in; (void)out_size;
    const float* x  = (const float*)d_in[0];
    const float* Wq = (const float*)d_in[1];
    const float* bq = (const float*)d_in[2];
    const float* Wk = (const float*)d_in[3];
    const float* bk = (const float*)d_in[4];
    const float* Wv = (const float*)d_in[5];
    const float* bv = (const float*)d_in[6];
    const float* Wp = (const float*)d_in[7];
    const float* bp = (const float*)d_in[8];
    float* out = (float*)d_out;

    __half *xh, *xl, *Wh, *Qh, *Ql, *Kh, *Vh, *Yh, *Yl;
    cudaGetSymbolAddress((void**)&xh, g_xh);
    cudaGetSymbolAddress((void**)&xl, g_xl);
    cudaGetSymbolAddress((void**)&Wh, g_Wh);
    cudaGetSymbolAddress((void**)&Qh, g_Qh);
    cudaGetSymbolAddress((void**)&Ql, g_Ql);
    cudaGetSymbolAddress((void**)&Kh, g_Kh);
    cudaGetSymbolAddress((void**)&Vh, g_Vh);
    cudaGetSymbolAddress((void**)&Yh, g_Yh);
    cudaGetSymbolAddress((void**)&Yl, g_Yl);

    cudaFuncSetAttribute(gemm_h<0>, cudaFuncAttributeMaxDynamicSharedMemorySize,
                         GEMM_SMEM_BYTES);
    cudaFuncSetAttribute(gemm_h<1>, cudaFuncAttributeMaxDynamicSharedMemorySize,
                         GEMM_SMEM_BYTES);
    cudaFuncSetAttribute(attn_mma, cudaFuncAttributeMaxDynamicSharedMemorySize,
                         ATTN_SMEM_BYTES);

    const size_t WSZ = (size_t)CDIM * CDIM;

    // fused conversion pass (x hi/lo + all 4 weights hi)
    {
        const int total = N4X + 4 * N4W;
        cvt_all<<<(total + 255) / 256, 256>>>(x, xh, xl, Wq, Wk, Wv, Wp, Wh);
    }

    // fused QKV GEMM: grid.x = 3 mats x 8 n-tiles
    gemm_h<1><<<dim3(24, MROWS / 64), 256, GEMM_SMEM_BYTES>>>(
        xh, xl, Wh, bq, bk, bv, nullptr, Qh, Ql, Kh, Vh);

    attn_mma<<<dim3(T_SEQ / 128, BATCH * NHEAD), 256, ATTN_SMEM_BYTES>>>(
        Qh, Ql, Kh, Vh, Yh, Yl);

    gemm_h<0><<<dim3(8, MROWS / 64), 256, GEMM_SMEM_BYTES>>>(
        Yh, Yl, Wh + 3 * WSZ, bp, nullptr, nullptr, out,
        nullptr, nullptr, nullptr, nullptr);
}

// round 12
// speedup vs baseline: 8.3700x; 1.3720x over previous
#include <cuda_runtime.h>
#include <cuda_fp16.h>
#include <cstdint>

#define T_SEQ  2048
#define NHEAD  16
#define HDIM   128
#define BATCH  2
#define CDIM   2048
#define MROWS  (BATCH * T_SEQ)   // 4096

// ---------------------------------------------------------------------------
// Device-global scratch (allocation-free, graph-safe), fp16
// Q carries hi/lo (exact); x, W, K, V, Y are fp16-rounded.
// ---------------------------------------------------------------------------
__device__ __half g_xh[(size_t)MROWS * CDIM];
__device__ __half g_Wh[4][(size_t)CDIM * CDIM];   // q,k,v,p
__device__ __half g_Qh[(size_t)BATCH * NHEAD * T_SEQ * HDIM];
__device__ __half g_Ql[(size_t)BATCH * NHEAD * T_SEQ * HDIM];
__device__ __half g_Kh[(size_t)BATCH * NHEAD * T_SEQ * HDIM];
__device__ __half g_Vh[(size_t)BATCH * NHEAD * T_SEQ * HDIM];
__device__ __half g_Yh[(size_t)BATCH * T_SEQ * CDIM];   // [b][c][t]

// ===========================================================================
// helpers
// ===========================================================================
__device__ __forceinline__ uint32_t smem_to_u32(const void* p) {
    uint32_t a;
    asm("{ .reg .u64 t; cvta.to.shared.u64 t, %1; cvt.u32.u64 %0, t; }"
        : "=r"(a) : "l"(p));
    return a;
}

__device__ __forceinline__ uint32_t hfp(float a, float b) {
    __half2 t = __floats2half2_rn(a, b);
    return *reinterpret_cast<uint32_t*>(&t);
}
__device__ __forceinline__ float hres(float a) {
    return a - __half2float(__float2half_rn(a));
}

#define LDMX4(r0, r1, r2, r3, addr) \
    asm volatile("ldmatrix.sync.aligned.m8n8.x4.shared.b16 {%0,%1,%2,%3}, [%4];" \
                 : "=r"(r0), "=r"(r1), "=r"(r2), "=r"(r3) : "r"(addr))

#define LDMX4T(r0, r1, r2, r3, addr) \
    asm volatile("ldmatrix.sync.aligned.m8n8.x4.trans.shared.b16 {%0,%1,%2,%3}, [%4];" \
                 : "=r"(r0), "=r"(r1), "=r"(r2), "=r"(r3) : "r"(addr))

#define MMA16816(c, a, b0, b1) \
    asm volatile("mma.sync.aligned.m16n8k16.row.col.f32.f16.f16.f32 " \
                 "{%0,%1,%2,%3}, {%4,%5,%6,%7}, {%8,%9}, {%0,%1,%2,%3};" \
                 : "+f"((c)[0]), "+f"((c)[1]), "+f"((c)[2]), "+f"((c)[3]) \
                 : "r"((a)[0]), "r"((a)[1]), "r"((a)[2]), "r"((a)[3]), \
                   "r"(b0), "r"(b1))

#define STSV4(addr, a, b, cc, d) \
    asm volatile("st.shared.v4.b32 [%0], {%1,%2,%3,%4};" \
                 :: "r"(addr), "r"(a), "r"(b), "r"(cc), "r"(d) : "memory")

#define CPASYNC16(saddr, gptr) \
    asm volatile("cp.async.cg.shared.global [%0], [%1], 16;" \
                 :: "r"(saddr), "l"(gptr) : "memory")
#define CPCOMMIT() asm volatile("cp.async.commit_group;" ::: "memory")
#define CPWAIT1()  asm volatile("cp.async.wait_group 1;" ::: "memory")
#define CPWAIT0()  asm volatile("cp.async.wait_group 0;" ::: "memory")

// ===========================================================================
// fused fp32 -> fp16 conversion: x + 4 weights, all hi-only, ONE launch
// ===========================================================================
#define N4X (MROWS * CDIM / 4)
#define N4W (CDIM * CDIM / 4)

__global__ void cvt_all(const float* __restrict__ x, __half* __restrict__ xh,
                        const float* __restrict__ Wq, const float* __restrict__ Wk,
                        const float* __restrict__ Wv, const float* __restrict__ Wp,
                        __half* __restrict__ Wh)
{
    const int i = blockIdx.x * blockDim.x + threadIdx.x;
    if (i < N4X) {
        const float4 v = ((const float4*)x)[i];
        uint2 h;
        h.x = hfp(v.x, v.y); h.y = hfp(v.z, v.w);
        ((uint2*)xh)[i] = h;
    } else {
        const int j = i - N4X;
        const int mat = j >> 20;            // j / N4W (N4W = 2^20)
        const int k   = j & (N4W - 1);
        if (mat < 4) {
            const float* W = (mat == 0) ? Wq : (mat == 1) ? Wk
                                             : (mat == 2) ? Wv : Wp;
            const float4 v = ((const float4*)W)[k];
            uint2 h;
            h.x = hfp(v.x, v.y); h.y = hfp(v.z, v.w);
            ((uint2*)(Wh + (size_t)mat * CDIM * CDIM))[k] = h;
        }
    }
}

// ===========================================================================
// Tensor-core GEMM, fp16 1-pass (A and B both fp16-rounded):
// C(M,N) = A(M,K) @ W(N,K)^T + bias(N).
// CTA tile 64x128, warp 32x32 (8 warps = 2m x 4n), K-chunk 64,
// 3-stage cp.async pipeline (72KB) -> 2 CTAs/SM, 1 sync/chunk.
// MODE 0: fp32 C out (grid.x=16).  MODE 1: fused QKV (grid.x=48, mat=bx>>4);
//   mat 0 -> Q hi/lo, mat 1 -> K hi, mat 2 -> V hi, head layout.
// Per-stage (24KB): Ah 0 (8K), Bh 8K (16K).
// ===========================================================================
#define GEMM_SMEM_BYTES 73728

template <int MODE>
__global__ void __launch_bounds__(256, 2)
gemm_h(const __half* __restrict__ Ah, const __half* __restrict__ Wh,
       const float* __restrict__ b0, const float* __restrict__ b1,
       const float* __restrict__ b2,
       float* __restrict__ C,
       __half* __restrict__ Qo, __half* __restrict__ Qlo,
       __half* __restrict__ Ko, __half* __restrict__ Vo)
{
    extern __shared__ __align__(1024) char sm[];
    const uint32_t sbase = smem_to_u32(sm);

    const int tid  = threadIdx.x;
    const int wid  = tid >> 5;
    const int lane = tid & 31;
    const int wm   = wid >> 2;        // 0..1 -> rows wm*32
    const int wn   = wid & 3;         // 0..3 -> cols wn*32
    const int quad = lane >> 3;
    const int rr   = lane & 7;
    const int mat  = (MODE == 1) ? ((int)blockIdx.x >> 4) : 0;
    const int nbx  = (MODE == 1) ? ((int)blockIdx.x & 15) : (int)blockIdx.x;
    const int mBase = blockIdx.y * 64;
    const int nBase = nbx * 128;

    const __half* Agh = Ah + (size_t)mBase * CDIM;
    const __half* Bgh = Wh + (size_t)mat * CDIM * CDIM + (size_t)nBase * CDIM;
    const float* bias = (MODE == 0) ? b0 : (mat == 0 ? b0 : (mat == 1 ? b1 : b2));

    float c[2][4][4];
#pragma unroll
    for (int mi = 0; mi < 2; mi++)
#pragma unroll
        for (int ni = 0; ni < 4; ni++)
#pragma unroll
            for (int k = 0; k < 4; k++) c[mi][ni][k] = 0.f;

    const int arow0 = wm * 32 + (quad & 1) * 8 + rr;
    const int acolq = (quad >> 1) * 8;
    const int brow0 = wn * 32 + (quad >> 1) * 8 + rr;
    const int bcolq = (quad & 1) * 8;

    // cp.async staging of chunk kt into stage stg
    auto stage_load = [&](int kt, int stg) {
        const uint32_t base = sbase + (uint32_t)stg * 24576u;
#pragma unroll
        for (int i = 0; i < 2; i++) {
            const int idx = tid + 256 * i;
            const int r = idx >> 3, g = idx & 7;
            const uint32_t off = (uint32_t)(r * 128 + g * 16);
            const uint32_t sw  = off ^ ((off >> 3) & 0x70);
            const size_t e = (size_t)r * CDIM + kt * 64 + g * 8;
            CPASYNC16(base + sw, (const char*)(Agh + e));
        }
#pragma unroll
        for (int i = 0; i < 4; i++) {
            const int idx = tid + 256 * i;
            const int r = idx >> 3, g = idx & 7;
            const uint32_t off = (uint32_t)(r * 128 + g * 16);
            const uint32_t sw  = off ^ ((off >> 3) & 0x70);
            const size_t e = (size_t)r * CDIM + kt * 64 + g * 8;
            CPASYNC16(base + 8192u + sw, (const char*)(Bgh + e));
        }
    };

    auto compute = [&](int stg) {
        const uint32_t base = sbase + (uint32_t)stg * 24576u;
        const uint32_t AhS = base, BhS = base + 8192u;
#pragma unroll
        for (int sub = 0; sub < 4; sub++) {
            const int kb = sub * 16;
            uint32_t bh[8];
#pragma unroll
            for (int p = 0; p < 2; p++) {
                const uint32_t off = (uint32_t)((brow0 + p * 16) * 128 + (kb + bcolq) * 2);
                const uint32_t sw  = off ^ ((off >> 3) & 0x70);
                LDMX4(bh[4 * p], bh[4 * p + 1], bh[4 * p + 2], bh[4 * p + 3], BhS + sw);
            }
#pragma unroll
            for (int mi = 0; mi < 2; mi++) {
                uint32_t ah[4];
                const uint32_t off = (uint32_t)((arow0 + mi * 16) * 128 + (kb + acolq) * 2);
                const uint32_t sw  = off ^ ((off >> 3) & 0x70);
                LDMX4(ah[0], ah[1], ah[2], ah[3], AhS + sw);
#pragma unroll
                for (int ni = 0; ni < 4; ni++)
                    MMA16816(c[mi][ni], ah, bh[2 * ni], bh[2 * ni + 1]);
            }
        }
    };

    stage_load(0, 0); CPCOMMIT();
    stage_load(1, 1); CPCOMMIT();

    int stg = 0;
    for (int kt = 0; kt < 32; kt++) {
        if (kt + 1 < 32) { CPWAIT1(); } else { CPWAIT0(); }
        __syncthreads();   // chunk kt visible; compute on stage (kt+2)%3 done
        if (kt + 2 < 32) {
            int ns = stg + 2; if (ns >= 3) ns -= 3;
            stage_load(kt + 2, ns);
            CPCOMMIT();
        }
        compute(stg);
        if (++stg == 3) stg = 0;
    }

    // epilogue: fragments -> smem Ct[64][132] fp32 -> gmem
    __syncthreads();
    float* Ct = (float*)sm;
    const int g2 = lane >> 2, t2 = (lane & 3) * 2;
#pragma unroll
    for (int mi = 0; mi < 2; mi++) {
        const int row = wm * 32 + mi * 16 + g2;
#pragma unroll
        for (int ni = 0; ni < 4; ni++) {
            const int col = wn * 32 + ni * 8 + t2;
            Ct[row * 132 + col]           = c[mi][ni][0];
            Ct[row * 132 + col + 1]       = c[mi][ni][1];
            Ct[(row + 8) * 132 + col]     = c[mi][ni][2];
            Ct[(row + 8) * 132 + col + 1] = c[mi][ni][3];
        }
    }
    __syncthreads();

    for (int idx = tid; idx < 64 * 32; idx += 256) {
        const int row = idx >> 5, c4 = (idx & 31) * 4;
        const int n = nBase + c4;
        const float4 bv = *(const float4*)&bias[n];
        float4 v;
        v.x = Ct[row * 132 + c4]     + bv.x;
        v.y = Ct[row * 132 + c4 + 1] + bv.y;
        v.z = Ct[row * 132 + c4 + 2] + bv.z;
        v.w = Ct[row * 132 + c4 + 3] + bv.w;
        const int m = mBase + row;
        if (MODE == 0) {
            *(float4*)&C[(size_t)m * CDIM + n] = v;
        } else {
            const int b = m >> 11, t = m & (T_SEQ - 1);
            const int h = n >> 7, d = n & (HDIM - 1);
            const size_t e = (((size_t)(b * NHEAD + h)) * T_SEQ + t) * HDIM + d;
            uint2 hh;
            hh.x = hfp(v.x, v.y); hh.y = hfp(v.z, v.w);
            if (mat == 0) {
                uint2 ll;
                ll.x = hfp(hres(v.x), hres(v.y)); ll.y = hfp(hres(v.z), hres(v.w));
                *(uint2*)(Qo + e)  = hh;
                *(uint2*)(Qlo + e) = ll;
            } else {
                __half* dst = (mat == 1) ? Ko : Vo;
                *(uint2*)(dst + e) = hh;
            }
        }
    }
}

// ===========================================================================
// FA2-style tensor-core flash attention, causal, fp16 (Q hi/lo exact,
// K/V fp16, P hi/lo in regs). Y output fp16-rounded (hi only).
// ===========================================================================
#define ATTN_SMEM_BYTES 131072

__global__ void __launch_bounds__(256, 1)
attn_mma(const __half* __restrict__ Qh, const __half* __restrict__ Ql,
         const __half* __restrict__ Kh, const __half* __restrict__ Vh,
         __half* __restrict__ Yh)
{
    extern __shared__ __align__(1024) char sm[];
    const uint32_t sb = smem_to_u32(sm);
    const uint32_t QHs = sb, QLs = sb + 32768u;

    const int tid  = threadIdx.x;
    const int lane = tid & 31;
    const int w    = tid >> 5;
    const int quad = lane >> 3;
    const int rr   = lane & 7;
    const int g    = lane >> 2;
    const int tq   = lane & 3;
    const int qb   = (int)gridDim.x - 1 - (int)blockIdx.x;  // heavy first
    const int bh   = blockIdx.y;

    const size_t headbase = (size_t)bh * T_SEQ * HDIM;
    const int jend = 2 * qb + 1;

    auto stage_kv = [&](int jb, int b) {
        const size_t base = headbase + (size_t)jb * 64 * HDIM;
        const char* kh = (const char*)(Kh + base);
        const char* vh = (const char*)(Vh + base);
        const uint32_t bufb = sb + 65536u + (uint32_t)b * 32768u;
#pragma unroll
        for (int i = 0; i < 4; i++) {
            const int c = tid + 256 * i;
            const int row = c >> 4, gg = c & 15;
            const uint32_t off = (uint32_t)row * 256u +
                                 ((uint32_t)(gg * 16) ^ ((uint32_t)(row & 7) << 4));
            const size_t gb = (size_t)c * 16;
            CPASYNC16(bufb + off,          kh + gb);
            CPASYNC16(bufb + 16384u + off, vh + gb);
        }
    };

    stage_kv(0, 0);
    CPCOMMIT();
    {
        const size_t base = headbase + (size_t)qb * 128 * HDIM;
        const uint4* qh4 = (const uint4*)(Qh + base);
        const uint4* ql4 = (const uint4*)(Ql + base);
#pragma unroll
        for (int i = 0; i < 8; i++) {
            const int c = tid + 256 * i;
            const int row = c >> 4, gg = c & 15;
            const uint32_t off = (uint32_t)row * 256u +
                                 ((uint32_t)(gg * 16) ^ ((uint32_t)(row & 7) << 4));
            const uint4 vh = qh4[c], vl = ql4[c];
            STSV4(QHs + off, vh.x, vh.y, vh.z, vh.w);
            STSV4(QLs + off, vl.x, vl.y, vl.z, vl.w);
        }
    }

    float o[16][4];
#pragma unroll
    for (int nd = 0; nd < 16; nd++)
#pragma unroll
        for (int k = 0; k < 4; k++) o[nd][k] = 0.f;
    float m_i[2] = {-1e30f, -1e30f}, l_i[2] = {0.f, 0.f};

    const float scale = 0.08838834764831845f;   // 1/sqrt(128)
    const int R0 = qb * 128 + w * 16;

    for (int jb = 0; jb <= jend; jb++) {
        const int buf = jb & 1;
        if (jb < jend) { stage_kv(jb + 1, buf ^ 1); CPCOMMIT(); }
        if (jb < jend) { CPWAIT1(); } else { CPWAIT0(); }
        __syncthreads();

        if (jb * 64 <= R0 + 15) {
            const uint32_t KHb = sb + 65536u + (uint32_t)buf * 32768u;
            const uint32_t VHb = KHb + 16384u;

            // ---- S = Q K^T : 16 rows x 64 keys, 2-pass (Q hi/lo, K fp16) ----
            float s[8][4];
#pragma unroll
            for (int ni = 0; ni < 8; ni++)
#pragma unroll
                for (int k = 0; k < 4; k++) s[ni][k] = 0.f;

#pragma unroll
            for (int kb = 0; kb < 8; kb++) {
                uint32_t ah[4], al[4];
                {
                    const int arow = w * 16 + (quad & 1) * 8 + rr;
                    const uint32_t cb = (uint32_t)(kb * 32 + (quad >> 1) * 16);
                    const uint32_t off = (uint32_t)arow * 256u +
                                         (cb ^ ((uint32_t)(arow & 7) << 4));
                    LDMX4(ah[0], ah[1], ah[2], ah[3], QHs + off);
                    LDMX4(al[0], al[1], al[2], al[3], QLs + off);
                }
#pragma unroll
                for (int p = 0; p < 4; p++) {
                    uint32_t bh2[4];
                    const int krow = p * 16 + (quad >> 1) * 8 + rr;
                    const uint32_t cb = (uint32_t)(kb * 32 + (quad & 1) * 16);
                    const uint32_t off = (uint32_t)krow * 256u +
                                         (cb ^ ((uint32_t)(krow & 7) << 4));
                    LDMX4(bh2[0], bh2[1], bh2[2], bh2[3], KHb + off);
                    MMA16816(s[2 * p],     ah, bh2[0], bh2[1]);
                    MMA16816(s[2 * p],     al, bh2[0], bh2[1]);
                    MMA16816(s[2 * p + 1], ah, bh2[2], bh2[3]);
                    MMA16816(s[2 * p + 1], al, bh2[2], bh2[3]);
                }
            }

            // ---- scale + causal mask ----
            const bool needmask = (jb * 64 + 63 > R0);
#pragma unroll
            for (int ni = 0; ni < 8; ni++)
#pragma unroll
                for (int j = 0; j < 4; j++) {
                    float v = s[ni][j] * scale;
                    if (needmask) {
                        const int rglob = R0 + g + ((j >> 1) << 3);
                        const int kglob = jb * 64 + ni * 8 + 2 * tq + (j & 1);
                        if (kglob > rglob) v = -1e30f;
                    }
                    s[ni][j] = v;
                }

            // ---- warp-local online softmax (rows g, g+8) ----
            float alpha[2];
#pragma unroll
            for (int r = 0; r < 2; r++) {
                float mx = -1e30f;
#pragma unroll
                for (int ni = 0; ni < 8; ni++)
                    mx = fmaxf(mx, fmaxf(s[ni][2 * r], s[ni][2 * r + 1]));
                mx = fmaxf(mx, __shfl_xor_sync(0xffffffffu, mx, 1));
                mx = fmaxf(mx, __shfl_xor_sync(0xffffffffu, mx, 2));
                const float mn = fmaxf(m_i[r], mx);
                alpha[r] = __expf(m_i[r] - mn);
                m_i[r] = mn;
                float sum = 0.f;
#pragma unroll
                for (int ni = 0; ni < 8; ni++) {
                    const float p0 = __expf(s[ni][2 * r] - mn);
                    const float p1 = __expf(s[ni][2 * r + 1] - mn);
                    s[ni][2 * r] = p0; s[ni][2 * r + 1] = p1;
                    sum += p0 + p1;
                }
                sum += __shfl_xor_sync(0xffffffffu, sum, 1);
                sum += __shfl_xor_sync(0xffffffffu, sum, 2);
                l_i[r] = l_i[r] * alpha[r] + sum;
#pragma unroll
                for (int nd = 0; nd < 16; nd++) {
                    o[nd][2 * r]     *= alpha[r];
                    o[nd][2 * r + 1] *= alpha[r];
                }
            }

            // ---- O += P V : P hi/lo packed in regs, V fp16 (2-pass) ----
#pragma unroll
            for (int kc = 0; kc < 4; kc++) {
                uint32_t aph[4], apl[4];
                const float* s0 = s[2 * kc];
                const float* s1 = s[2 * kc + 1];
                aph[0] = hfp(s0[0], s0[1]);
                aph[1] = hfp(s0[2], s0[3]);
                aph[2] = hfp(s1[0], s1[1]);
                aph[3] = hfp(s1[2], s1[3]);
                apl[0] = hfp(hres(s0[0]), hres(s0[1]));
                apl[1] = hfp(hres(s0[2]), hres(s0[3]));
                apl[2] = hfp(hres(s1[0]), hres(s1[1]));
                apl[3] = hfp(hres(s1[2]), hres(s1[3]));
#pragma unroll
                for (int nd = 0; nd < 8; nd++) {
                    const int key = kc * 16 + (quad & 1) * 8 + rr;
                    const uint32_t db = (uint32_t)(nd * 32 + (quad >> 1) * 16);
                    const uint32_t off = (uint32_t)key * 256u +
                                         (db ^ ((uint32_t)(key & 7) << 4));
                    uint32_t vh[4];
                    LDMX4T(vh[0], vh[1], vh[2], vh[3], VHb + off);
                    MMA16816(o[2 * nd],     aph, vh[0], vh[1]);
                    MMA16816(o[2 * nd],     apl, vh[0], vh[1]);
                    MMA16816(o[2 * nd + 1], aph, vh[2], vh[3]);
                    MMA16816(o[2 * nd + 1], apl, vh[2], vh[3]);
                }
            }
        }
        __syncthreads();
    }

    // ---- epilogue: normalize, transpose-stage, store Y fp16 [d][t] ----
    const float inv0 = 1.f / l_i[0], inv1 = 1.f / l_i[1];
    float* Od = (float*)sm;   // [128 d][132]
#pragma unroll
    for (int nd = 0; nd < 16; nd++) {
        const int d = nd * 8 + 2 * tq;
        const int t0 = w * 16 + g;
        Od[d * 132 + t0]           = o[nd][0] * inv0;
        Od[(d + 1) * 132 + t0]     = o[nd][1] * inv0;
        Od[d * 132 + t0 + 8]       = o[nd][2] * inv1;
        Od[(d + 1) * 132 + t0 + 8] = o[nd][3] * inv1;
    }
    __syncthreads();

    const int b = bh >> 4, h = bh & 15;
    const size_t ybase = ((size_t)(b * CDIM + h * HDIM)) * T_SEQ + (size_t)qb * 128;
    for (int idx = tid; idx < 128 * 32; idx += 256) {
        const int d = idx >> 5, q4 = (idx & 31) * 4;
        const float4 v = *(const float4*)&Od[d * 132 + q4];
        uint2 hh;
        hh.x = hfp(v.x, v.y); hh.y = hfp(v.z, v.w);
        *(uint2*)(Yh + ybase + (size_t)d * T_SEQ + q4) = hh;
    }
}

// ===========================================================================
extern "C" void kernel_launch(void* const* d_in, const int* in_sizes, int n_in,
                              void* d_out, int out_size)
{
    (void)in_sizes; (void)n_in; (void)out_size;
    const float* x  = (const float*)d_in[0];
    const float* Wq = (const float*)d_in[1];
    const float* bq = (const float*)d_in[2];
    const float* Wk = (const float*)d_in[3];
    const float* bk = (const float*)d_in[4];
    const float* Wv = (const float*)d_in[5];
    const float* bv = (const float*)d_in[6];
    const float* Wp = (const float*)d_in[7];
    const float* bp = (const float*)d_in[8];
    float* out = (float*)d_out;

    __half *xh, *Wh, *Qh, *Ql, *Kh, *Vh, *Yh;
    cudaGetSymbolAddress((void**)&xh, g_xh);
    cudaGetSymbolAddress((void**)&Wh, g_Wh);
    cudaGetSymbolAddress((void**)&Qh, g_Qh);
    cudaGetSymbolAddress((void**)&Ql, g_Ql);
    cudaGetSymbolAddress((void**)&Kh, g_Kh);
    cudaGetSymbolAddress((void**)&Vh, g_Vh);
    cudaGetSymbolAddress((void**)&Yh, g_Yh);

    cudaFuncSetAttribute(gemm_h<0>, cudaFuncAttributeMaxDynamicSharedMemorySize,
                         GEMM_SMEM_BYTES);
    cudaFuncSetAttribute(gemm_h<1>, cudaFuncAttributeMaxDynamicSharedMemorySize,
                         GEMM_SMEM_BYTES);
    cudaFuncSetAttribute(attn_mma, cudaFuncAttributeMaxDynamicSharedMemorySize,
                         ATTN_SMEM_BYTES);

    const size_t WSZ = (size_t)CDIM * CDIM;

    // fused conversion pass (x + all 4 weights, fp16)
    {
        const int total = N4X + 4 * N4W;
        cvt_all<<<(total + 255) / 256, 256>>>(x, xh, Wq, Wk, Wv, Wp, Wh);
    }

    // fused QKV GEMM: grid.x = 3 mats x 16 n-tiles
    gemm_h<1><<<dim3(48, MROWS / 64), 256, GEMM_SMEM_BYTES>>>(
        xh, Wh, bq, bk, bv, nullptr, Qh, Ql, Kh, Vh);

    attn_mma<<<dim3(T_SEQ / 128, BATCH * NHEAD), 256, ATTN_SMEM_BYTES>>>(
        Qh, Ql, Kh, Vh, Yh);

    gemm_h<0><<<dim3(16, MROWS / 64), 256, GEMM_SMEM_BYTES>>>(
        Yh, Wh + 3 * WSZ, bp, nullptr, nullptr, out,
        nullptr, nullptr, nullptr, nullptr);
}

// round 13
// speedup vs baseline: 8.8188x; 1.0536x over previous
#include <cuda_runtime.h>
#include <cuda_fp16.h>
#include <cstdint>

#define T_SEQ  2048
#define NHEAD  16
#define HDIM   128
#define BATCH  2
#define CDIM   2048
#define MROWS  (BATCH * T_SEQ)   // 4096

// ---------------------------------------------------------------------------
// Device-global scratch (allocation-free, graph-safe), fp16
// Q carries hi/lo (exact); x, W, K, V, Y are fp16-rounded.
// ---------------------------------------------------------------------------
__device__ __half g_xh[(size_t)MROWS * CDIM];
__device__ __half g_Wh[4][(size_t)CDIM * CDIM];   // q,k,v,p
__device__ __half g_Qh[(size_t)BATCH * NHEAD * T_SEQ * HDIM];
__device__ __half g_Ql[(size_t)BATCH * NHEAD * T_SEQ * HDIM];
__device__ __half g_Kh[(size_t)BATCH * NHEAD * T_SEQ * HDIM];
__device__ __half g_Vh[(size_t)BATCH * NHEAD * T_SEQ * HDIM];
__device__ __half g_Yh[(size_t)BATCH * T_SEQ * CDIM];   // [b][c][t]

// ===========================================================================
// helpers
// ===========================================================================
__device__ __forceinline__ uint32_t smem_to_u32(const void* p) {
    uint32_t a;
    asm("{ .reg .u64 t; cvta.to.shared.u64 t, %1; cvt.u32.u64 %0, t; }"
        : "=r"(a) : "l"(p));
    return a;
}

__device__ __forceinline__ uint32_t hfp(float a, float b) {
    __half2 t = __floats2half2_rn(a, b);
    return *reinterpret_cast<uint32_t*>(&t);
}
__device__ __forceinline__ float hres(float a) {
    return a - __half2float(__float2half_rn(a));
}

#define LDMX4(r0, r1, r2, r3, addr) \
    asm volatile("ldmatrix.sync.aligned.m8n8.x4.shared.b16 {%0,%1,%2,%3}, [%4];" \
                 : "=r"(r0), "=r"(r1), "=r"(r2), "=r"(r3) : "r"(addr))

#define LDMX4T(r0, r1, r2, r3, addr) \
    asm volatile("ldmatrix.sync.aligned.m8n8.x4.trans.shared.b16 {%0,%1,%2,%3}, [%4];" \
                 : "=r"(r0), "=r"(r1), "=r"(r2), "=r"(r3) : "r"(addr))

#define MMA16816(c, a, b0, b1) \
    asm volatile("mma.sync.aligned.m16n8k16.row.col.f32.f16.f16.f32 " \
                 "{%0,%1,%2,%3}, {%4,%5,%6,%7}, {%8,%9}, {%0,%1,%2,%3};" \
                 : "+f"((c)[0]), "+f"((c)[1]), "+f"((c)[2]), "+f"((c)[3]) \
                 : "r"((a)[0]), "r"((a)[1]), "r"((a)[2]), "r"((a)[3]), \
                   "r"(b0), "r"(b1))

#define STSV4(addr, a, b, cc, d) \
    asm volatile("st.shared.v4.b32 [%0], {%1,%2,%3,%4};" \
                 :: "r"(addr), "r"(a), "r"(b), "r"(cc), "r"(d) : "memory")

#define CPASYNC16(saddr, gptr) \
    asm volatile("cp.async.cg.shared.global [%0], [%1], 16;" \
                 :: "r"(saddr), "l"(gptr) : "memory")
#define CPCOMMIT() asm volatile("cp.async.commit_group;" ::: "memory")
#define CPWAIT1()  asm volatile("cp.async.wait_group 1;" ::: "memory")
#define CPWAIT0()  asm volatile("cp.async.wait_group 0;" ::: "memory")

// ===========================================================================
// fused fp32 -> fp16 conversion: x + 4 weights, all hi-only, ONE launch
// ===========================================================================
#define N4X (MROWS * CDIM / 4)
#define N4W (CDIM * CDIM / 4)

__global__ void cvt_all(const float* __restrict__ x, __half* __restrict__ xh,
                        const float* __restrict__ Wq, const float* __restrict__ Wk,
                        const float* __restrict__ Wv, const float* __restrict__ Wp,
                        __half* __restrict__ Wh)
{
    const int i = blockIdx.x * blockDim.x + threadIdx.x;
    if (i < N4X) {
        const float4 v = ((const float4*)x)[i];
        uint2 h;
        h.x = hfp(v.x, v.y); h.y = hfp(v.z, v.w);
        ((uint2*)xh)[i] = h;
    } else {
        const int j = i - N4X;
        const int mat = j >> 20;            // j / N4W (N4W = 2^20)
        const int k   = j & (N4W - 1);
        if (mat < 4) {
            const float* W = (mat == 0) ? Wq : (mat == 1) ? Wk
                                             : (mat == 2) ? Wv : Wp;
            const float4 v = ((const float4*)W)[k];
            uint2 h;
            h.x = hfp(v.x, v.y); h.y = hfp(v.z, v.w);
            ((uint2*)(Wh + (size_t)mat * CDIM * CDIM))[k] = h;
        }
    }
}

// ===========================================================================
// Tensor-core GEMM, fp16 1-pass: C(M,N) = A(M,K) @ W(N,K)^T + bias(N).
// CTA tile 128x128, warp tile 32x64 (8 warps = 4m x 2n), K-chunk 64,
// 3-stage cp.async pipeline (96KB) -> 2 CTAs/SM, 1 sync/chunk.
// MMA:LDSM = 2.67 per warp.
// MODE 0: fp32 C out (grid 16 x 32).  MODE 1: fused QKV (grid.x=48, mat=bx>>4)
// Per-stage (32KB): Ah 0 (16K), Bh 16K (16K).
// ===========================================================================
#define GEMM_SMEM_BYTES 98304

template <int MODE>
__global__ void __launch_bounds__(256, 2)
gemm_h(const __half* __restrict__ Ah, const __half* __restrict__ Wh,
       const float* __restrict__ b0, const float* __restrict__ b1,
       const float* __restrict__ b2,
       float* __restrict__ C,
       __half* __restrict__ Qo, __half* __restrict__ Qlo,
       __half* __restrict__ Ko, __half* __restrict__ Vo)
{
    extern __shared__ __align__(1024) char sm[];
    const uint32_t sbase = smem_to_u32(sm);

    const int tid  = threadIdx.x;
    const int wid  = tid >> 5;
    const int lane = tid & 31;
    const int wm   = wid >> 1;        // 0..3 -> rows wm*32
    const int wn   = wid & 1;         // 0..1 -> cols wn*64
    const int quad = lane >> 3;
    const int rr   = lane & 7;
    const int mat  = (MODE == 1) ? ((int)blockIdx.x >> 4) : 0;
    const int nbx  = (MODE == 1) ? ((int)blockIdx.x & 15) : (int)blockIdx.x;
    const int mBase = blockIdx.y * 128;
    const int nBase = nbx * 128;

    const __half* Agh = Ah + (size_t)mBase * CDIM;
    const __half* Bgh = Wh + (size_t)mat * CDIM * CDIM + (size_t)nBase * CDIM;
    const float* bias = (MODE == 0) ? b0 : (mat == 0 ? b0 : (mat == 1 ? b1 : b2));

    float c[2][8][4];
#pragma unroll
    for (int mi = 0; mi < 2; mi++)
#pragma unroll
        for (int ni = 0; ni < 8; ni++)
#pragma unroll
            for (int k = 0; k < 4; k++) c[mi][ni][k] = 0.f;

    const int arow0 = wm * 32 + (quad & 1) * 8 + rr;
    const int acolq = (quad >> 1) * 8;
    const int brow0 = wn * 64 + (quad >> 1) * 8 + rr;
    const int bcolq = (quad & 1) * 8;

    // cp.async staging of chunk kt into stage stg (A 16K + B 16K)
    auto stage_load = [&](int kt, int stg) {
        const uint32_t base = sbase + (uint32_t)stg * 32768u;
#pragma unroll
        for (int i = 0; i < 4; i++) {
            const int idx = tid + 256 * i;
            const int r = idx >> 3, g = idx & 7;
            const uint32_t off = (uint32_t)(r * 128 + g * 16);
            const uint32_t sw  = off ^ ((off >> 3) & 0x70);
            const size_t e = (size_t)r * CDIM + kt * 64 + g * 8;
            CPASYNC16(base + sw,          (const char*)(Agh + e));
            CPASYNC16(base + 16384u + sw, (const char*)(Bgh + e));
        }
    };

    auto compute = [&](int stg) {
        const uint32_t base = sbase + (uint32_t)stg * 32768u;
        const uint32_t AhS = base, BhS = base + 16384u;
#pragma unroll
        for (int sub = 0; sub < 4; sub++) {
            const int kb = sub * 16;
            uint32_t bh[16];
#pragma unroll
            for (int p = 0; p < 4; p++) {
                const uint32_t off = (uint32_t)((brow0 + p * 16) * 128 + (kb + bcolq) * 2);
                const uint32_t sw  = off ^ ((off >> 3) & 0x70);
                LDMX4(bh[4 * p], bh[4 * p + 1], bh[4 * p + 2], bh[4 * p + 3], BhS + sw);
            }
#pragma unroll
            for (int mi = 0; mi < 2; mi++) {
                uint32_t ah[4];
                const uint32_t off = (uint32_t)((arow0 + mi * 16) * 128 + (kb + acolq) * 2);
                const uint32_t sw  = off ^ ((off >> 3) & 0x70);
                LDMX4(ah[0], ah[1], ah[2], ah[3], AhS + sw);
#pragma unroll
                for (int ni = 0; ni < 8; ni++)
                    MMA16816(c[mi][ni], ah, bh[2 * ni], bh[2 * ni + 1]);
            }
        }
    };

    stage_load(0, 0); CPCOMMIT();
    stage_load(1, 1); CPCOMMIT();

    int stg = 0;
    for (int kt = 0; kt < 32; kt++) {
        if (kt + 1 < 32) { CPWAIT1(); } else { CPWAIT0(); }
        __syncthreads();   // chunk kt visible; compute on stage (kt+2)%3 done
        if (kt + 2 < 32) {
            int ns = stg + 2; if (ns >= 3) ns -= 3;
            stage_load(kt + 2, ns);
            CPCOMMIT();
        }
        compute(stg);
        if (++stg == 3) stg = 0;
    }

    // epilogue: fragments -> smem Ct[128][132] fp32 -> gmem
    __syncthreads();
    float* Ct = (float*)sm;
    const int g2 = lane >> 2, t2 = (lane & 3) * 2;
#pragma unroll
    for (int mi = 0; mi < 2; mi++) {
        const int row = wm * 32 + mi * 16 + g2;
#pragma unroll
        for (int ni = 0; ni < 8; ni++) {
            const int col = wn * 64 + ni * 8 + t2;
            Ct[row * 132 + col]           = c[mi][ni][0];
            Ct[row * 132 + col + 1]       = c[mi][ni][1];
            Ct[(row + 8) * 132 + col]     = c[mi][ni][2];
            Ct[(row + 8) * 132 + col + 1] = c[mi][ni][3];
        }
    }
    __syncthreads();

    for (int idx = tid; idx < 128 * 32; idx += 256) {
        const int row = idx >> 5, c4 = (idx & 31) * 4;
        const int n = nBase + c4;
        const float4 bv = *(const float4*)&bias[n];
        float4 v;
        v.x = Ct[row * 132 + c4]     + bv.x;
        v.y = Ct[row * 132 + c4 + 1] + bv.y;
        v.z = Ct[row * 132 + c4 + 2] + bv.z;
        v.w = Ct[row * 132 + c4 + 3] + bv.w;
        const int m = mBase + row;
        if (MODE == 0) {
            *(float4*)&C[(size_t)m * CDIM + n] = v;
        } else {
            const int b = m >> 11, t = m & (T_SEQ - 1);
            const int h = n >> 7, d = n & (HDIM - 1);
            const size_t e = (((size_t)(b * NHEAD + h)) * T_SEQ + t) * HDIM + d;
            uint2 hh;
            hh.x = hfp(v.x, v.y); hh.y = hfp(v.z, v.w);
            if (mat == 0) {
                uint2 ll;
                ll.x = hfp(hres(v.x), hres(v.y)); ll.y = hfp(hres(v.z), hres(v.w));
                *(uint2*)(Qo + e)  = hh;
                *(uint2*)(Qlo + e) = ll;
            } else {
                __half* dst = (mat == 1) ? Ko : Vo;
                *(uint2*)(dst + e) = hh;
            }
        }
    }
}

// ===========================================================================
// FA2-style tensor-core flash attention, causal, fp16 (Q hi/lo exact,
// K/V fp16, P hi/lo in regs). Y output fp16-rounded. (unchanged R12)
// ===========================================================================
#define ATTN_SMEM_BYTES 131072

__global__ void __launch_bounds__(256, 1)
attn_mma(const __half* __restrict__ Qh, const __half* __restrict__ Ql,
         const __half* __restrict__ Kh, const __half* __restrict__ Vh,
         __half* __restrict__ Yh)
{
    extern __shared__ __align__(1024) char sm[];
    const uint32_t sb = smem_to_u32(sm);
    const uint32_t QHs = sb, QLs = sb + 32768u;

    const int tid  = threadIdx.x;
    const int lane = tid & 31;
    const int w    = tid >> 5;
    const int quad = lane >> 3;
    const int rr   = lane & 7;
    const int g    = lane >> 2;
    const int tq   = lane & 3;
    const int qb   = (int)gridDim.x - 1 - (int)blockIdx.x;  // heavy first
    const int bh   = blockIdx.y;

    const size_t headbase = (size_t)bh * T_SEQ * HDIM;
    const int jend = 2 * qb + 1;

    auto stage_kv = [&](int jb, int b) {
        const size_t base = headbase + (size_t)jb * 64 * HDIM;
        const char* kh = (const char*)(Kh + base);
        const char* vh = (const char*)(Vh + base);
        const uint32_t bufb = sb + 65536u + (uint32_t)b * 32768u;
#pragma unroll
        for (int i = 0; i < 4; i++) {
            const int c = tid + 256 * i;
            const int row = c >> 4, gg = c & 15;
            const uint32_t off = (uint32_t)row * 256u +
                                 ((uint32_t)(gg * 16) ^ ((uint32_t)(row & 7) << 4));
            const size_t gb = (size_t)c * 16;
            CPASYNC16(bufb + off,          kh + gb);
            CPASYNC16(bufb + 16384u + off, vh + gb);
        }
    };

    stage_kv(0, 0);
    CPCOMMIT();
    {
        const size_t base = headbase + (size_t)qb * 128 * HDIM;
        const uint4* qh4 = (const uint4*)(Qh + base);
        const uint4* ql4 = (const uint4*)(Ql + base);
#pragma unroll
        for (int i = 0; i < 8; i++) {
            const int c = tid + 256 * i;
            const int row = c >> 4, gg = c & 15;
            const uint32_t off = (uint32_t)row * 256u +
                                 ((uint32_t)(gg * 16) ^ ((uint32_t)(row & 7) << 4));
            const uint4 vh = qh4[c], vl = ql4[c];
            STSV4(QHs + off, vh.x, vh.y, vh.z, vh.w);
            STSV4(QLs + off, vl.x, vl.y, vl.z, vl.w);
        }
    }

    float o[16][4];
#pragma unroll
    for (int nd = 0; nd < 16; nd++)
#pragma unroll
        for (int k = 0; k < 4; k++) o[nd][k] = 0.f;
    float m_i[2] = {-1e30f, -1e30f}, l_i[2] = {0.f, 0.f};

    const float scale = 0.08838834764831845f;   // 1/sqrt(128)
    const int R0 = qb * 128 + w * 16;

    for (int jb = 0; jb <= jend; jb++) {
        const int buf = jb & 1;
        if (jb < jend) { stage_kv(jb + 1, buf ^ 1); CPCOMMIT(); }
        if (jb < jend) { CPWAIT1(); } else { CPWAIT0(); }
        __syncthreads();

        if (jb * 64 <= R0 + 15) {
            const uint32_t KHb = sb + 65536u + (uint32_t)buf * 32768u;
            const uint32_t VHb = KHb + 16384u;

            // ---- S = Q K^T : 16 rows x 64 keys, 2-pass (Q hi/lo, K fp16) ----
            float s[8][4];
#pragma unroll
            for (int ni = 0; ni < 8; ni++)
#pragma unroll
                for (int k = 0; k < 4; k++) s[ni][k] = 0.f;

#pragma unroll
            for (int kb = 0; kb < 8; kb++) {
                uint32_t ah[4], al[4];
                {
                    const int arow = w * 16 + (quad & 1) * 8 + rr;
                    const uint32_t cb = (uint32_t)(kb * 32 + (quad >> 1) * 16);
                    const uint32_t off = (uint32_t)arow * 256u +
                                         (cb ^ ((uint32_t)(arow & 7) << 4));
                    LDMX4(ah[0], ah[1], ah[2], ah[3], QHs + off);
                    LDMX4(al[0], al[1], al[2], al[3], QLs + off);
                }
#pragma unroll
                for (int p = 0; p < 4; p++) {
                    uint32_t bh2[4];
                    const int krow = p * 16 + (quad >> 1) * 8 + rr;
                    const uint32_t cb = (uint32_t)(kb * 32 + (quad & 1) * 16);
                    const uint32_t off = (uint32_t)krow * 256u +
                                         (cb ^ ((uint32_t)(krow & 7) << 4));
                    LDMX4(bh2[0], bh2[1], bh2[2], bh2[3], KHb + off);
                    MMA16816(s[2 * p],     ah, bh2[0], bh2[1]);
                    MMA16816(s[2 * p],     al, bh2[0], bh2[1]);
                    MMA16816(s[2 * p + 1], ah, bh2[2], bh2[3]);
                    MMA16816(s[2 * p + 1], al, bh2[2], bh2[3]);
                }
            }

            // ---- scale + causal mask ----
            const bool needmask = (jb * 64 + 63 > R0);
#pragma unroll
            for (int ni = 0; ni < 8; ni++)
#pragma unroll
                for (int j = 0; j < 4; j++) {
                    float v = s[ni][j] * scale;
                    if (needmask) {
                        const int rglob = R0 + g + ((j >> 1) << 3);
                        const int kglob = jb * 64 + ni * 8 + 2 * tq + (j & 1);
                        if (kglob > rglob) v = -1e30f;
                    }
                    s[ni][j] = v;
                }

            // ---- warp-local online softmax (rows g, g+8) ----
            float alpha[2];
#pragma unroll
            for (int r = 0; r < 2; r++) {
                float mx = -1e30f;
#pragma unroll
                for (int ni = 0; ni < 8; ni++)
                    mx = fmaxf(mx, fmaxf(s[ni][2 * r], s[ni][2 * r + 1]));
                mx = fmaxf(mx, __shfl_xor_sync(0xffffffffu, mx, 1));
                mx = fmaxf(mx, __shfl_xor_sync(0xffffffffu, mx, 2));
                const float mn = fmaxf(m_i[r], mx);
                alpha[r] = __expf(m_i[r] - mn);
                m_i[r] = mn;
                float sum = 0.f;
#pragma unroll
                for (int ni = 0; ni < 8; ni++) {
                    const float p0 = __expf(s[ni][2 * r] - mn);
                    const float p1 = __expf(s[ni][2 * r + 1] - mn);
                    s[ni][2 * r] = p0; s[ni][2 * r + 1] = p1;
                    sum += p0 + p1;
                }
                sum += __shfl_xor_sync(0xffffffffu, sum, 1);
                sum += __shfl_xor_sync(0xffffffffu, sum, 2);
                l_i[r] = l_i[r] * alpha[r] + sum;
#pragma unroll
                for (int nd = 0; nd < 16; nd++) {
                    o[nd][2 * r]     *= alpha[r];
                    o[nd][2 * r + 1] *= alpha[r];
                }
            }

            // ---- O += P V : P hi/lo packed in regs, V fp16 (2-pass) ----
#pragma unroll
            for (int kc = 0; kc < 4; kc++) {
                uint32_t aph[4], apl[4];
                const float* s0 = s[2 * kc];
                const float* s1 = s[2 * kc + 1];
                aph[0] = hfp(s0[0], s0[1]);
                aph[1] = hfp(s0[2], s0[3]);
                aph[2] = hfp(s1[0], s1[1]);
                aph[3] = hfp(s1[2], s1[3]);
                apl[0] = hfp(hres(s0[0]), hres(s0[1]));
                apl[1] = hfp(hres(s0[2]), hres(s0[3]));
                apl[2] = hfp(hres(s1[0]), hres(s1[1]));
                apl[3] = hfp(hres(s1[2]), hres(s1[3]));
#pragma unroll
                for (int nd = 0; nd < 8; nd++) {
                    const int key = kc * 16 + (quad & 1) * 8 + rr;
                    const uint32_t db = (uint32_t)(nd * 32 + (quad >> 1) * 16);
                    const uint32_t off = (uint32_t)key * 256u +
                                         (db ^ ((uint32_t)(key & 7) << 4));
                    uint32_t vh[4];
                    LDMX4T(vh[0], vh[1], vh[2], vh[3], VHb + off);
                    MMA16816(o[2 * nd],     aph, vh[0], vh[1]);
                    MMA16816(o[2 * nd],     apl, vh[0], vh[1]);
                    MMA16816(o[2 * nd + 1], aph, vh[2], vh[3]);
                    MMA16816(o[2 * nd + 1], apl, vh[2], vh[3]);
                }
            }
        }
        __syncthreads();
    }

    // ---- epilogue: normalize, transpose-stage, store Y fp16 [d][t] ----
    const float inv0 = 1.f / l_i[0], inv1 = 1.f / l_i[1];
    float* Od = (float*)sm;   // [128 d][132]
#pragma unroll
    for (int nd = 0; nd < 16; nd++) {
        const int d = nd * 8 + 2 * tq;
        const int t0 = w * 16 + g;
        Od[d * 132 + t0]           = o[nd][0] * inv0;
        Od[(d + 1) * 132 + t0]     = o[nd][1] * inv0;
        Od[d * 132 + t0 + 8]       = o[nd][2] * inv1;
        Od[(d + 1) * 132 + t0 + 8] = o[nd][3] * inv1;
    }
    __syncthreads();

    const int b = bh >> 4, h = bh & 15;
    const size_t ybase = ((size_t)(b * CDIM + h * HDIM)) * T_SEQ + (size_t)qb * 128;
    for (int idx = tid; idx < 128 * 32; idx += 256) {
        const int d = idx >> 5, q4 = (idx & 31) * 4;
        const float4 v = *(const float4*)&Od[d * 132 + q4];
        uint2 hh;
        hh.x = hfp(v.x, v.y); hh.y = hfp(v.z, v.w);
        *(uint2*)(Yh + ybase + (size_t)d * T_SEQ + q4) = hh;
    }
}

// ===========================================================================
extern "C" void kernel_launch(void* const* d_in, const int* in_sizes, int n_in,
                              void* d_out, int out_size)
{
    (void)in_sizes; (void)n_in; (void)out_size;
    const float* x  = (const float*)d_in[0];
    const float* Wq = (const float*)d_in[1];
    const float* bq = (const float*)d_in[2];
    const float* Wk = (const float*)d_in[3];
    const float* bk = (const float*)d_in[4];
    const float* Wv = (const float*)d_in[5];
    const float* bv = (const float*)d_in[6];
    const float* Wp = (const float*)d_in[7];
    const float* bp = (const float*)d_in[8];
    float* out = (float*)d_out;

    __half *xh, *Wh, *Qh, *Ql, *Kh, *Vh, *Yh;
    cudaGetSymbolAddress((void**)&xh, g_xh);
    cudaGetSymbolAddress((void**)&Wh, g_Wh);
    cudaGetSymbolAddress((void**)&Qh, g_Qh);
    cudaGetSymbolAddress((void**)&Ql, g_Ql);
    cudaGetSymbolAddress((void**)&Kh, g_Kh);
    cudaGetSymbolAddress((void**)&Vh, g_Vh);
    cudaGetSymbolAddress((void**)&Yh, g_Yh);

    cudaFuncSetAttribute(gemm_h<0>, cudaFuncAttributeMaxDynamicSharedMemorySize,
                         GEMM_SMEM_BYTES);
    cudaFuncSetAttribute(gemm_h<1>, cudaFuncAttributeMaxDynamicSharedMemorySize,
                         GEMM_SMEM_BYTES);
    cudaFuncSetAttribute(attn_mma, cudaFuncAttributeMaxDynamicSharedMemorySize,
                         ATTN_SMEM_BYTES);

    const size_t WSZ = (size_t)CDIM * CDIM;

    // fused conversion pass (x + all 4 weights, fp16)
    {
        const int total = N4X + 4 * N4W;
        cvt_all<<<(total + 255) / 256, 256>>>(x, xh, Wq, Wk, Wv, Wp, Wh);
    }

    // fused QKV GEMM: grid.x = 3 mats x 16 n-tiles, grid.y = 32 m-tiles
    gemm_h<1><<<dim3(48, MROWS / 128), 256, GEMM_SMEM_BYTES>>>(
        xh, Wh, bq, bk, bv, nullptr, Qh, Ql, Kh, Vh);

    attn_mma<<<dim3(T_SEQ / 128, BATCH * NHEAD), 256, ATTN_SMEM_BYTES>>>(
        Qh, Ql, Kh, Vh, Yh);

    gemm_h<0><<<dim3(16, MROWS / 128), 256, GEMM_SMEM_BYTES>>>(
        Yh, Wh + 3 * WSZ, bp, nullptr, nullptr, out,
        nullptr, nullptr, nullptr, nullptr);
}